// round 9
// baseline (speedup 1.0000x reference)
#include <cuda_runtime.h>
#include <math.h>
#include <stdint.h>

#define BATCH 16
#define T_LEN 131072
#define HOP 256
#define NFFT 2048
#define NBINS 1025
#define NFR 513
#define NFRT (BATCH*NFR)          /* 8208 */
#define NPT 257                    /* frame pairs per batch (last has no B) */
#define NPAIR (BATCH*NPT)          /* 4112 */
#define PLEN 2304                  /* pair-buffer length: 2048 + 256 */
#define NMELS 80
#define MIN_P 32
#define L_OLA 133120               /* NFFT + HOP*(NFR-1) */
#define MOM (0.99f/1.99f)

#define PAD(i) ((i) + ((i)>>3))
#define ZLEN 2304                  /* PAD(2047)=2302 */

// ---------------- scratch (static device globals; no allocs) ----------------
__device__ float  g_fpts[NMELS+2];
__device__ float  g_win[NFFT];
__device__ float  g_env[L_OLA];
__device__ int    g_fbi[NBINS];
__device__ float2 g_fbw[NBINS];
__device__ float  g_lin[NFRT*NBINS];
__device__ float2 g_tprev[NFRT*NBINS];
__device__ float  g_pf[NPAIR*PLEN];     /* pre-summed pair buffers */
__device__ float  g_inv[BATCH*T_LEN];

// ---------------- threefry-2x32-20 (matches jax partitionable) ----------------
__host__ __device__ __forceinline__ unsigned rotl32(unsigned x, int r){ return (x<<r)|(x>>(32-r)); }
__host__ __device__ inline void tf2x32(unsigned k0,unsigned k1,unsigned x0,unsigned x1,unsigned&o0,unsigned&o1){
  unsigned k2 = k0^k1^0x1BD11BDAu;
  x0+=k0; x1+=k1;
  #define TFR(r) { x0+=x1; x1=rotl32(x1,(r)); x1^=x0; }
  TFR(13) TFR(15) TFR(26) TFR(6)  x0+=k1; x1+=k2+1u;
  TFR(17) TFR(29) TFR(16) TFR(24) x0+=k2; x1+=k0+2u;
  TFR(13) TFR(15) TFR(26) TFR(6)  x0+=k0; x1+=k1+3u;
  TFR(17) TFR(29) TFR(16) TFR(24) x0+=k1; x1+=k2+4u;
  TFR(13) TFR(15) TFR(26) TFR(6)  x0+=k2; x1+=k0+5u;
  #undef TFR
  o0=x0; o1=x1;
}
__device__ __forceinline__ float u01(unsigned bits){
  return __uint_as_float((bits>>9) | 0x3f800000u) - 1.0f;
}
__device__ __forceinline__ int refl(int j, int n){
  if (j < 0) j = -j;
  if (j >= n) j = 2*n - 2 - j;
  return j;
}

// ---------------- register radix-8 DFT (DIF), DIR=+1 fwd / -1 inv ----------------
template<int DIR>
__device__ __forceinline__ void dft8(float* ar, float* ai){
  const float r2 = 0.70710678118654752f;
  const float d = (float)DIR;
  float t0r=ar[0]+ar[4], t0i=ai[0]+ai[4];
  float t4r=ar[0]-ar[4], t4i=ai[0]-ai[4];
  float t1r=ar[1]+ar[5], t1i=ai[1]+ai[5];
  float t5r=ar[1]-ar[5], t5i=ai[1]-ai[5];
  float t2r=ar[2]+ar[6], t2i=ai[2]+ai[6];
  float t6r=ar[2]-ar[6], t6i=ai[2]-ai[6];
  float t3r=ar[3]+ar[7], t3i=ai[3]+ai[7];
  float t7r=ar[3]-ar[7], t7i=ai[3]-ai[7];
  { float a=t5r,b=t5i; t5r=r2*(a+d*b); t5i=r2*(b-d*a); }      // *w8^1
  { float a=t6r,b=t6i; t6r=d*b; t6i=-d*a; }                   // *w8^2 = -i*d
  { float a=t7r,b=t7i; t7r=r2*(d*b-a); t7i=-r2*(b+d*a); }     // *w8^3
  float u0r=t0r+t2r,u0i=t0i+t2i, u1r=t0r-t2r,u1i=t0i-t2i;
  float u2r=t1r+t3r,u2i=t1i+t3i, u3r=t1r-t3r,u3i=t1i-t3i;
  float vr=d*u3i, vi=-d*u3r;
  ar[0]=u0r+u2r; ai[0]=u0i+u2i;
  ar[4]=u0r-u2r; ai[4]=u0i-u2i;
  ar[2]=u1r+vr;  ai[2]=u1i+vi;
  ar[6]=u1r-vr;  ai[6]=u1i-vi;
  u0r=t4r+t6r; u0i=t4i+t6i; u1r=t4r-t6r; u1i=t4i-t6i;
  u2r=t5r+t7r; u2i=t5i+t7i; u3r=t5r-t7r; u3i=t5i-t7i;
  vr=d*u3i; vi=-d*u3r;
  ar[1]=u0r+u2r; ai[1]=u0i+u2i;
  ar[5]=u0r-u2r; ai[5]=u0i-u2i;
  ar[3]=u1r+vr;  ai[3]=u1i+vi;
  ar[7]=u1r-vr;  ai[7]=u1i-vi;
}

// ---------------- size-2048 Stockham FFT, radix 8*8*8*4, single SoA buffer ----------------
template<int DIR>
__device__ __forceinline__ void fft2048_r8(float* Zr, float* Zi, int tid){
  #pragma unroll
  for (int st = 0; st < 3; ++st){
    const int s = (st==0) ? 1 : (st==1) ? 8 : 64;
    int q = tid & (s-1);
    int ps = tid - q;
    float ar[8], ai[8];
    #pragma unroll
    for (int j=0;j<8;++j){ int idx = tid + (j<<8); ar[j]=Zr[PAD(idx)]; ai[j]=Zi[PAD(idx)]; }
    __syncthreads();
    dft8<DIR>(ar, ai);
    float sn, cs;
    sincospif((float)ps * (1.0f/1024.0f), &sn, &cs);
    float w1r = cs, w1i = -(float)DIR * sn;
    float wr = w1r, wi = w1i;
    int base = q + (ps<<3);
    Zr[PAD(base)] = ar[0]; Zi[PAD(base)] = ai[0];
    #pragma unroll
    for (int k=1;k<8;++k){
      float br = ar[k]*wr - ai[k]*wi;
      float bi = ar[k]*wi + ai[k]*wr;
      int idx = base + s*k;
      Zr[PAD(idx)] = br; Zi[PAD(idx)] = bi;
      float nwr = wr*w1r - wi*w1i; wi = wr*w1i + wi*w1r; wr = nwr;
    }
    __syncthreads();
  }
  float cr[8], ci[8];
  #pragma unroll
  for (int h=0; h<2; ++h){
    int i = tid + (h<<8);
    #pragma unroll
    for (int j=0;j<4;++j){ int idx = i + (j<<9); cr[h*4+j]=Zr[PAD(idx)]; ci[h*4+j]=Zi[PAD(idx)]; }
  }
  __syncthreads();
  const float d = (float)DIR;
  #pragma unroll
  for (int h=0;h<2;++h){
    int i = tid + (h<<8);
    float u0r=cr[h*4]+cr[h*4+2], u0i=ci[h*4]+ci[h*4+2];
    float u1r=cr[h*4]-cr[h*4+2], u1i=ci[h*4]-ci[h*4+2];
    float u2r=cr[h*4+1]+cr[h*4+3], u2i=ci[h*4+1]+ci[h*4+3];
    float u3r=cr[h*4+1]-cr[h*4+3], u3i=ci[h*4+1]-ci[h*4+3];
    float vr=d*u3i, vi=-d*u3r;
    Zr[PAD(i)]      = u0r+u2r; Zi[PAD(i)]      = u0i+u2i;
    Zr[PAD(i+512)]  = u1r+vr;  Zi[PAD(i+512)]  = u1i+vi;
    Zr[PAD(i+1024)] = u0r-u2r; Zi[PAD(i+1024)] = u0i-u2i;
    Zr[PAD(i+1536)] = u1r-vr;  Zi[PAD(i+1536)] = u1i-vi;
  }
  __syncthreads();
}

// ---------------- store pair buffer: A (Zr) + shifted B (Zi) pre-summed ----------------
__device__ __forceinline__ void store_pair(const float* Zr, const float* Zi,
                                           int tid, int fr0pair, bool hasB){
  float* oa = g_pf + (size_t)fr0pair * PLEN;
  for (int n = tid; n < PLEN; n += 256){
    float v = 0.f;
    if (n < 2048) v = Zr[PAD(n)] * (g_win[n] * (1.0f/2048.0f));
    if (hasB && n >= 256){
      int nb = n - 256;
      v += Zi[PAD(nb)] * (g_win[nb] * (1.0f/2048.0f));
    }
    oa[n] = v;
  }
}

// ---------------- mel breakpoints (82 double pows total, once) ----------------
__global__ void k_fpts(){
  int m = threadIdx.x;
  if (m < NMELS+2){
    double mmax = 2595.0*log10(1.0 + 8000.0/700.0);
    g_fpts[m] = (float)(700.0*(pow(10.0, (double)m*mmax/81.0/2595.0) - 1.0));
  }
}

// ---------------- init tables (all float, no pow) ----------------
__global__ void k_tables(){
  int idx = blockIdx.x*blockDim.x + threadIdx.x;
  if (idx < 2048){
    g_win[idx] = 0.5f - 0.5f*cospif((float)idx * (1.0f/1024.0f));
  } else if (idx < 2048+L_OLA){
    int i = idx - 2048;
    int flo = (i - 1792) >> 8; if (flo < 0) flo = 0;
    int fhi = i >> 8;          if (fhi > NFR-1) fhi = NFR-1;
    float acc = 0.f;
    for (int f = flo; f <= fhi; ++f){
      int n = i - 256*f;
      float w = 0.5f - 0.5f*cospif((float)n * (1.0f/1024.0f));
      acc += w*w;
    }
    g_env[i] = acc;
  } else {
    int f = idx - 2048 - L_OLA;
    if (f < NBINS){
      float freq = (float)f * (8000.0f/1024.0f);
      int first = -1; float w0 = 0.f, w1 = 0.f;
      #pragma unroll 4
      for (int m = 0; m < NMELS; ++m){
        float fp0 = g_fpts[m], fp1 = g_fpts[m+1], fp2 = g_fpts[m+2];
        float dn = (freq - fp0)/(fp1 - fp0);
        float up = (fp2 - freq)/(fp2 - fp1);
        float v = fminf(dn, up);
        if (v > 0.f){
          if (first < 0){ first = m; w0 = v; }
          else w1 = v;
        }
      }
      g_fbi[f] = first;
      g_fbw[f] = make_float2(w0, w1);
    }
  }
}

// ---------------- f0 / loudness (1 frame per warp, shuffle autocorr) + MLP ----------------
__global__ void k_feats_mlp(const float* __restrict__ x,
                            const float* __restrict__ W1, const float* __restrict__ b1,
                            const float* __restrict__ W2, const float* __restrict__ b2,
                            const float* __restrict__ W3, const float* __restrict__ b3,
                            float* __restrict__ outc){
  __shared__ float s[8][768];          // 512 window + zero tail (tap reach 735)
  __shared__ float h1s[8*256];
  __shared__ float h2s[8*256];
  __shared__ float feat[8][2];
  int tid = threadIdx.x;
  int w = tid >> 5, lane = tid & 31;
  int base = blockIdx.x * 8;
  const unsigned FULL = 0xffffffffu;

  {
    int fr = base + w;
    int b = fr / NFR, t = fr % NFR;
    const float* xb = x + (size_t)b * T_LEN;
    for (int k = lane; k < 512; k += 32)
      s[w][k] = xb[refl(t*HOP + k - 256, T_LEN)];
    for (int k = 512 + lane; k < 768; k += 32)
      s[w][k] = 0.f;
    __syncwarp();
    float ss = 0.f;
    for (int k = lane; k < 512; k += 32){ float v = s[w][k]; ss += v*v; }
    #pragma unroll
    for (int o = 16; o; o >>= 1) ss += __shfl_xor_sync(FULL, ss, o);
    float acc[7];
    #pragma unroll
    for (int kk = 0; kk < 7; ++kk) acc[kk] = 0.f;
    for (int T = 0; T < 480; T += 32){
      float p = s[w][T + lane];
      float wreg[8];
      #pragma unroll
      for (int kk = 0; kk < 8; ++kk) wreg[kk] = s[w][T + 32 + lane + (kk<<5)];
      #pragma unroll 8
      for (int j = 0; j < 32; ++j){
        float v0 = __shfl_sync(FULL, p, j);
        int src = (lane + j) & 31;
        bool hi = (lane + j) >= 32;
        float sh[8];
        #pragma unroll
        for (int kk = 0; kk < 8; ++kk) sh[kk] = __shfl_sync(FULL, wreg[kk], src);
        #pragma unroll
        for (int kk = 0; kk < 7; ++kk) acc[kk] += v0 * (hi ? sh[kk+1] : sh[kk]);
      }
    }
    float best = -1e30f; int bi = 0;
    #pragma unroll
    for (int kk = 0; kk < 7; ++kk){
      if (acc[kk] > best){ best = acc[kk]; bi = lane + (kk<<5); }
    }
    #pragma unroll
    for (int o = 16; o; o >>= 1){
      float vo = __shfl_xor_sync(FULL, best, o);
      int   io = __shfl_xor_sync(FULL, bi,   o);
      if (vo > best || (vo == best && io < bi)){ best = vo; bi = io; }
    }
    if (lane == 0){
      float period = (float)(bi + MIN_P);
      float f0 = 16000.0f/(period + 1e-8f);
      f0 = fminf(fmaxf(f0, 50.0f), 500.0f);
      float loud = 20.0f*log10f(sqrtf(ss/512.0f) + 1e-8f);
      feat[w][0] = f0; feat[w][1] = loud;
    }
  }
  __syncthreads();

  #pragma unroll
  for (int u = 0; u < 8; ++u){
    float f0 = feat[u][0], ld = feat[u][1];
    float z = f0*W1[tid] + ld*W1[256+tid] + b1[tid];
    h1s[u*256+tid] = z > 0.f ? z : expm1f(z);
  }
  __syncthreads();
  float acc[8];
  #pragma unroll
  for (int u = 0; u < 8; ++u) acc[u] = b2[tid];
  for (int k = 0; k < 256; ++k){
    float wv = W2[k*256 + tid];
    #pragma unroll
    for (int u = 0; u < 8; ++u) acc[u] += h1s[u*256+k]*wv;
  }
  #pragma unroll
  for (int u = 0; u < 8; ++u){
    float z = acc[u];
    h2s[u*256+tid] = z > 0.f ? z : expm1f(z);
  }
  __syncthreads();
  int o = tid & 63;
  for (int pass = 0; pass < 2; ++pass){
    int u = (tid >> 6) + pass*4;
    float a3 = b3[o];
    for (int k = 0; k < 256; ++k) a3 += h2s[u*256+k]*W3[k*64 + o];
    int fr = base + u;
    outc[(size_t)fr*64 + o] = a3;
  }
}

// ---------------- STFT (2 frames packed) -> mag -> mel (sparse scatter) -> linear ----------------
__global__ void k_stft_lin(const float* __restrict__ x){
  __shared__ float Zr[ZLEN], Zi[ZLEN];
  __shared__ float mel[2][NMELS];
  int tid = threadIdx.x;
  int pb = blockIdx.x;
  int b = pb / NPT, pt = pb % NPT;
  int t0 = 2*pt;
  bool hasB = (t0 + 1 < NFR);
  int fr0 = b*NFR + t0;
  const float* xb = x + (size_t)b * T_LEN;
  for (int k = tid; k < 2048; k += 256){
    float w = g_win[k];
    Zr[PAD(k)] = xb[refl(t0*HOP + k - 1024, T_LEN)] * w;
    float vb = 0.f;
    if (hasB) vb = xb[refl((t0+1)*HOP + k - 1024, T_LEN)] * w;
    Zi[PAD(k)] = vb;
  }
  if (tid < 2*NMELS) ((float*)mel)[tid] = 0.f;
  __syncthreads();
  fft2048_r8<1>(Zr, Zi, tid);
  for (int k = tid; k <= 1024; k += 256){
    int m = (2048 - k) & 2047;
    float zkr=Zr[PAD(k)], zki=Zi[PAD(k)], zmr=Zr[PAD(m)], zmi=Zi[PAD(m)];
    float far_ = 0.5f*(zkr + zmr), fai = 0.5f*(zki - zmi);
    float dr = zkr - zmr, di = zki + zmi;
    float fbr = 0.5f*di, fbi = -0.5f*dr;
    float maga = sqrtf(far_*far_ + fai*fai);
    float magb = sqrtf(fbr*fbr + fbi*fbi);
    int i = g_fbi[k];
    float2 w = g_fbw[k];
    if (i >= 0){
      atomicAdd(&mel[0][i], maga*w.x);
      atomicAdd(&mel[1][i], magb*w.x);
      if (w.y != 0.f && i+1 < NMELS){
        atomicAdd(&mel[0][i+1], maga*w.y);
        atomicAdd(&mel[1][i+1], magb*w.y);
      }
    }
  }
  __syncthreads();
  for (int f = tid; f <= 1024; f += 256){
    float src = fmaxf((f + 0.5f)*(80.0f/1025.0f) - 0.5f, 0.0f);
    int i0 = (int)floorf(src); if (i0 > 79) i0 = 79; if (i0 < 0) i0 = 0;
    int i1 = i0 + 1; if (i1 > 79) i1 = 79;
    float w = src - (float)i0;
    g_lin[(size_t)fr0*NBINS + f] = (1.0f - w)*mel[0][i0] + w*mel[0][i1];
    if (hasB) g_lin[(size_t)(fr0+1)*NBINS + f] = (1.0f - w)*mel[1][i0] + w*mel[1][i1];
  }
}

// ---------------- first inverse FFT: inline jax-threefry angles, 2 frames packed ----------------
__global__ void k_ifft0(unsigned kr0,unsigned kr1,unsigned ki0,unsigned ki1){
  __shared__ float Zr[ZLEN], Zi[ZLEN];
  int tid = threadIdx.x;
  int pb = blockIdx.x;
  int b = pb / NPT, pt = pb % NPT;
  int t0 = 2*pt;
  bool hasB = (t0 + 1 < NFR);
  int fr0 = b*NFR + t0;
  const float* lin0 = g_lin + (size_t)fr0*NBINS;
  for (int k = tid; k <= 1024; k += 256){
    float msk = (k == 0 || k == 1024) ? 0.f : 1.f;
    unsigned e = ((unsigned)(b*NBINS + k))*((unsigned)NFR) + (unsigned)t0;
    unsigned r0,r1,i0,i1;
    tf2x32(kr0,kr1, 0u, e, r0,r1);
    tf2x32(ki0,ki1, 0u, e, i0,i1);
    float  L = lin0[k];
    float ar_ = L*u01(r0^r1), ai_ = L*u01(i0^i1)*msk;
    float br_ = 0.f, bi_ = 0.f;
    if (hasB){
      tf2x32(kr0,kr1, 0u, e+1u, r0,r1);
      tf2x32(ki0,ki1, 0u, e+1u, i0,i1);
      float Lb = lin0[NBINS + k];
      br_ = Lb*u01(r0^r1); bi_ = Lb*u01(i0^i1)*msk;
    }
    Zr[PAD(k)] = ar_ - bi_;
    Zi[PAD(k)] = ai_ + br_;
    if (k > 0 && k < 1024){
      int mm = 2048 - k;
      Zr[PAD(mm)] = ar_ + bi_;
      Zi[PAD(mm)] = br_ - ai_;
    }
  }
  __syncthreads();
  fft2048_r8<-1>(Zr, Zi, tid);
  store_pair(Zr, Zi, tid, pb, hasB);
}

// ---------------- fused GL iteration: fwd FFT of inv + phase update + inverse FFT ----------------
__global__ void k_gl(int first){
  __shared__ float Zr[ZLEN], Zi[ZLEN];
  int tid = threadIdx.x;
  int pb = blockIdx.x;
  int b = pb / NPT, pt = pb % NPT;
  int t0 = 2*pt;
  bool hasB = (t0 + 1 < NFR);
  int fr0 = b*NFR + t0;
  const float* xb = g_inv + (size_t)b * T_LEN;
  for (int k = tid; k < 2048; k += 256){
    float w = g_win[k];
    Zr[PAD(k)] = xb[refl(t0*HOP + k - 1024, T_LEN)] * w;
    float vb = 0.f;
    if (hasB) vb = xb[refl((t0+1)*HOP + k - 1024, T_LEN)] * w;
    Zi[PAD(k)] = vb;
  }
  __syncthreads();
  fft2048_r8<1>(Zr, Zi, tid);
  const float* lin0 = g_lin   + (size_t)fr0*NBINS;
  float2*      tpp  = g_tprev + (size_t)fr0*NBINS;
  for (int k = tid; k <= 1024; k += 256){
    int m = (2048 - k) & 2047;
    float zkr=Zr[PAD(k)], zki=Zi[PAD(k)], zmr=Zr[PAD(m)], zmi=Zi[PAD(m)];
    float rar = 0.5f*(zkr + zmr), rai = 0.5f*(zki - zmi);
    float dr = zkr - zmr, di = zki + zmi;
    float rbr = 0.5f*di, rbi = -0.5f*dr;
    float msk = (k == 0 || k == 1024) ? 0.f : 1.f;
    float tpx = 0.f, tpy = 0.f;
    if (!first){ float2 tp = tpp[k]; tpx = tp.x; tpy = tp.y; }
    float ax = rar - MOM*tpx, ay = rai - MOM*tpy;
    float mg = sqrtf(ax*ax + ay*ay) + 1e-16f;
    tpp[k] = make_float2(rar, rai);
    float L = lin0[k];
    float ar_ = L*(ax/mg), ai_ = L*(ay/mg)*msk;
    float br_ = 0.f, bi_ = 0.f;
    if (hasB){
      float tbx = 0.f, tby = 0.f;
      if (!first){ float2 tb = tpp[NBINS + k]; tbx = tb.x; tby = tb.y; }
      float bx = rbr - MOM*tbx, by = rbi - MOM*tby;
      float mb = sqrtf(bx*bx + by*by) + 1e-16f;
      tpp[NBINS + k] = make_float2(rbr, rbi);
      float Lb = lin0[NBINS + k];
      br_ = Lb*(bx/mb); bi_ = Lb*(by/mb)*msk;
    }
    Zr[PAD(k)] = ar_ - bi_;
    Zi[PAD(k)] = ai_ + br_;
    if (k > 0 && k < 1024){
      int mm = 2048 - k;
      Zr[PAD(mm)] = ar_ + bi_;
      Zi[PAD(mm)] = br_ - ai_;
    }
  }
  __syncthreads();
  fft2048_r8<-1>(Zr, Zi, tid);
  store_pair(Zr, Zi, tid, pb, hasB);
}

// ---------------- overlap-add gather over pre-summed pair buffers ----------------
__global__ void k_ola(float* __restrict__ out_final, int is_final){
  int gid = blockIdx.x*blockDim.x + threadIdx.x;
  if (gid >= BATCH*T_LEN) return;
  int b = gid >> 17;
  int i = gid & (T_LEN - 1);
  int pos = i + 1024;
  int plo = (pos >= PLEN) ? (((pos - PLEN) >> 9) + 1) : 0;
  int phi = pos >> 9; if (phi > NPT-1) phi = NPT-1;
  const float* pfb = g_pf + (size_t)b * NPT * PLEN;
  float acc = 0.f;
  for (int p = plo; p <= phi; ++p)
    acc += pfb[(size_t)p*PLEN + (pos - (p<<9))];
  float e = g_env[pos];
  float r = acc / (e > 1e-11f ? e : 1.0f);
  if (is_final) out_final[gid] = r;
  else          g_inv[gid] = r;
}

// ---------------- launch (single stream, serial) ----------------
extern "C" void kernel_launch(void* const* d_in, const int* in_sizes, int n_in,
                              void* d_out, int out_size){
  const float* x  = (const float*)d_in[0];
  const float* W1 = (const float*)d_in[1];
  const float* b1 = (const float*)d_in[2];
  const float* W2 = (const float*)d_in[3];
  const float* b2 = (const float*)d_in[4];
  const float* W3 = (const float*)d_in[5];
  const float* b3 = (const float*)d_in[6];
  float* out  = (float*)d_out;
  float* outc = out + (size_t)BATCH*T_LEN;

  unsigned kr0,kr1,ki0,ki1;
  tf2x32(0u, 42u, 0u, 0u, kr0, kr1);
  tf2x32(0u, 42u, 0u, 1u, ki0, ki1);

  k_fpts<<<1, 128>>>();
  k_tables<<<(2048+L_OLA+NBINS + 255)/256, 256>>>();
  k_feats_mlp<<<NFRT/8, 256>>>(x, W1, b1, W2, b2, W3, b3, outc);
  k_stft_lin<<<NPAIR, 256>>>(x);
  k_ifft0<<<NPAIR, 256>>>(kr0, kr1, ki0, ki1);
  k_ola<<<(BATCH*T_LEN)/256, 256>>>(out, 0);
  for (int it = 1; it <= 4; ++it){
    k_gl<<<NPAIR, 256>>>(it == 1);
    k_ola<<<(BATCH*T_LEN)/256, 256>>>(out, it == 4);
  }
}

// round 10
// speedup vs baseline: 1.5372x; 1.5372x over previous
#include <cuda_runtime.h>
#include <math.h>
#include <stdint.h>

#define BATCH 16
#define T_LEN 131072
#define HOP 256
#define NFFT 2048
#define NBINS 1025
#define NFR 513
#define NFRT (BATCH*NFR)          /* 8208 */
#define NPT 257                    /* frame pairs per batch (last has no B) */
#define NPAIR (BATCH*NPT)          /* 4112 */
#define PLEN 2304                  /* pair-buffer length: 2048 + 256 */
#define NMELS 80
#define MIN_P 32
#define L_OLA 133120               /* NFFT + HOP*(NFR-1) */
#define MOM (0.99f/1.99f)

#define PAD(i) ((i) + ((i)>>3))
#define ZLEN 2304                  /* PAD(2047)=2302 */

// ---------------- scratch (static device globals; no allocs) ----------------
__device__ float  g_fpts[NMELS+2];
__device__ float  g_win[NFFT];
__device__ float  g_env[L_OLA];
__device__ int    g_fbi[NBINS];
__device__ float2 g_fbw[NBINS];
__device__ float  g_lin[NFRT*NBINS];
__device__ float2 g_tprev[NFRT*NBINS];
__device__ float  g_pf[NPAIR*PLEN];     /* pre-summed pair buffers */
__device__ float  g_inv[BATCH*T_LEN];

// ---------------- threefry-2x32-20 (matches jax partitionable) ----------------
__host__ __device__ __forceinline__ unsigned rotl32(unsigned x, int r){ return (x<<r)|(x>>(32-r)); }
__host__ __device__ inline void tf2x32(unsigned k0,unsigned k1,unsigned x0,unsigned x1,unsigned&o0,unsigned&o1){
  unsigned k2 = k0^k1^0x1BD11BDAu;
  x0+=k0; x1+=k1;
  #define TFR(r) { x0+=x1; x1=rotl32(x1,(r)); x1^=x0; }
  TFR(13) TFR(15) TFR(26) TFR(6)  x0+=k1; x1+=k2+1u;
  TFR(17) TFR(29) TFR(16) TFR(24) x0+=k2; x1+=k0+2u;
  TFR(13) TFR(15) TFR(26) TFR(6)  x0+=k0; x1+=k1+3u;
  TFR(17) TFR(29) TFR(16) TFR(24) x0+=k1; x1+=k2+4u;
  TFR(13) TFR(15) TFR(26) TFR(6)  x0+=k2; x1+=k0+5u;
  #undef TFR
  o0=x0; o1=x1;
}
__device__ __forceinline__ float u01(unsigned bits){
  return __uint_as_float((bits>>9) | 0x3f800000u) - 1.0f;
}
__device__ __forceinline__ int refl(int j, int n){
  if (j < 0) j = -j;
  if (j >= n) j = 2*n - 2 - j;
  return j;
}

// ---------------- register radix-8 DFT (DIF), DIR=+1 fwd / -1 inv ----------------
template<int DIR>
__device__ __forceinline__ void dft8(float* ar, float* ai){
  const float r2 = 0.70710678118654752f;
  const float d = (float)DIR;
  float t0r=ar[0]+ar[4], t0i=ai[0]+ai[4];
  float t4r=ar[0]-ar[4], t4i=ai[0]-ai[4];
  float t1r=ar[1]+ar[5], t1i=ai[1]+ai[5];
  float t5r=ar[1]-ar[5], t5i=ai[1]-ai[5];
  float t2r=ar[2]+ar[6], t2i=ai[2]+ai[6];
  float t6r=ar[2]-ar[6], t6i=ai[2]-ai[6];
  float t3r=ar[3]+ar[7], t3i=ai[3]+ai[7];
  float t7r=ar[3]-ar[7], t7i=ai[3]-ai[7];
  { float a=t5r,b=t5i; t5r=r2*(a+d*b); t5i=r2*(b-d*a); }      // *w8^1
  { float a=t6r,b=t6i; t6r=d*b; t6i=-d*a; }                   // *w8^2 = -i*d
  { float a=t7r,b=t7i; t7r=r2*(d*b-a); t7i=-r2*(b+d*a); }     // *w8^3
  float u0r=t0r+t2r,u0i=t0i+t2i, u1r=t0r-t2r,u1i=t0i-t2i;
  float u2r=t1r+t3r,u2i=t1i+t3i, u3r=t1r-t3r,u3i=t1i-t3i;
  float vr=d*u3i, vi=-d*u3r;
  ar[0]=u0r+u2r; ai[0]=u0i+u2i;
  ar[4]=u0r-u2r; ai[4]=u0i-u2i;
  ar[2]=u1r+vr;  ai[2]=u1i+vi;
  ar[6]=u1r-vr;  ai[6]=u1i-vi;
  u0r=t4r+t6r; u0i=t4i+t6i; u1r=t4r-t6r; u1i=t4i-t6i;
  u2r=t5r+t7r; u2i=t5i+t7i; u3r=t5r-t7r; u3i=t5i-t7i;
  vr=d*u3i; vi=-d*u3r;
  ar[1]=u0r+u2r; ai[1]=u0i+u2i;
  ar[5]=u0r-u2r; ai[5]=u0i-u2i;
  ar[3]=u1r+vr;  ai[3]=u1i+vi;
  ar[7]=u1r-vr;  ai[7]=u1i-vi;
}

// ---------------- size-2048 Stockham FFT, radix 8*8*8*4, single SoA buffer ----------------
template<int DIR>
__device__ __forceinline__ void fft2048_r8(float* Zr, float* Zi, int tid){
  #pragma unroll
  for (int st = 0; st < 3; ++st){
    const int s = (st==0) ? 1 : (st==1) ? 8 : 64;
    int q = tid & (s-1);
    int ps = tid - q;
    float ar[8], ai[8];
    #pragma unroll
    for (int j=0;j<8;++j){ int idx = tid + (j<<8); ar[j]=Zr[PAD(idx)]; ai[j]=Zi[PAD(idx)]; }
    __syncthreads();
    dft8<DIR>(ar, ai);
    float sn, cs;
    sincospif((float)ps * (1.0f/1024.0f), &sn, &cs);
    float w1r = cs, w1i = -(float)DIR * sn;
    float wr = w1r, wi = w1i;
    int base = q + (ps<<3);
    Zr[PAD(base)] = ar[0]; Zi[PAD(base)] = ai[0];
    #pragma unroll
    for (int k=1;k<8;++k){
      float br = ar[k]*wr - ai[k]*wi;
      float bi = ar[k]*wi + ai[k]*wr;
      int idx = base + s*k;
      Zr[PAD(idx)] = br; Zi[PAD(idx)] = bi;
      float nwr = wr*w1r - wi*w1i; wi = wr*w1i + wi*w1r; wr = nwr;
    }
    __syncthreads();
  }
  float cr[8], ci[8];
  #pragma unroll
  for (int h=0; h<2; ++h){
    int i = tid + (h<<8);
    #pragma unroll
    for (int j=0;j<4;++j){ int idx = i + (j<<9); cr[h*4+j]=Zr[PAD(idx)]; ci[h*4+j]=Zi[PAD(idx)]; }
  }
  __syncthreads();
  const float d = (float)DIR;
  #pragma unroll
  for (int h=0;h<2;++h){
    int i = tid + (h<<8);
    float u0r=cr[h*4]+cr[h*4+2], u0i=ci[h*4]+ci[h*4+2];
    float u1r=cr[h*4]-cr[h*4+2], u1i=ci[h*4]-ci[h*4+2];
    float u2r=cr[h*4+1]+cr[h*4+3], u2i=ci[h*4+1]+ci[h*4+3];
    float u3r=cr[h*4+1]-cr[h*4+3], u3i=ci[h*4+1]-ci[h*4+3];
    float vr=d*u3i, vi=-d*u3r;
    Zr[PAD(i)]      = u0r+u2r; Zi[PAD(i)]      = u0i+u2i;
    Zr[PAD(i+512)]  = u1r+vr;  Zi[PAD(i+512)]  = u1i+vi;
    Zr[PAD(i+1024)] = u0r-u2r; Zi[PAD(i+1024)] = u0i-u2i;
    Zr[PAD(i+1536)] = u1r-vr;  Zi[PAD(i+1536)] = u1i-vi;
  }
  __syncthreads();
}

// ---------------- store pair buffer: A (Zr) + shifted B (Zi) pre-summed ----------------
__device__ __forceinline__ void store_pair(const float* Zr, const float* Zi,
                                           int tid, int fr0pair, bool hasB){
  float* oa = g_pf + (size_t)fr0pair * PLEN;
  for (int n = tid; n < PLEN; n += 256){
    float v = 0.f;
    if (n < 2048) v = Zr[PAD(n)] * (g_win[n] * (1.0f/2048.0f));
    if (hasB && n >= 256){
      int nb = n - 256;
      v += Zi[PAD(nb)] * (g_win[nb] * (1.0f/2048.0f));
    }
    oa[n] = v;
  }
}

// ---------------- mel breakpoints (82 double pows total, once) ----------------
__global__ void k_fpts(){
  int m = threadIdx.x;
  if (m < NMELS+2){
    double mmax = 2595.0*log10(1.0 + 8000.0/700.0);
    g_fpts[m] = (float)(700.0*(pow(10.0, (double)m*mmax/81.0/2595.0) - 1.0));
  }
}

// ---------------- init tables (all float, no pow) ----------------
__global__ void k_tables(){
  int idx = blockIdx.x*blockDim.x + threadIdx.x;
  if (idx < 2048){
    g_win[idx] = 0.5f - 0.5f*cospif((float)idx * (1.0f/1024.0f));
  } else if (idx < 2048+L_OLA){
    int i = idx - 2048;
    int flo = (i - 1792) >> 8; if (flo < 0) flo = 0;
    int fhi = i >> 8;          if (fhi > NFR-1) fhi = NFR-1;
    float acc = 0.f;
    for (int f = flo; f <= fhi; ++f){
      int n = i - 256*f;
      float w = 0.5f - 0.5f*cospif((float)n * (1.0f/1024.0f));
      acc += w*w;
    }
    g_env[i] = acc;
  } else {
    int f = idx - 2048 - L_OLA;
    if (f < NBINS){
      float freq = (float)f * (8000.0f/1024.0f);
      int first = -1; float w0 = 0.f, w1 = 0.f;
      #pragma unroll 4
      for (int m = 0; m < NMELS; ++m){
        float fp0 = g_fpts[m], fp1 = g_fpts[m+1], fp2 = g_fpts[m+2];
        float dn = (freq - fp0)/(fp1 - fp0);
        float up = (fp2 - freq)/(fp2 - fp1);
        float v = fminf(dn, up);
        if (v > 0.f){
          if (first < 0){ first = m; w0 = v; }
          else w1 = v;
        }
      }
      g_fbi[f] = first;
      g_fbw[f] = make_float2(w0, w1);
    }
  }
}

// ---------------- f0 / loudness (1 frame per warp, shuffle autocorr) + MLP ----------------
__global__ void k_feats_mlp(const float* __restrict__ x,
                            const float* __restrict__ W1, const float* __restrict__ b1,
                            const float* __restrict__ W2, const float* __restrict__ b2,
                            const float* __restrict__ W3, const float* __restrict__ b3,
                            float* __restrict__ outc){
  __shared__ float s[8][768];          // 512 window + zero tail (tap reach 735)
  __shared__ float h1s[8*256];
  __shared__ float h2s[8*256];
  __shared__ float feat[8][2];
  int tid = threadIdx.x;
  int w = tid >> 5, lane = tid & 31;
  int base = blockIdx.x * 8;
  const unsigned FULL = 0xffffffffu;

  {
    int fr = base + w;
    int b = fr / NFR, t = fr % NFR;
    const float* xb = x + (size_t)b * T_LEN;
    for (int k = lane; k < 512; k += 32)
      s[w][k] = xb[refl(t*HOP + k - 256, T_LEN)];
    for (int k = 512 + lane; k < 768; k += 32)
      s[w][k] = 0.f;
    __syncwarp();
    float ss = 0.f;
    for (int k = lane; k < 512; k += 32){ float v = s[w][k]; ss += v*v; }
    #pragma unroll
    for (int o = 16; o; o >>= 1) ss += __shfl_xor_sync(FULL, ss, o);
    float acc[7];
    #pragma unroll
    for (int kk = 0; kk < 7; ++kk) acc[kk] = 0.f;
    for (int T = 0; T < 480; T += 32){
      float p = s[w][T + lane];
      float wreg[8];
      #pragma unroll
      for (int kk = 0; kk < 8; ++kk) wreg[kk] = s[w][T + 32 + lane + (kk<<5)];
      #pragma unroll 8
      for (int j = 0; j < 32; ++j){
        float v0 = __shfl_sync(FULL, p, j);
        int src = (lane + j) & 31;
        bool hi = (lane + j) >= 32;
        float sh[8];
        #pragma unroll
        for (int kk = 0; kk < 8; ++kk) sh[kk] = __shfl_sync(FULL, wreg[kk], src);
        #pragma unroll
        for (int kk = 0; kk < 7; ++kk) acc[kk] += v0 * (hi ? sh[kk+1] : sh[kk]);
      }
    }
    float best = -1e30f; int bi = 0;
    #pragma unroll
    for (int kk = 0; kk < 7; ++kk){
      if (acc[kk] > best){ best = acc[kk]; bi = lane + (kk<<5); }
    }
    #pragma unroll
    for (int o = 16; o; o >>= 1){
      float vo = __shfl_xor_sync(FULL, best, o);
      int   io = __shfl_xor_sync(FULL, bi,   o);
      if (vo > best || (vo == best && io < bi)){ best = vo; bi = io; }
    }
    if (lane == 0){
      float period = (float)(bi + MIN_P);
      float f0 = 16000.0f/(period + 1e-8f);
      f0 = fminf(fmaxf(f0, 50.0f), 500.0f);
      float loud = 20.0f*log10f(sqrtf(ss/512.0f) + 1e-8f);
      feat[w][0] = f0; feat[w][1] = loud;
    }
  }
  __syncthreads();

  #pragma unroll
  for (int u = 0; u < 8; ++u){
    float f0 = feat[u][0], ld = feat[u][1];
    float z = f0*W1[tid] + ld*W1[256+tid] + b1[tid];
    h1s[u*256+tid] = z > 0.f ? z : expm1f(z);
  }
  __syncthreads();
  float acc[8];
  #pragma unroll
  for (int u = 0; u < 8; ++u) acc[u] = b2[tid];
  for (int k = 0; k < 256; ++k){
    float wv = W2[k*256 + tid];
    #pragma unroll
    for (int u = 0; u < 8; ++u) acc[u] += h1s[u*256+k]*wv;
  }
  #pragma unroll
  for (int u = 0; u < 8; ++u){
    float z = acc[u];
    h2s[u*256+tid] = z > 0.f ? z : expm1f(z);
  }
  __syncthreads();
  int o = tid & 63;
  for (int pass = 0; pass < 2; ++pass){
    int u = (tid >> 6) + pass*4;
    float a3 = b3[o];
    for (int k = 0; k < 256; ++k) a3 += h2s[u*256+k]*W3[k*64 + o];
    int fr = base + u;
    outc[(size_t)fr*64 + o] = a3;
  }
}

// ---------------- STFT (2 frames packed) -> mag -> mel (sparse scatter) -> linear ----------------
__global__ void k_stft_lin(const float* __restrict__ x){
  __shared__ float Zr[ZLEN], Zi[ZLEN];
  __shared__ float mel[2][NMELS];
  int tid = threadIdx.x;
  int pb = blockIdx.x;
  int b = pb / NPT, pt = pb % NPT;
  int t0 = 2*pt;
  bool hasB = (t0 + 1 < NFR);
  int fr0 = b*NFR + t0;
  const float* xb = x + (size_t)b * T_LEN;
  for (int k = tid; k < 2048; k += 256){
    float w = g_win[k];
    Zr[PAD(k)] = xb[refl(t0*HOP + k - 1024, T_LEN)] * w;
    float vb = 0.f;
    if (hasB) vb = xb[refl((t0+1)*HOP + k - 1024, T_LEN)] * w;
    Zi[PAD(k)] = vb;
  }
  if (tid < 2*NMELS) ((float*)mel)[tid] = 0.f;
  __syncthreads();
  fft2048_r8<1>(Zr, Zi, tid);
  for (int k = tid; k <= 1024; k += 256){
    int m = (2048 - k) & 2047;
    float zkr=Zr[PAD(k)], zki=Zi[PAD(k)], zmr=Zr[PAD(m)], zmi=Zi[PAD(m)];
    float far_ = 0.5f*(zkr + zmr), fai = 0.5f*(zki - zmi);
    float dr = zkr - zmr, di = zki + zmi;
    float fbr = 0.5f*di, fbi = -0.5f*dr;
    float maga = sqrtf(far_*far_ + fai*fai);
    float magb = sqrtf(fbr*fbr + fbi*fbi);
    int i = g_fbi[k];
    float2 w = g_fbw[k];
    if (i >= 0){
      atomicAdd(&mel[0][i], maga*w.x);
      atomicAdd(&mel[1][i], magb*w.x);
      if (w.y != 0.f && i+1 < NMELS){
        atomicAdd(&mel[0][i+1], maga*w.y);
        atomicAdd(&mel[1][i+1], magb*w.y);
      }
    }
  }
  __syncthreads();
  for (int f = tid; f <= 1024; f += 256){
    float src = fmaxf((f + 0.5f)*(80.0f/1025.0f) - 0.5f, 0.0f);
    int i0 = (int)floorf(src); if (i0 > 79) i0 = 79; if (i0 < 0) i0 = 0;
    int i1 = i0 + 1; if (i1 > 79) i1 = 79;
    float w = src - (float)i0;
    g_lin[(size_t)fr0*NBINS + f] = (1.0f - w)*mel[0][i0] + w*mel[0][i1];
    if (hasB) g_lin[(size_t)(fr0+1)*NBINS + f] = (1.0f - w)*mel[1][i0] + w*mel[1][i1];
  }
}

// ---------------- first inverse FFT: inline jax-threefry angles, 2 frames packed ----------------
__global__ void k_ifft0(unsigned kr0,unsigned kr1,unsigned ki0,unsigned ki1){
  __shared__ float Zr[ZLEN], Zi[ZLEN];
  int tid = threadIdx.x;
  int pb = blockIdx.x;
  int b = pb / NPT, pt = pb % NPT;
  int t0 = 2*pt;
  bool hasB = (t0 + 1 < NFR);
  int fr0 = b*NFR + t0;
  const float* lin0 = g_lin + (size_t)fr0*NBINS;
  for (int k = tid; k <= 1024; k += 256){
    float msk = (k == 0 || k == 1024) ? 0.f : 1.f;
    unsigned e = ((unsigned)(b*NBINS + k))*((unsigned)NFR) + (unsigned)t0;
    unsigned r0,r1,i0,i1;
    tf2x32(kr0,kr1, 0u, e, r0,r1);
    tf2x32(ki0,ki1, 0u, e, i0,i1);
    float  L = lin0[k];
    float ar_ = L*u01(r0^r1), ai_ = L*u01(i0^i1)*msk;
    float br_ = 0.f, bi_ = 0.f;
    if (hasB){
      tf2x32(kr0,kr1, 0u, e+1u, r0,r1);
      tf2x32(ki0,ki1, 0u, e+1u, i0,i1);
      float Lb = lin0[NBINS + k];
      br_ = Lb*u01(r0^r1); bi_ = Lb*u01(i0^i1)*msk;
    }
    Zr[PAD(k)] = ar_ - bi_;
    Zi[PAD(k)] = ai_ + br_;
    if (k > 0 && k < 1024){
      int mm = 2048 - k;
      Zr[PAD(mm)] = ar_ + bi_;
      Zi[PAD(mm)] = br_ - ai_;
    }
  }
  __syncthreads();
  fft2048_r8<-1>(Zr, Zi, tid);
  store_pair(Zr, Zi, tid, pb, hasB);
}

// ---------------- fused GL iteration: fwd FFT of inv + phase update + inverse FFT ----------------
__global__ void k_gl(int first){
  __shared__ float Zr[ZLEN], Zi[ZLEN];
  int tid = threadIdx.x;
  int pb = blockIdx.x;
  int b = pb / NPT, pt = pb % NPT;
  int t0 = 2*pt;
  bool hasB = (t0 + 1 < NFR);
  int fr0 = b*NFR + t0;
  const float* xb = g_inv + (size_t)b * T_LEN;
  for (int k = tid; k < 2048; k += 256){
    float w = g_win[k];
    Zr[PAD(k)] = xb[refl(t0*HOP + k - 1024, T_LEN)] * w;
    float vb = 0.f;
    if (hasB) vb = xb[refl((t0+1)*HOP + k - 1024, T_LEN)] * w;
    Zi[PAD(k)] = vb;
  }
  __syncthreads();
  fft2048_r8<1>(Zr, Zi, tid);
  const float* lin0 = g_lin   + (size_t)fr0*NBINS;
  float2*      tpp  = g_tprev + (size_t)fr0*NBINS;
  for (int k = tid; k <= 1024; k += 256){
    int m = (2048 - k) & 2047;
    float zkr=Zr[PAD(k)], zki=Zi[PAD(k)], zmr=Zr[PAD(m)], zmi=Zi[PAD(m)];
    float rar = 0.5f*(zkr + zmr), rai = 0.5f*(zki - zmi);
    float dr = zkr - zmr, di = zki + zmi;
    float rbr = 0.5f*di, rbi = -0.5f*dr;
    float msk = (k == 0 || k == 1024) ? 0.f : 1.f;
    float tpx = 0.f, tpy = 0.f;
    if (!first){ float2 tp = tpp[k]; tpx = tp.x; tpy = tp.y; }
    float ax = rar - MOM*tpx, ay = rai - MOM*tpy;
    float mg = sqrtf(ax*ax + ay*ay) + 1e-16f;
    tpp[k] = make_float2(rar, rai);
    float L = lin0[k];
    float ar_ = L*(ax/mg), ai_ = L*(ay/mg)*msk;
    float br_ = 0.f, bi_ = 0.f;
    if (hasB){
      float tbx = 0.f, tby = 0.f;
      if (!first){ float2 tb = tpp[NBINS + k]; tbx = tb.x; tby = tb.y; }
      float bx = rbr - MOM*tbx, by = rbi - MOM*tby;
      float mb = sqrtf(bx*bx + by*by) + 1e-16f;
      tpp[NBINS + k] = make_float2(rbr, rbi);
      float Lb = lin0[NBINS + k];
      br_ = Lb*(bx/mb); bi_ = Lb*(by/mb)*msk;
    }
    Zr[PAD(k)] = ar_ - bi_;
    Zi[PAD(k)] = ai_ + br_;
    if (k > 0 && k < 1024){
      int mm = 2048 - k;
      Zr[PAD(mm)] = ar_ + bi_;
      Zi[PAD(mm)] = br_ - ai_;
    }
  }
  __syncthreads();
  fft2048_r8<-1>(Zr, Zi, tid);
  store_pair(Zr, Zi, tid, pb, hasB);
}

// ---------------- overlap-add gather: 4 samples/thread, float4 rows ----------------
__global__ void k_ola(float* __restrict__ out_final, int is_final){
  int q = blockIdx.x*blockDim.x + threadIdx.x;
  if (q >= BATCH*T_LEN/4) return;
  int b = q >> 15;                 /* 32768 quads per batch */
  int i4 = (q & 32767) << 2;
  int pos = i4 + 1024;
  int plo = (pos >= PLEN) ? (((pos - PLEN) >> 9) + 1) : 0;
  int phi = (pos + 3) >> 9; if (phi > NPT-1) phi = NPT-1;
  const float* pfb = g_pf + (size_t)b * NPT * PLEN;
  float a0=0.f, a1=0.f, a2=0.f, a3=0.f;
  for (int p = plo; p <= phi; ++p){
    int off = pos - (p<<9);
    const float* row = pfb + (size_t)p*PLEN;
    if (off >= 0 && off + 3 < PLEN){
      float4 v = *(const float4*)(row + off);
      a0 += v.x; a1 += v.y; a2 += v.z; a3 += v.w;
    } else {
      if (off   >= 0 && off   < PLEN) a0 += row[off];
      if (off+1 >= 0 && off+1 < PLEN) a1 += row[off+1];
      if (off+2 >= 0 && off+2 < PLEN) a2 += row[off+2];
      if (off+3 >= 0 && off+3 < PLEN) a3 += row[off+3];
    }
  }
  float4 ev = *(const float4*)(g_env + pos);
  float4 r;
  r.x = a0 / (ev.x > 1e-11f ? ev.x : 1.f);
  r.y = a1 / (ev.y > 1e-11f ? ev.y : 1.f);
  r.z = a2 / (ev.z > 1e-11f ? ev.z : 1.f);
  r.w = a3 / (ev.w > 1e-11f ? ev.w : 1.f);
  size_t o = ((size_t)b << 17) + i4;
  if (is_final) *(float4*)(out_final + o) = r;
  else          *(float4*)(g_inv + o) = r;
}

// ---------------- launch (single stream, serial) ----------------
extern "C" void kernel_launch(void* const* d_in, const int* in_sizes, int n_in,
                              void* d_out, int out_size){
  const float* x  = (const float*)d_in[0];
  const float* W1 = (const float*)d_in[1];
  const float* b1 = (const float*)d_in[2];
  const float* W2 = (const float*)d_in[3];
  const float* b2 = (const float*)d_in[4];
  const float* W3 = (const float*)d_in[5];
  const float* b3 = (const float*)d_in[6];
  float* out  = (float*)d_out;
  float* outc = out + (size_t)BATCH*T_LEN;

  unsigned kr0,kr1,ki0,ki1;
  tf2x32(0u, 42u, 0u, 0u, kr0, kr1);
  tf2x32(0u, 42u, 0u, 1u, ki0, ki1);

  k_fpts<<<1, 128>>>();
  k_tables<<<(2048+L_OLA+NBINS + 255)/256, 256>>>();
  k_feats_mlp<<<NFRT/8, 256>>>(x, W1, b1, W2, b2, W3, b3, outc);
  k_stft_lin<<<NPAIR, 256>>>(x);
  k_ifft0<<<NPAIR, 256>>>(kr0, kr1, ki0, ki1);
  k_ola<<<(BATCH*T_LEN/4)/256, 256>>>(out, 0);
  for (int it = 1; it <= 4; ++it){
    k_gl<<<NPAIR, 256>>>(it == 1);
    k_ola<<<(BATCH*T_LEN/4)/256, 256>>>(out, it == 4);
  }
}

// round 11
// speedup vs baseline: 1.6458x; 1.0707x over previous
#include <cuda_runtime.h>
#include <math.h>
#include <stdint.h>

#define BATCH 16
#define T_LEN 131072
#define HOP 256
#define NFFT 2048
#define NBINS 1025
#define NFR 513
#define NFRT (BATCH*NFR)          /* 8208 */
#define NPT 257                    /* frame pairs per batch (last has no B) */
#define NPAIR (BATCH*NPT)          /* 4112 */
#define NMELS 80
#define MIN_P 32
#define L_OLA 133120               /* NFFT + HOP*(NFR-1) */
#define MOM (0.99f/1.99f)

#define PAD(i) ((i) + ((i)>>3))
#define ZLEN 2304                  /* PAD(2047)=2302 */

// ---------------- scratch (static device globals; no allocs) ----------------
__device__ float  g_fpts[NMELS+2];
__device__ float  g_win[NFFT];
__device__ float  g_env[L_OLA];
__device__ int    g_fbi[NBINS];
__device__ float2 g_fbw[NBINS];
__device__ float  g_lin[NFRT*NBINS];
__device__ float2 g_tprev[NFRT*NBINS];
__device__ float  g_frames[NFRT*NFFT];
__device__ float  g_inv[BATCH*T_LEN];

// ---------------- threefry-2x32-20 (matches jax partitionable) ----------------
__host__ __device__ __forceinline__ unsigned rotl32(unsigned x, int r){ return (x<<r)|(x>>(32-r)); }
__host__ __device__ inline void tf2x32(unsigned k0,unsigned k1,unsigned x0,unsigned x1,unsigned&o0,unsigned&o1){
  unsigned k2 = k0^k1^0x1BD11BDAu;
  x0+=k0; x1+=k1;
  #define TFR(r) { x0+=x1; x1=rotl32(x1,(r)); x1^=x0; }
  TFR(13) TFR(15) TFR(26) TFR(6)  x0+=k1; x1+=k2+1u;
  TFR(17) TFR(29) TFR(16) TFR(24) x0+=k2; x1+=k0+2u;
  TFR(13) TFR(15) TFR(26) TFR(6)  x0+=k0; x1+=k1+3u;
  TFR(17) TFR(29) TFR(16) TFR(24) x0+=k1; x1+=k2+4u;
  TFR(13) TFR(15) TFR(26) TFR(6)  x0+=k2; x1+=k0+5u;
  #undef TFR
  o0=x0; o1=x1;
}
__device__ __forceinline__ float u01(unsigned bits){
  return __uint_as_float((bits>>9) | 0x3f800000u) - 1.0f;
}
__device__ __forceinline__ int refl(int j, int n){
  if (j < 0) j = -j;
  if (j >= n) j = 2*n - 2 - j;
  return j;
}

// ---------------- register radix-8 DFT (DIF), DIR=+1 fwd / -1 inv ----------------
template<int DIR>
__device__ __forceinline__ void dft8(float* ar, float* ai){
  const float r2 = 0.70710678118654752f;
  const float d = (float)DIR;
  float t0r=ar[0]+ar[4], t0i=ai[0]+ai[4];
  float t4r=ar[0]-ar[4], t4i=ai[0]-ai[4];
  float t1r=ar[1]+ar[5], t1i=ai[1]+ai[5];
  float t5r=ar[1]-ar[5], t5i=ai[1]-ai[5];
  float t2r=ar[2]+ar[6], t2i=ai[2]+ai[6];
  float t6r=ar[2]-ar[6], t6i=ai[2]-ai[6];
  float t3r=ar[3]+ar[7], t3i=ai[3]+ai[7];
  float t7r=ar[3]-ar[7], t7i=ai[3]-ai[7];
  { float a=t5r,b=t5i; t5r=r2*(a+d*b); t5i=r2*(b-d*a); }      // *w8^1
  { float a=t6r,b=t6i; t6r=d*b; t6i=-d*a; }                   // *w8^2 = -i*d
  { float a=t7r,b=t7i; t7r=r2*(d*b-a); t7i=-r2*(b+d*a); }     // *w8^3
  float u0r=t0r+t2r,u0i=t0i+t2i, u1r=t0r-t2r,u1i=t0i-t2i;
  float u2r=t1r+t3r,u2i=t1i+t3i, u3r=t1r-t3r,u3i=t1i-t3i;
  float vr=d*u3i, vi=-d*u3r;
  ar[0]=u0r+u2r; ai[0]=u0i+u2i;
  ar[4]=u0r-u2r; ai[4]=u0i-u2i;
  ar[2]=u1r+vr;  ai[2]=u1i+vi;
  ar[6]=u1r-vr;  ai[6]=u1i-vi;
  u0r=t4r+t6r; u0i=t4i+t6i; u1r=t4r-t6r; u1i=t4i-t6i;
  u2r=t5r+t7r; u2i=t5i+t7i; u3r=t5r-t7r; u3i=t5i-t7i;
  vr=d*u3i; vi=-d*u3r;
  ar[1]=u0r+u2r; ai[1]=u0i+u2i;
  ar[5]=u0r-u2r; ai[5]=u0i-u2i;
  ar[3]=u1r+vr;  ai[3]=u1i+vi;
  ar[7]=u1r-vr;  ai[7]=u1i-vi;
}

// ---------------- size-2048 Stockham FFT, radix 8*8*8*4, single SoA buffer ----------------
template<int DIR>
__device__ __forceinline__ void fft2048_r8(float* Zr, float* Zi, int tid){
  #pragma unroll
  for (int st = 0; st < 3; ++st){
    const int s = (st==0) ? 1 : (st==1) ? 8 : 64;
    int q = tid & (s-1);
    int ps = tid - q;
    float ar[8], ai[8];
    #pragma unroll
    for (int j=0;j<8;++j){ int idx = tid + (j<<8); ar[j]=Zr[PAD(idx)]; ai[j]=Zi[PAD(idx)]; }
    __syncthreads();
    dft8<DIR>(ar, ai);
    float sn, cs;
    sincospif((float)ps * (1.0f/1024.0f), &sn, &cs);
    float w1r = cs, w1i = -(float)DIR * sn;
    float wr = w1r, wi = w1i;
    int base = q + (ps<<3);
    Zr[PAD(base)] = ar[0]; Zi[PAD(base)] = ai[0];
    #pragma unroll
    for (int k=1;k<8;++k){
      float br = ar[k]*wr - ai[k]*wi;
      float bi = ar[k]*wi + ai[k]*wr;
      int idx = base + s*k;
      Zr[PAD(idx)] = br; Zi[PAD(idx)] = bi;
      float nwr = wr*w1r - wi*w1i; wi = wr*w1i + wi*w1r; wr = nwr;
    }
    __syncthreads();
  }
  float cr[8], ci[8];
  #pragma unroll
  for (int h=0; h<2; ++h){
    int i = tid + (h<<8);
    #pragma unroll
    for (int j=0;j<4;++j){ int idx = i + (j<<9); cr[h*4+j]=Zr[PAD(idx)]; ci[h*4+j]=Zi[PAD(idx)]; }
  }
  __syncthreads();
  const float d = (float)DIR;
  #pragma unroll
  for (int h=0;h<2;++h){
    int i = tid + (h<<8);
    float u0r=cr[h*4]+cr[h*4+2], u0i=ci[h*4]+ci[h*4+2];
    float u1r=cr[h*4]-cr[h*4+2], u1i=ci[h*4]-ci[h*4+2];
    float u2r=cr[h*4+1]+cr[h*4+3], u2i=ci[h*4+1]+ci[h*4+3];
    float u3r=cr[h*4+1]-cr[h*4+3], u3i=ci[h*4+1]-ci[h*4+3];
    float vr=d*u3i, vi=-d*u3r;
    Zr[PAD(i)]      = u0r+u2r; Zi[PAD(i)]      = u0i+u2i;
    Zr[PAD(i+512)]  = u1r+vr;  Zi[PAD(i+512)]  = u1i+vi;
    Zr[PAD(i+1024)] = u0r-u2r; Zi[PAD(i+1024)] = u0i-u2i;
    Zr[PAD(i+1536)] = u1r-vr;  Zi[PAD(i+1536)] = u1i-vi;
  }
  __syncthreads();
}

// ---------------- store windowed frames (float4 writes) ----------------
__device__ __forceinline__ void store_frames(const float* Zr, const float* Zi,
                                             int tid, int fr0, bool hasB){
  float* oa = g_frames + (size_t)fr0 * 2048;
  for (int n4 = tid << 2; n4 < 2048; n4 += 1024){
    float4 wv = *(const float4*)(g_win + n4);
    wv.x *= (1.0f/2048.0f); wv.y *= (1.0f/2048.0f);
    wv.z *= (1.0f/2048.0f); wv.w *= (1.0f/2048.0f);
    float4 va;
    va.x = Zr[PAD(n4)]   * wv.x;
    va.y = Zr[PAD(n4+1)] * wv.y;
    va.z = Zr[PAD(n4+2)] * wv.z;
    va.w = Zr[PAD(n4+3)] * wv.w;
    *(float4*)(oa + n4) = va;
    if (hasB){
      float4 vb;
      vb.x = Zi[PAD(n4)]   * wv.x;
      vb.y = Zi[PAD(n4+1)] * wv.y;
      vb.z = Zi[PAD(n4+2)] * wv.z;
      vb.w = Zi[PAD(n4+3)] * wv.w;
      *(float4*)(oa + 2048 + n4) = vb;
    }
  }
}

// ---------------- mel breakpoints (82 double pows total, once) ----------------
__global__ void k_fpts(){
  int m = threadIdx.x;
  if (m < NMELS+2){
    double mmax = 2595.0*log10(1.0 + 8000.0/700.0);
    g_fpts[m] = (float)(700.0*(pow(10.0, (double)m*mmax/81.0/2595.0) - 1.0));
  }
}

// ---------------- init tables (all float, no pow) ----------------
__global__ void k_tables(){
  int idx = blockIdx.x*blockDim.x + threadIdx.x;
  if (idx < 2048){
    g_win[idx] = 0.5f - 0.5f*cospif((float)idx * (1.0f/1024.0f));
  } else if (idx < 2048+L_OLA){
    int i = idx - 2048;
    int flo = (i - 1792) >> 8; if (flo < 0) flo = 0;
    int fhi = i >> 8;          if (fhi > NFR-1) fhi = NFR-1;
    float acc = 0.f;
    for (int f = flo; f <= fhi; ++f){
      int n = i - 256*f;
      float w = 0.5f - 0.5f*cospif((float)n * (1.0f/1024.0f));
      acc += w*w;
    }
    g_env[i] = acc;
  } else {
    int f = idx - 2048 - L_OLA;
    if (f < NBINS){
      float freq = (float)f * (8000.0f/1024.0f);
      int first = -1; float w0 = 0.f, w1 = 0.f;
      #pragma unroll 4
      for (int m = 0; m < NMELS; ++m){
        float fp0 = g_fpts[m], fp1 = g_fpts[m+1], fp2 = g_fpts[m+2];
        float dn = (freq - fp0)/(fp1 - fp0);
        float up = (fp2 - freq)/(fp2 - fp1);
        float v = fminf(dn, up);
        if (v > 0.f){
          if (first < 0){ first = m; w0 = v; }
          else w1 = v;
        }
      }
      g_fbi[f] = first;
      g_fbw[f] = make_float2(w0, w1);
    }
  }
}

// ---------------- f0 / loudness (1 frame per warp, shuffle autocorr) + MLP ----------------
__global__ void k_feats_mlp(const float* __restrict__ x,
                            const float* __restrict__ W1, const float* __restrict__ b1,
                            const float* __restrict__ W2, const float* __restrict__ b2,
                            const float* __restrict__ W3, const float* __restrict__ b3,
                            float* __restrict__ outc){
  __shared__ float s[8][768];          // 512 window + zero tail (tap reach 735)
  __shared__ float h1s[8*256];
  __shared__ float h2s[8*256];
  __shared__ float feat[8][2];
  int tid = threadIdx.x;
  int w = tid >> 5, lane = tid & 31;
  int base = blockIdx.x * 8;
  const unsigned FULL = 0xffffffffu;

  {
    int fr = base + w;
    int b = fr / NFR, t = fr % NFR;
    const float* xb = x + (size_t)b * T_LEN;
    for (int k = lane; k < 512; k += 32)
      s[w][k] = xb[refl(t*HOP + k - 256, T_LEN)];
    for (int k = 512 + lane; k < 768; k += 32)
      s[w][k] = 0.f;
    __syncwarp();
    float ss = 0.f;
    for (int k = lane; k < 512; k += 32){ float v = s[w][k]; ss += v*v; }
    #pragma unroll
    for (int o = 16; o; o >>= 1) ss += __shfl_xor_sync(FULL, ss, o);
    float acc[7];
    #pragma unroll
    for (int kk = 0; kk < 7; ++kk) acc[kk] = 0.f;
    for (int T = 0; T < 480; T += 32){
      float p = s[w][T + lane];
      float wreg[8];
      #pragma unroll
      for (int kk = 0; kk < 8; ++kk) wreg[kk] = s[w][T + 32 + lane + (kk<<5)];
      #pragma unroll 8
      for (int j = 0; j < 32; ++j){
        float v0 = __shfl_sync(FULL, p, j);
        int src = (lane + j) & 31;
        bool hi = (lane + j) >= 32;
        float sh[8];
        #pragma unroll
        for (int kk = 0; kk < 8; ++kk) sh[kk] = __shfl_sync(FULL, wreg[kk], src);
        #pragma unroll
        for (int kk = 0; kk < 7; ++kk) acc[kk] += v0 * (hi ? sh[kk+1] : sh[kk]);
      }
    }
    float best = -1e30f; int bi = 0;
    #pragma unroll
    for (int kk = 0; kk < 7; ++kk){
      if (acc[kk] > best){ best = acc[kk]; bi = lane + (kk<<5); }
    }
    #pragma unroll
    for (int o = 16; o; o >>= 1){
      float vo = __shfl_xor_sync(FULL, best, o);
      int   io = __shfl_xor_sync(FULL, bi,   o);
      if (vo > best || (vo == best && io < bi)){ best = vo; bi = io; }
    }
    if (lane == 0){
      float period = (float)(bi + MIN_P);
      float f0 = 16000.0f/(period + 1e-8f);
      f0 = fminf(fmaxf(f0, 50.0f), 500.0f);
      float loud = 20.0f*log10f(sqrtf(ss/512.0f) + 1e-8f);
      feat[w][0] = f0; feat[w][1] = loud;
    }
  }
  __syncthreads();

  #pragma unroll
  for (int u = 0; u < 8; ++u){
    float f0 = feat[u][0], ld = feat[u][1];
    float z = f0*W1[tid] + ld*W1[256+tid] + b1[tid];
    h1s[u*256+tid] = z > 0.f ? z : expm1f(z);
  }
  __syncthreads();
  float acc[8];
  #pragma unroll
  for (int u = 0; u < 8; ++u) acc[u] = b2[tid];
  for (int k = 0; k < 256; ++k){
    float wv = W2[k*256 + tid];
    #pragma unroll
    for (int u = 0; u < 8; ++u) acc[u] += h1s[u*256+k]*wv;
  }
  #pragma unroll
  for (int u = 0; u < 8; ++u){
    float z = acc[u];
    h2s[u*256+tid] = z > 0.f ? z : expm1f(z);
  }
  __syncthreads();
  int o = tid & 63;
  for (int pass = 0; pass < 2; ++pass){
    int u = (tid >> 6) + pass*4;
    float a3 = b3[o];
    for (int k = 0; k < 256; ++k) a3 += h2s[u*256+k]*W3[k*64 + o];
    int fr = base + u;
    outc[(size_t)fr*64 + o] = a3;
  }
}

// ---------------- STFT (2 frames packed) -> mag -> mel (sparse scatter) -> linear ----------------
__global__ void k_stft_lin(const float* __restrict__ x){
  __shared__ float Zr[ZLEN], Zi[ZLEN];
  __shared__ float mel[2][NMELS];
  int tid = threadIdx.x;
  int pb = blockIdx.x;
  int b = pb / NPT, pt = pb % NPT;
  int t0 = 2*pt;
  bool hasB = (t0 + 1 < NFR);
  int fr0 = b*NFR + t0;
  const float* xb = x + (size_t)b * T_LEN;
  for (int k = tid; k < 2048; k += 256){
    float w = g_win[k];
    Zr[PAD(k)] = xb[refl(t0*HOP + k - 1024, T_LEN)] * w;
    float vb = 0.f;
    if (hasB) vb = xb[refl((t0+1)*HOP + k - 1024, T_LEN)] * w;
    Zi[PAD(k)] = vb;
  }
  if (tid < 2*NMELS) ((float*)mel)[tid] = 0.f;
  __syncthreads();
  fft2048_r8<1>(Zr, Zi, tid);
  for (int k = tid; k <= 1024; k += 256){
    int m = (2048 - k) & 2047;
    float zkr=Zr[PAD(k)], zki=Zi[PAD(k)], zmr=Zr[PAD(m)], zmi=Zi[PAD(m)];
    float far_ = 0.5f*(zkr + zmr), fai = 0.5f*(zki - zmi);
    float dr = zkr - zmr, di = zki + zmi;
    float fbr = 0.5f*di, fbi = -0.5f*dr;
    float maga = sqrtf(far_*far_ + fai*fai);
    float magb = sqrtf(fbr*fbr + fbi*fbi);
    int i = g_fbi[k];
    float2 w = g_fbw[k];
    if (i >= 0){
      atomicAdd(&mel[0][i], maga*w.x);
      atomicAdd(&mel[1][i], magb*w.x);
      if (w.y != 0.f && i+1 < NMELS){
        atomicAdd(&mel[0][i+1], maga*w.y);
        atomicAdd(&mel[1][i+1], magb*w.y);
      }
    }
  }
  __syncthreads();
  for (int f = tid; f <= 1024; f += 256){
    float src = fmaxf((f + 0.5f)*(80.0f/1025.0f) - 0.5f, 0.0f);
    int i0 = (int)floorf(src); if (i0 > 79) i0 = 79; if (i0 < 0) i0 = 0;
    int i1 = i0 + 1; if (i1 > 79) i1 = 79;
    float w = src - (float)i0;
    g_lin[(size_t)fr0*NBINS + f] = (1.0f - w)*mel[0][i0] + w*mel[0][i1];
    if (hasB) g_lin[(size_t)(fr0+1)*NBINS + f] = (1.0f - w)*mel[1][i0] + w*mel[1][i1];
  }
}

// ---------------- first inverse FFT: inline jax-threefry angles, 2 frames packed ----------------
__global__ void k_ifft0(unsigned kr0,unsigned kr1,unsigned ki0,unsigned ki1){
  __shared__ float Zr[ZLEN], Zi[ZLEN];
  int tid = threadIdx.x;
  int pb = blockIdx.x;
  int b = pb / NPT, pt = pb % NPT;
  int t0 = 2*pt;
  bool hasB = (t0 + 1 < NFR);
  int fr0 = b*NFR + t0;
  const float* lin0 = g_lin + (size_t)fr0*NBINS;
  for (int k = tid; k <= 1024; k += 256){
    float msk = (k == 0 || k == 1024) ? 0.f : 1.f;
    unsigned e = ((unsigned)(b*NBINS + k))*((unsigned)NFR) + (unsigned)t0;
    unsigned r0,r1,i0,i1;
    tf2x32(kr0,kr1, 0u, e, r0,r1);
    tf2x32(ki0,ki1, 0u, e, i0,i1);
    float  L = lin0[k];
    float ar_ = L*u01(r0^r1), ai_ = L*u01(i0^i1)*msk;
    float br_ = 0.f, bi_ = 0.f;
    if (hasB){
      tf2x32(kr0,kr1, 0u, e+1u, r0,r1);
      tf2x32(ki0,ki1, 0u, e+1u, i0,i1);
      float Lb = lin0[NBINS + k];
      br_ = Lb*u01(r0^r1); bi_ = Lb*u01(i0^i1)*msk;
    }
    Zr[PAD(k)] = ar_ - bi_;
    Zi[PAD(k)] = ai_ + br_;
    if (k > 0 && k < 1024){
      int mm = 2048 - k;
      Zr[PAD(mm)] = ar_ + bi_;
      Zi[PAD(mm)] = br_ - ai_;
    }
  }
  __syncthreads();
  fft2048_r8<-1>(Zr, Zi, tid);
  store_frames(Zr, Zi, tid, fr0, hasB);
}

// ---------------- fused GL iteration: fwd FFT of inv + phase update + inverse FFT ----------------
__global__ void k_gl(int first){
  __shared__ float Zr[ZLEN], Zi[ZLEN];
  int tid = threadIdx.x;
  int pb = blockIdx.x;
  int b = pb / NPT, pt = pb % NPT;
  int t0 = 2*pt;
  bool hasB = (t0 + 1 < NFR);
  int fr0 = b*NFR + t0;
  const float* xb = g_inv + (size_t)b * T_LEN;
  for (int k = tid; k < 2048; k += 256){
    float w = g_win[k];
    Zr[PAD(k)] = xb[refl(t0*HOP + k - 1024, T_LEN)] * w;
    float vb = 0.f;
    if (hasB) vb = xb[refl((t0+1)*HOP + k - 1024, T_LEN)] * w;
    Zi[PAD(k)] = vb;
  }
  __syncthreads();
  fft2048_r8<1>(Zr, Zi, tid);
  const float* lin0 = g_lin   + (size_t)fr0*NBINS;
  float2*      tpp  = g_tprev + (size_t)fr0*NBINS;
  for (int k = tid; k <= 1024; k += 256){
    int m = (2048 - k) & 2047;
    float zkr=Zr[PAD(k)], zki=Zi[PAD(k)], zmr=Zr[PAD(m)], zmi=Zi[PAD(m)];
    float rar = 0.5f*(zkr + zmr), rai = 0.5f*(zki - zmi);
    float dr = zkr - zmr, di = zki + zmi;
    float rbr = 0.5f*di, rbi = -0.5f*dr;
    float msk = (k == 0 || k == 1024) ? 0.f : 1.f;
    float tpx = 0.f, tpy = 0.f;
    if (!first){ float2 tp = tpp[k]; tpx = tp.x; tpy = tp.y; }
    float ax = rar - MOM*tpx, ay = rai - MOM*tpy;
    float mg = sqrtf(ax*ax + ay*ay) + 1e-16f;
    tpp[k] = make_float2(rar, rai);
    float L = lin0[k];
    float ar_ = L*(ax/mg), ai_ = L*(ay/mg)*msk;
    float br_ = 0.f, bi_ = 0.f;
    if (hasB){
      float tbx = 0.f, tby = 0.f;
      if (!first){ float2 tb = tpp[NBINS + k]; tbx = tb.x; tby = tb.y; }
      float bx = rbr - MOM*tbx, by = rbi - MOM*tby;
      float mb = sqrtf(bx*bx + by*by) + 1e-16f;
      tpp[NBINS + k] = make_float2(rbr, rbi);
      float Lb = lin0[NBINS + k];
      br_ = Lb*(bx/mb); bi_ = Lb*(by/mb)*msk;
    }
    Zr[PAD(k)] = ar_ - bi_;
    Zi[PAD(k)] = ai_ + br_;
    if (k > 0 && k < 1024){
      int mm = 2048 - k;
      Zr[PAD(mm)] = ar_ + bi_;
      Zi[PAD(mm)] = br_ - ai_;
    }
  }
  __syncthreads();
  fft2048_r8<-1>(Zr, Zi, tid);
  store_frames(Zr, Zi, tid, fr0, hasB);
}

// ---------------- overlap-add gather: 4 samples/thread, all-float4, branch-free ----------------
__global__ void k_ola(float* __restrict__ out_final, int is_final){
  int q = blockIdx.x*blockDim.x + threadIdx.x;
  if (q >= BATCH*T_LEN/4) return;
  int b = q >> 15;                 /* 32768 quads per batch */
  int i4 = (q & 32767) << 2;
  int pos = i4 + 1024;
  int flo = (pos - 1792) >> 8; if (flo < 0) flo = 0;
  int fhi = pos >> 8;          if (fhi > NFR-1) fhi = NFR-1;
  const float* fbuf = g_frames + (size_t)b * NFR * 2048;
  float a0=0.f, a1=0.f, a2=0.f, a3=0.f;
  for (int f = flo; f <= fhi; ++f){
    // off = pos-256f: >=0, <=2044, multiple of 4 -> aligned in-range float4
    float4 v = *(const float4*)(fbuf + (size_t)f*2048 + (pos - (f<<8)));
    a0 += v.x; a1 += v.y; a2 += v.z; a3 += v.w;
  }
  float4 ev = *(const float4*)(g_env + pos);
  float4 r;
  r.x = a0 / (ev.x > 1e-11f ? ev.x : 1.f);
  r.y = a1 / (ev.y > 1e-11f ? ev.y : 1.f);
  r.z = a2 / (ev.z > 1e-11f ? ev.z : 1.f);
  r.w = a3 / (ev.w > 1e-11f ? ev.w : 1.f);
  size_t o = ((size_t)b << 17) + i4;
  if (is_final) *(float4*)(out_final + o) = r;
  else          *(float4*)(g_inv + o) = r;
}

// ---------------- launch (single stream, serial) ----------------
extern "C" void kernel_launch(void* const* d_in, const int* in_sizes, int n_in,
                              void* d_out, int out_size){
  const float* x  = (const float*)d_in[0];
  const float* W1 = (const float*)d_in[1];
  const float* b1 = (const float*)d_in[2];
  const float* W2 = (const float*)d_in[3];
  const float* b2 = (const float*)d_in[4];
  const float* W3 = (const float*)d_in[5];
  const float* b3 = (const float*)d_in[6];
  float* out  = (float*)d_out;
  float* outc = out + (size_t)BATCH*T_LEN;

  unsigned kr0,kr1,ki0,ki1;
  tf2x32(0u, 42u, 0u, 0u, kr0, kr1);
  tf2x32(0u, 42u, 0u, 1u, ki0, ki1);

  k_fpts<<<1, 128>>>();
  k_tables<<<(2048+L_OLA+NBINS + 255)/256, 256>>>();
  k_feats_mlp<<<NFRT/8, 256>>>(x, W1, b1, W2, b2, W3, b3, outc);
  k_stft_lin<<<NPAIR, 256>>>(x);
  k_ifft0<<<NPAIR, 256>>>(kr0, kr1, ki0, ki1);
  k_ola<<<(BATCH*T_LEN/4)/256, 256>>>(out, 0);
  for (int it = 1; it <= 4; ++it){
    k_gl<<<NPAIR, 256>>>(it == 1);
    k_ola<<<(BATCH*T_LEN/4)/256, 256>>>(out, it == 4);
  }
}

// round 12
// speedup vs baseline: 1.7714x; 1.0763x over previous
#include <cuda_runtime.h>
#include <math.h>
#include <stdint.h>

#define BATCH 16
#define T_LEN 131072
#define HOP 256
#define NFFT 2048
#define NBINS 1025
#define NFR 513
#define NFRT (BATCH*NFR)          /* 8208 */
#define NPT 257                    /* frame pairs per batch (last has no B) */
#define NPAIR (BATCH*NPT)          /* 4112 */
#define NMELS 80
#define MIN_P 32
#define L_OLA 133120               /* NFFT + HOP*(NFR-1) */
#define MOM (0.99f/1.99f)

#define PAD(i) ((i) + ((i)>>3))
#define ZLEN 2304                  /* PAD(2047)=2302 */

// ---------------- scratch (static device globals; no allocs) ----------------
__device__ float  g_fpts[NMELS+2];
__device__ float  g_win[NFFT];
__device__ float  g_env[L_OLA];
__device__ int    g_fbi[NBINS];
__device__ float2 g_fbw[NBINS];
__device__ float  g_lin[NFRT*NBINS];
__device__ float2 g_tprev[NFRT*NBINS];
__device__ float  g_frames[NFRT*NFFT];
__device__ float  g_inv[BATCH*T_LEN];

// ---------------- threefry-2x32-20 (matches jax partitionable) ----------------
__host__ __device__ __forceinline__ unsigned rotl32(unsigned x, int r){ return (x<<r)|(x>>(32-r)); }
__host__ __device__ inline void tf2x32(unsigned k0,unsigned k1,unsigned x0,unsigned x1,unsigned&o0,unsigned&o1){
  unsigned k2 = k0^k1^0x1BD11BDAu;
  x0+=k0; x1+=k1;
  #define TFR(r) { x0+=x1; x1=rotl32(x1,(r)); x1^=x0; }
  TFR(13) TFR(15) TFR(26) TFR(6)  x0+=k1; x1+=k2+1u;
  TFR(17) TFR(29) TFR(16) TFR(24) x0+=k2; x1+=k0+2u;
  TFR(13) TFR(15) TFR(26) TFR(6)  x0+=k0; x1+=k1+3u;
  TFR(17) TFR(29) TFR(16) TFR(24) x0+=k1; x1+=k2+4u;
  TFR(13) TFR(15) TFR(26) TFR(6)  x0+=k2; x1+=k0+5u;
  #undef TFR
  o0=x0; o1=x1;
}
__device__ __forceinline__ float u01(unsigned bits){
  return __uint_as_float((bits>>9) | 0x3f800000u) - 1.0f;
}
__device__ __forceinline__ int refl(int j, int n){
  if (j < 0) j = -j;
  if (j >= n) j = 2*n - 2 - j;
  return j;
}

// ---------------- register radix-8 DFT (DIF), DIR=+1 fwd / -1 inv ----------------
template<int DIR>
__device__ __forceinline__ void dft8(float* ar, float* ai){
  const float r2 = 0.70710678118654752f;
  const float d = (float)DIR;
  float t0r=ar[0]+ar[4], t0i=ai[0]+ai[4];
  float t4r=ar[0]-ar[4], t4i=ai[0]-ai[4];
  float t1r=ar[1]+ar[5], t1i=ai[1]+ai[5];
  float t5r=ar[1]-ar[5], t5i=ai[1]-ai[5];
  float t2r=ar[2]+ar[6], t2i=ai[2]+ai[6];
  float t6r=ar[2]-ar[6], t6i=ai[2]-ai[6];
  float t3r=ar[3]+ar[7], t3i=ai[3]+ai[7];
  float t7r=ar[3]-ar[7], t7i=ai[3]-ai[7];
  { float a=t5r,b=t5i; t5r=r2*(a+d*b); t5i=r2*(b-d*a); }      // *w8^1
  { float a=t6r,b=t6i; t6r=d*b; t6i=-d*a; }                   // *w8^2 = -i*d
  { float a=t7r,b=t7i; t7r=r2*(d*b-a); t7i=-r2*(b+d*a); }     // *w8^3
  float u0r=t0r+t2r,u0i=t0i+t2i, u1r=t0r-t2r,u1i=t0i-t2i;
  float u2r=t1r+t3r,u2i=t1i+t3i, u3r=t1r-t3r,u3i=t1i-t3i;
  float vr=d*u3i, vi=-d*u3r;
  ar[0]=u0r+u2r; ai[0]=u0i+u2i;
  ar[4]=u0r-u2r; ai[4]=u0i-u2i;
  ar[2]=u1r+vr;  ai[2]=u1i+vi;
  ar[6]=u1r-vr;  ai[6]=u1i-vi;
  u0r=t4r+t6r; u0i=t4i+t6i; u1r=t4r-t6r; u1i=t4i-t6i;
  u2r=t5r+t7r; u2i=t5i+t7i; u3r=t5r-t7r; u3i=t5i-t7i;
  vr=d*u3i; vi=-d*u3r;
  ar[1]=u0r+u2r; ai[1]=u0i+u2i;
  ar[5]=u0r-u2r; ai[5]=u0i-u2i;
  ar[3]=u1r+vr;  ai[3]=u1i+vi;
  ar[7]=u1r-vr;  ai[7]=u1i-vi;
}

// ---------------- size-2048 Stockham FFT, radix 8*8*8*4, single SoA buffer ----------------
template<int DIR>
__device__ __forceinline__ void fft2048_r8(float* Zr, float* Zi, int tid){
  #pragma unroll
  for (int st = 0; st < 3; ++st){
    const int s = (st==0) ? 1 : (st==1) ? 8 : 64;
    int q = tid & (s-1);
    int ps = tid - q;
    float ar[8], ai[8];
    #pragma unroll
    for (int j=0;j<8;++j){ int idx = tid + (j<<8); ar[j]=Zr[PAD(idx)]; ai[j]=Zi[PAD(idx)]; }
    __syncthreads();
    dft8<DIR>(ar, ai);
    float sn, cs;
    sincospif((float)ps * (1.0f/1024.0f), &sn, &cs);
    float w1r = cs, w1i = -(float)DIR * sn;
    // log-depth twiddle tree (depth 3 instead of chained depth 7)
    float twr[8], twi[8];
    twr[1]=w1r;                       twi[1]=w1i;
    twr[2]=w1r*w1r - w1i*w1i;         twi[2]=2.f*w1r*w1i;
    twr[3]=twr[2]*w1r - twi[2]*w1i;   twi[3]=twr[2]*w1i + twi[2]*w1r;
    twr[4]=twr[2]*twr[2]-twi[2]*twi[2]; twi[4]=2.f*twr[2]*twi[2];
    twr[5]=twr[4]*w1r - twi[4]*w1i;   twi[5]=twr[4]*w1i + twi[4]*w1r;
    twr[6]=twr[4]*twr[2]-twi[4]*twi[2]; twi[6]=twr[4]*twi[2]+twi[4]*twr[2];
    twr[7]=twr[4]*twr[3]-twi[4]*twi[3]; twi[7]=twr[4]*twi[3]+twi[4]*twr[3];
    int base = q + (ps<<3);
    Zr[PAD(base)] = ar[0]; Zi[PAD(base)] = ai[0];
    #pragma unroll
    for (int k=1;k<8;++k){
      float br = ar[k]*twr[k] - ai[k]*twi[k];
      float bi = ar[k]*twi[k] + ai[k]*twr[k];
      int idx = base + s*k;
      Zr[PAD(idx)] = br; Zi[PAD(idx)] = bi;
    }
    __syncthreads();
  }
  float cr[8], ci[8];
  #pragma unroll
  for (int h=0; h<2; ++h){
    int i = tid + (h<<8);
    #pragma unroll
    for (int j=0;j<4;++j){ int idx = i + (j<<9); cr[h*4+j]=Zr[PAD(idx)]; ci[h*4+j]=Zi[PAD(idx)]; }
  }
  __syncthreads();
  const float d = (float)DIR;
  #pragma unroll
  for (int h=0;h<2;++h){
    int i = tid + (h<<8);
    float u0r=cr[h*4]+cr[h*4+2], u0i=ci[h*4]+ci[h*4+2];
    float u1r=cr[h*4]-cr[h*4+2], u1i=ci[h*4]-ci[h*4+2];
    float u2r=cr[h*4+1]+cr[h*4+3], u2i=ci[h*4+1]+ci[h*4+3];
    float u3r=cr[h*4+1]-cr[h*4+3], u3i=ci[h*4+1]-ci[h*4+3];
    float vr=d*u3i, vi=-d*u3r;
    Zr[PAD(i)]      = u0r+u2r; Zi[PAD(i)]      = u0i+u2i;
    Zr[PAD(i+512)]  = u1r+vr;  Zi[PAD(i+512)]  = u1i+vi;
    Zr[PAD(i+1024)] = u0r-u2r; Zi[PAD(i+1024)] = u0i-u2i;
    Zr[PAD(i+1536)] = u1r-vr;  Zi[PAD(i+1536)] = u1i-vi;
  }
  __syncthreads();
}

// ---------------- store windowed frames (float4 writes) ----------------
__device__ __forceinline__ void store_frames(const float* Zr, const float* Zi,
                                             int tid, int fr0, bool hasB){
  float* oa = g_frames + (size_t)fr0 * 2048;
  for (int n4 = tid << 2; n4 < 2048; n4 += 1024){
    float4 wv = *(const float4*)(g_win + n4);
    wv.x *= (1.0f/2048.0f); wv.y *= (1.0f/2048.0f);
    wv.z *= (1.0f/2048.0f); wv.w *= (1.0f/2048.0f);
    float4 va;
    va.x = Zr[PAD(n4)]   * wv.x;
    va.y = Zr[PAD(n4+1)] * wv.y;
    va.z = Zr[PAD(n4+2)] * wv.z;
    va.w = Zr[PAD(n4+3)] * wv.w;
    *(float4*)(oa + n4) = va;
    if (hasB){
      float4 vb;
      vb.x = Zi[PAD(n4)]   * wv.x;
      vb.y = Zi[PAD(n4+1)] * wv.y;
      vb.z = Zi[PAD(n4+2)] * wv.z;
      vb.w = Zi[PAD(n4+3)] * wv.w;
      *(float4*)(oa + 2048 + n4) = vb;
    }
  }
}

// ---------------- mel breakpoints (82 double pows total, once) ----------------
__global__ void k_fpts(){
  int m = threadIdx.x;
  if (m < NMELS+2){
    double mmax = 2595.0*log10(1.0 + 8000.0/700.0);
    g_fpts[m] = (float)(700.0*(pow(10.0, (double)m*mmax/81.0/2595.0) - 1.0));
  }
}

// ---------------- init tables (all float, no pow) ----------------
__global__ void k_tables(){
  int idx = blockIdx.x*blockDim.x + threadIdx.x;
  if (idx < 2048){
    g_win[idx] = 0.5f - 0.5f*cospif((float)idx * (1.0f/1024.0f));
  } else if (idx < 2048+L_OLA){
    int i = idx - 2048;
    int flo = (i - 1792) >> 8; if (flo < 0) flo = 0;
    int fhi = i >> 8;          if (fhi > NFR-1) fhi = NFR-1;
    float acc = 0.f;
    for (int f = flo; f <= fhi; ++f){
      int n = i - 256*f;
      float w = 0.5f - 0.5f*cospif((float)n * (1.0f/1024.0f));
      acc += w*w;
    }
    g_env[i] = acc;
  } else {
    int f = idx - 2048 - L_OLA;
    if (f < NBINS){
      float freq = (float)f * (8000.0f/1024.0f);
      int first = -1; float w0 = 0.f, w1 = 0.f;
      #pragma unroll 4
      for (int m = 0; m < NMELS; ++m){
        float fp0 = g_fpts[m], fp1 = g_fpts[m+1], fp2 = g_fpts[m+2];
        float dn = (freq - fp0)/(fp1 - fp0);
        float up = (fp2 - freq)/(fp2 - fp1);
        float v = fminf(dn, up);
        if (v > 0.f){
          if (first < 0){ first = m; w0 = v; }
          else w1 = v;
        }
      }
      g_fbi[f] = first;
      g_fbw[f] = make_float2(w0, w1);
    }
  }
}

// ---------------- f0 / loudness (1 frame per warp, shuffle autocorr) + MLP ----------------
__global__ void k_feats_mlp(const float* __restrict__ x,
                            const float* __restrict__ W1, const float* __restrict__ b1,
                            const float* __restrict__ W2, const float* __restrict__ b2,
                            const float* __restrict__ W3, const float* __restrict__ b3,
                            float* __restrict__ outc){
  __shared__ float s[8][768];          // 512 window + zero tail (tap reach 735)
  __shared__ float h1s[8*256];
  __shared__ float h2s[8*256];
  __shared__ float feat[8][2];
  int tid = threadIdx.x;
  int w = tid >> 5, lane = tid & 31;
  int base = blockIdx.x * 8;
  const unsigned FULL = 0xffffffffu;

  {
    int fr = base + w;
    int b = fr / NFR, t = fr % NFR;
    const float* xb = x + (size_t)b * T_LEN;
    for (int k = lane; k < 512; k += 32)
      s[w][k] = xb[refl(t*HOP + k - 256, T_LEN)];
    for (int k = 512 + lane; k < 768; k += 32)
      s[w][k] = 0.f;
    __syncwarp();
    float ss = 0.f;
    for (int k = lane; k < 512; k += 32){ float v = s[w][k]; ss += v*v; }
    #pragma unroll
    for (int o = 16; o; o >>= 1) ss += __shfl_xor_sync(FULL, ss, o);
    float acc[7];
    #pragma unroll
    for (int kk = 0; kk < 7; ++kk) acc[kk] = 0.f;
    for (int T = 0; T < 480; T += 32){
      float p = s[w][T + lane];
      float wreg[8];
      #pragma unroll
      for (int kk = 0; kk < 8; ++kk) wreg[kk] = s[w][T + 32 + lane + (kk<<5)];
      #pragma unroll 8
      for (int j = 0; j < 32; ++j){
        float v0 = __shfl_sync(FULL, p, j);
        int src = (lane + j) & 31;
        bool hi = (lane + j) >= 32;
        float sh[8];
        #pragma unroll
        for (int kk = 0; kk < 8; ++kk) sh[kk] = __shfl_sync(FULL, wreg[kk], src);
        #pragma unroll
        for (int kk = 0; kk < 7; ++kk) acc[kk] += v0 * (hi ? sh[kk+1] : sh[kk]);
      }
    }
    float best = -1e30f; int bi = 0;
    #pragma unroll
    for (int kk = 0; kk < 7; ++kk){
      if (acc[kk] > best){ best = acc[kk]; bi = lane + (kk<<5); }
    }
    #pragma unroll
    for (int o = 16; o; o >>= 1){
      float vo = __shfl_xor_sync(FULL, best, o);
      int   io = __shfl_xor_sync(FULL, bi,   o);
      if (vo > best || (vo == best && io < bi)){ best = vo; bi = io; }
    }
    if (lane == 0){
      float period = (float)(bi + MIN_P);
      float f0 = 16000.0f/(period + 1e-8f);
      f0 = fminf(fmaxf(f0, 50.0f), 500.0f);
      float loud = 20.0f*log10f(sqrtf(ss/512.0f) + 1e-8f);
      feat[w][0] = f0; feat[w][1] = loud;
    }
  }
  __syncthreads();

  #pragma unroll
  for (int u = 0; u < 8; ++u){
    float f0 = feat[u][0], ld = feat[u][1];
    float z = f0*W1[tid] + ld*W1[256+tid] + b1[tid];
    h1s[u*256+tid] = z > 0.f ? z : expm1f(z);
  }
  __syncthreads();
  float acc[8];
  #pragma unroll
  for (int u = 0; u < 8; ++u) acc[u] = b2[tid];
  for (int k = 0; k < 256; ++k){
    float wv = W2[k*256 + tid];
    #pragma unroll
    for (int u = 0; u < 8; ++u) acc[u] += h1s[u*256+k]*wv;
  }
  #pragma unroll
  for (int u = 0; u < 8; ++u){
    float z = acc[u];
    h2s[u*256+tid] = z > 0.f ? z : expm1f(z);
  }
  __syncthreads();
  int o = tid & 63;
  for (int pass = 0; pass < 2; ++pass){
    int u = (tid >> 6) + pass*4;
    float a3 = b3[o];
    for (int k = 0; k < 256; ++k) a3 += h2s[u*256+k]*W3[k*64 + o];
    int fr = base + u;
    outc[(size_t)fr*64 + o] = a3;
  }
}

// ---------------- FUSED: STFT -> mag -> mel -> linear -> random phases -> iFFT -> frames ----------------
__global__ void k_stft_ifft0(const float* __restrict__ x,
                             unsigned kr0,unsigned kr1,unsigned ki0,unsigned ki1){
  __shared__ float Zr[ZLEN], Zi[ZLEN];
  __shared__ float mel[2][NMELS];
  int tid = threadIdx.x;
  int pb = blockIdx.x;
  int b = pb / NPT, pt = pb % NPT;
  int t0 = 2*pt;
  bool hasB = (t0 + 1 < NFR);
  int fr0 = b*NFR + t0;
  const float* xb = x + (size_t)b * T_LEN;
  for (int k = tid; k < 2048; k += 256){
    float w = g_win[k];
    Zr[PAD(k)] = xb[refl(t0*HOP + k - 1024, T_LEN)] * w;
    float vb = 0.f;
    if (hasB) vb = xb[refl((t0+1)*HOP + k - 1024, T_LEN)] * w;
    Zi[PAD(k)] = vb;
  }
  if (tid < 2*NMELS) ((float*)mel)[tid] = 0.f;
  __syncthreads();
  fft2048_r8<1>(Zr, Zi, tid);
  for (int k = tid; k <= 1024; k += 256){
    int m = (2048 - k) & 2047;
    float zkr=Zr[PAD(k)], zki=Zi[PAD(k)], zmr=Zr[PAD(m)], zmi=Zi[PAD(m)];
    float far_ = 0.5f*(zkr + zmr), fai = 0.5f*(zki - zmi);
    float dr = zkr - zmr, di = zki + zmi;
    float fbr = 0.5f*di, fbi = -0.5f*dr;
    float maga = sqrtf(far_*far_ + fai*fai);
    float magb = sqrtf(fbr*fbr + fbi*fbi);
    int i = g_fbi[k];
    float2 w = g_fbw[k];
    if (i >= 0){
      atomicAdd(&mel[0][i], maga*w.x);
      atomicAdd(&mel[1][i], magb*w.x);
      if (w.y != 0.f && i+1 < NMELS){
        atomicAdd(&mel[0][i+1], maga*w.y);
        atomicAdd(&mel[1][i+1], magb*w.y);
      }
    }
  }
  __syncthreads();
  // merged: mel->linear (write g_lin for GL loop) + threefry angles + Hermitian pack.
  // After the sync above no thread reads Z anymore, and each thread's writes
  // {k, 2048-k} are disjoint across threads -> in-place overwrite is safe.
  for (int k = tid; k <= 1024; k += 256){
    float src = fmaxf((k + 0.5f)*(80.0f/1025.0f) - 0.5f, 0.0f);
    int i0 = (int)floorf(src); if (i0 > 79) i0 = 79; if (i0 < 0) i0 = 0;
    int i1 = i0 + 1; if (i1 > 79) i1 = 79;
    float wq = src - (float)i0;
    float L  = (1.0f - wq)*mel[0][i0] + wq*mel[0][i1];
    float Lb = (1.0f - wq)*mel[1][i0] + wq*mel[1][i1];
    g_lin[(size_t)fr0*NBINS + k] = L;
    if (hasB) g_lin[(size_t)(fr0+1)*NBINS + k] = Lb;
    float msk = (k == 0 || k == 1024) ? 0.f : 1.f;
    unsigned e = ((unsigned)(b*NBINS + k))*((unsigned)NFR) + (unsigned)t0;
    unsigned r0,r1,i0u,i1u;
    tf2x32(kr0,kr1, 0u, e, r0,r1);
    tf2x32(ki0,ki1, 0u, e, i0u,i1u);
    float ar_ = L*u01(r0^r1), ai_ = L*u01(i0u^i1u)*msk;
    float br_ = 0.f, bi_ = 0.f;
    if (hasB){
      tf2x32(kr0,kr1, 0u, e+1u, r0,r1);
      tf2x32(ki0,ki1, 0u, e+1u, i0u,i1u);
      br_ = Lb*u01(r0^r1); bi_ = Lb*u01(i0u^i1u)*msk;
    }
    Zr[PAD(k)] = ar_ - bi_;
    Zi[PAD(k)] = ai_ + br_;
    if (k > 0 && k < 1024){
      int mm = 2048 - k;
      Zr[PAD(mm)] = ar_ + bi_;
      Zi[PAD(mm)] = br_ - ai_;
    }
  }
  __syncthreads();
  fft2048_r8<-1>(Zr, Zi, tid);
  store_frames(Zr, Zi, tid, fr0, hasB);
}

// ---------------- fused GL iteration: fwd FFT of inv + phase update + inverse FFT ----------------
__global__ void __launch_bounds__(256, 6) k_gl(int first){
  __shared__ float Zr[ZLEN], Zi[ZLEN];
  int tid = threadIdx.x;
  int pb = blockIdx.x;
  int b = pb / NPT, pt = pb % NPT;
  int t0 = 2*pt;
  bool hasB = (t0 + 1 < NFR);
  int fr0 = b*NFR + t0;
  const float* xb = g_inv + (size_t)b * T_LEN;
  for (int k = tid; k < 2048; k += 256){
    float w = g_win[k];
    Zr[PAD(k)] = xb[refl(t0*HOP + k - 1024, T_LEN)] * w;
    float vb = 0.f;
    if (hasB) vb = xb[refl((t0+1)*HOP + k - 1024, T_LEN)] * w;
    Zi[PAD(k)] = vb;
  }
  __syncthreads();
  fft2048_r8<1>(Zr, Zi, tid);
  const float* lin0 = g_lin   + (size_t)fr0*NBINS;
  float2*      tpp  = g_tprev + (size_t)fr0*NBINS;
  for (int k = tid; k <= 1024; k += 256){
    int m = (2048 - k) & 2047;
    float zkr=Zr[PAD(k)], zki=Zi[PAD(k)], zmr=Zr[PAD(m)], zmi=Zi[PAD(m)];
    float rar = 0.5f*(zkr + zmr), rai = 0.5f*(zki - zmi);
    float dr = zkr - zmr, di = zki + zmi;
    float rbr = 0.5f*di, rbi = -0.5f*dr;
    float msk = (k == 0 || k == 1024) ? 0.f : 1.f;
    float tpx = 0.f, tpy = 0.f;
    if (!first){ float2 tp = tpp[k]; tpx = tp.x; tpy = tp.y; }
    float ax = rar - MOM*tpx, ay = rai - MOM*tpy;
    float mg = sqrtf(ax*ax + ay*ay) + 1e-16f;
    tpp[k] = make_float2(rar, rai);
    float L = lin0[k];
    float ar_ = L*(ax/mg), ai_ = L*(ay/mg)*msk;
    float br_ = 0.f, bi_ = 0.f;
    if (hasB){
      float tbx = 0.f, tby = 0.f;
      if (!first){ float2 tb = tpp[NBINS + k]; tbx = tb.x; tby = tb.y; }
      float bx = rbr - MOM*tbx, by = rbi - MOM*tby;
      float mb = sqrtf(bx*bx + by*by) + 1e-16f;
      tpp[NBINS + k] = make_float2(rbr, rbi);
      float Lb = lin0[NBINS + k];
      br_ = Lb*(bx/mb); bi_ = Lb*(by/mb)*msk;
    }
    Zr[PAD(k)] = ar_ - bi_;
    Zi[PAD(k)] = ai_ + br_;
    if (k > 0 && k < 1024){
      int mm = 2048 - k;
      Zr[PAD(mm)] = ar_ + bi_;
      Zi[PAD(mm)] = br_ - ai_;
    }
  }
  __syncthreads();
  fft2048_r8<-1>(Zr, Zi, tid);
  store_frames(Zr, Zi, tid, fr0, hasB);
}

// ---------------- overlap-add gather: 4 samples/thread, all-float4, branch-free ----------------
__global__ void k_ola(float* __restrict__ out_final, int is_final){
  int q = blockIdx.x*blockDim.x + threadIdx.x;
  if (q >= BATCH*T_LEN/4) return;
  int b = q >> 15;                 /* 32768 quads per batch */
  int i4 = (q & 32767) << 2;
  int pos = i4 + 1024;
  int flo = (pos - 1792) >> 8; if (flo < 0) flo = 0;
  int fhi = pos >> 8;          if (fhi > NFR-1) fhi = NFR-1;
  const float* fbuf = g_frames + (size_t)b * NFR * 2048;
  float a0=0.f, a1=0.f, a2=0.f, a3=0.f;
  for (int f = flo; f <= fhi; ++f){
    float4 v = *(const float4*)(fbuf + (size_t)f*2048 + (pos - (f<<8)));
    a0 += v.x; a1 += v.y; a2 += v.z; a3 += v.w;
  }
  float4 ev = *(const float4*)(g_env + pos);
  float4 r;
  r.x = a0 / (ev.x > 1e-11f ? ev.x : 1.f);
  r.y = a1 / (ev.y > 1e-11f ? ev.y : 1.f);
  r.z = a2 / (ev.z > 1e-11f ? ev.z : 1.f);
  r.w = a3 / (ev.w > 1e-11f ? ev.w : 1.f);
  size_t o = ((size_t)b << 17) + i4;
  if (is_final) *(float4*)(out_final + o) = r;
  else          *(float4*)(g_inv + o) = r;
}

// ---------------- launch (single stream, serial) ----------------
extern "C" void kernel_launch(void* const* d_in, const int* in_sizes, int n_in,
                              void* d_out, int out_size){
  const float* x  = (const float*)d_in[0];
  const float* W1 = (const float*)d_in[1];
  const float* b1 = (const float*)d_in[2];
  const float* W2 = (const float*)d_in[3];
  const float* b2 = (const float*)d_in[4];
  const float* W3 = (const float*)d_in[5];
  const float* b3 = (const float*)d_in[6];
  float* out  = (float*)d_out;
  float* outc = out + (size_t)BATCH*T_LEN;

  unsigned kr0,kr1,ki0,ki1;
  tf2x32(0u, 42u, 0u, 0u, kr0, kr1);
  tf2x32(0u, 42u, 0u, 1u, ki0, ki1);

  k_fpts<<<1, 128>>>();
  k_tables<<<(2048+L_OLA+NBINS + 255)/256, 256>>>();
  k_feats_mlp<<<NFRT/8, 256>>>(x, W1, b1, W2, b2, W3, b3, outc);
  k_stft_ifft0<<<NPAIR, 256>>>(x, kr0, kr1, ki0, ki1);
  k_ola<<<(BATCH*T_LEN/4)/256, 256>>>(out, 0);
  for (int it = 1; it <= 4; ++it){
    k_gl<<<NPAIR, 256>>>(it == 1);
    k_ola<<<(BATCH*T_LEN/4)/256, 256>>>(out, it == 4);
  }
}

// round 13
// speedup vs baseline: 1.8246x; 1.0300x over previous
#include <cuda_runtime.h>
#include <math.h>
#include <stdint.h>

#define BATCH 16
#define T_LEN 131072
#define HOP 256
#define NFFT 2048
#define NBINS 1025
#define NFR 513
#define NFRT (BATCH*NFR)          /* 8208 */
#define NPT 257                    /* frame pairs per batch (last has no B) */
#define NPAIR (BATCH*NPT)          /* 4112 */
#define NMELS 80
#define MIN_P 32
#define L_OLA 133120               /* NFFT + HOP*(NFR-1) */
#define MOM (0.99f/1.99f)

#define PAD(i) ((i) + ((i)>>3))
#define ZLEN 2304                  /* PAD(2047)=2302 */

// ---------------- scratch (static device globals; no allocs) ----------------
__device__ float  g_fpts[NMELS+2];
__device__ float  g_win[NFFT];
__device__ float  g_env[L_OLA];
__device__ int    g_fbi[NBINS];
__device__ float2 g_fbw[NBINS];
__device__ float  g_lin[NFRT*NBINS];
__device__ float2 g_tprev[NFRT*NBINS];
__device__ float  g_frames[NFRT*NFFT];
__device__ float  g_inv[BATCH*T_LEN];

// ---------------- threefry-2x32-20 (matches jax partitionable) ----------------
__host__ __device__ __forceinline__ unsigned rotl32(unsigned x, int r){ return (x<<r)|(x>>(32-r)); }
__host__ __device__ inline void tf2x32(unsigned k0,unsigned k1,unsigned x0,unsigned x1,unsigned&o0,unsigned&o1){
  unsigned k2 = k0^k1^0x1BD11BDAu;
  x0+=k0; x1+=k1;
  #define TFR(r) { x0+=x1; x1=rotl32(x1,(r)); x1^=x0; }
  TFR(13) TFR(15) TFR(26) TFR(6)  x0+=k1; x1+=k2+1u;
  TFR(17) TFR(29) TFR(16) TFR(24) x0+=k2; x1+=k0+2u;
  TFR(13) TFR(15) TFR(26) TFR(6)  x0+=k0; x1+=k1+3u;
  TFR(17) TFR(29) TFR(16) TFR(24) x0+=k1; x1+=k2+4u;
  TFR(13) TFR(15) TFR(26) TFR(6)  x0+=k2; x1+=k0+5u;
  #undef TFR
  o0=x0; o1=x1;
}
__device__ __forceinline__ float u01(unsigned bits){
  return __uint_as_float((bits>>9) | 0x3f800000u) - 1.0f;
}
__device__ __forceinline__ int refl(int j, int n){
  if (j < 0) j = -j;
  if (j >= n) j = 2*n - 2 - j;
  return j;
}

// ---------------- register radix-8 DFT (DIF), DIR=+1 fwd / -1 inv ----------------
template<int DIR>
__device__ __forceinline__ void dft8(float* ar, float* ai){
  const float r2 = 0.70710678118654752f;
  const float d = (float)DIR;
  float t0r=ar[0]+ar[4], t0i=ai[0]+ai[4];
  float t4r=ar[0]-ar[4], t4i=ai[0]-ai[4];
  float t1r=ar[1]+ar[5], t1i=ai[1]+ai[5];
  float t5r=ar[1]-ar[5], t5i=ai[1]-ai[5];
  float t2r=ar[2]+ar[6], t2i=ai[2]+ai[6];
  float t6r=ar[2]-ar[6], t6i=ai[2]-ai[6];
  float t3r=ar[3]+ar[7], t3i=ai[3]+ai[7];
  float t7r=ar[3]-ar[7], t7i=ai[3]-ai[7];
  { float a=t5r,b=t5i; t5r=r2*(a+d*b); t5i=r2*(b-d*a); }      // *w8^1
  { float a=t6r,b=t6i; t6r=d*b; t6i=-d*a; }                   // *w8^2 = -i*d
  { float a=t7r,b=t7i; t7r=r2*(d*b-a); t7i=-r2*(b+d*a); }     // *w8^3
  float u0r=t0r+t2r,u0i=t0i+t2i, u1r=t0r-t2r,u1i=t0i-t2i;
  float u2r=t1r+t3r,u2i=t1i+t3i, u3r=t1r-t3r,u3i=t1i-t3i;
  float vr=d*u3i, vi=-d*u3r;
  ar[0]=u0r+u2r; ai[0]=u0i+u2i;
  ar[4]=u0r-u2r; ai[4]=u0i-u2i;
  ar[2]=u1r+vr;  ai[2]=u1i+vi;
  ar[6]=u1r-vr;  ai[6]=u1i-vi;
  u0r=t4r+t6r; u0i=t4i+t6i; u1r=t4r-t6r; u1i=t4i-t6i;
  u2r=t5r+t7r; u2i=t5i+t7i; u3r=t5r-t7r; u3i=t5i-t7i;
  vr=d*u3i; vi=-d*u3r;
  ar[1]=u0r+u2r; ai[1]=u0i+u2i;
  ar[5]=u0r-u2r; ai[5]=u0i-u2i;
  ar[3]=u1r+vr;  ai[3]=u1i+vi;
  ar[7]=u1r-vr;  ai[7]=u1i-vi;
}

// ---------------- size-2048 Stockham FFT, radix 8*8*8*4, single SoA buffer ----------------
template<int DIR>
__device__ __forceinline__ void fft2048_r8(float* Zr, float* Zi, int tid){
  #pragma unroll
  for (int st = 0; st < 3; ++st){
    const int s = (st==0) ? 1 : (st==1) ? 8 : 64;
    int q = tid & (s-1);
    int ps = tid - q;
    float ar[8], ai[8];
    #pragma unroll
    for (int j=0;j<8;++j){ int idx = tid + (j<<8); ar[j]=Zr[PAD(idx)]; ai[j]=Zi[PAD(idx)]; }
    __syncthreads();
    dft8<DIR>(ar, ai);
    float sn, cs;
    sincospif((float)ps * (1.0f/1024.0f), &sn, &cs);
    float w1r = cs, w1i = -(float)DIR * sn;
    float twr[8], twi[8];
    twr[1]=w1r;                       twi[1]=w1i;
    twr[2]=w1r*w1r - w1i*w1i;         twi[2]=2.f*w1r*w1i;
    twr[3]=twr[2]*w1r - twi[2]*w1i;   twi[3]=twr[2]*w1i + twi[2]*w1r;
    twr[4]=twr[2]*twr[2]-twi[2]*twi[2]; twi[4]=2.f*twr[2]*twi[2];
    twr[5]=twr[4]*w1r - twi[4]*w1i;   twi[5]=twr[4]*w1i + twi[4]*w1r;
    twr[6]=twr[4]*twr[2]-twi[4]*twi[2]; twi[6]=twr[4]*twi[2]+twi[4]*twr[2];
    twr[7]=twr[4]*twr[3]-twi[4]*twi[3]; twi[7]=twr[4]*twi[3]+twi[4]*twr[3];
    int base = q + (ps<<3);
    Zr[PAD(base)] = ar[0]; Zi[PAD(base)] = ai[0];
    #pragma unroll
    for (int k=1;k<8;++k){
      float br = ar[k]*twr[k] - ai[k]*twi[k];
      float bi = ar[k]*twi[k] + ai[k]*twr[k];
      int idx = base + s*k;
      Zr[PAD(idx)] = br; Zi[PAD(idx)] = bi;
    }
    __syncthreads();
  }
  float cr[8], ci[8];
  #pragma unroll
  for (int h=0; h<2; ++h){
    int i = tid + (h<<8);
    #pragma unroll
    for (int j=0;j<4;++j){ int idx = i + (j<<9); cr[h*4+j]=Zr[PAD(idx)]; ci[h*4+j]=Zi[PAD(idx)]; }
  }
  __syncthreads();
  const float d = (float)DIR;
  #pragma unroll
  for (int h=0;h<2;++h){
    int i = tid + (h<<8);
    float u0r=cr[h*4]+cr[h*4+2], u0i=ci[h*4]+ci[h*4+2];
    float u1r=cr[h*4]-cr[h*4+2], u1i=ci[h*4]-ci[h*4+2];
    float u2r=cr[h*4+1]+cr[h*4+3], u2i=ci[h*4+1]+ci[h*4+3];
    float u3r=cr[h*4+1]-cr[h*4+3], u3i=ci[h*4+1]-ci[h*4+3];
    float vr=d*u3i, vi=-d*u3r;
    Zr[PAD(i)]      = u0r+u2r; Zi[PAD(i)]      = u0i+u2i;
    Zr[PAD(i+512)]  = u1r+vr;  Zi[PAD(i+512)]  = u1i+vi;
    Zr[PAD(i+1024)] = u0r-u2r; Zi[PAD(i+1024)] = u0i-u2i;
    Zr[PAD(i+1536)] = u1r-vr;  Zi[PAD(i+1536)] = u1i-vi;
  }
  __syncthreads();
}

// ---------------- load 2 windowed frames into Zr/Zi (float4 fast path) ----------------
__device__ __forceinline__ void load_pair(const float* __restrict__ xb,
                                          float* Zr, float* Zi,
                                          int tid, int t0, bool hasB){
  int start = t0*HOP - 1024;
  if (start >= 0 && start + 256 + 2048 <= T_LEN){
    // interior: contiguous, aligned; B window is start+256
    for (int k4 = tid << 2; k4 < 2048; k4 += 1024){
      float4 wv = *(const float4*)(g_win + k4);
      float4 va = *(const float4*)(xb + start + k4);
      float4 vb = *(const float4*)(xb + start + 256 + k4);
      Zr[PAD(k4)]   = va.x*wv.x; Zi[PAD(k4)]   = vb.x*wv.x;
      Zr[PAD(k4+1)] = va.y*wv.y; Zi[PAD(k4+1)] = vb.y*wv.y;
      Zr[PAD(k4+2)] = va.z*wv.z; Zi[PAD(k4+2)] = vb.z*wv.z;
      Zr[PAD(k4+3)] = va.w*wv.w; Zi[PAD(k4+3)] = vb.w*wv.w;
    }
  } else {
    for (int k = tid; k < 2048; k += 256){
      float w = g_win[k];
      Zr[PAD(k)] = xb[refl(start + k, T_LEN)] * w;
      float vb = 0.f;
      if (hasB) vb = xb[refl(start + 256 + k, T_LEN)] * w;
      Zi[PAD(k)] = vb;
    }
  }
}

// ---------------- store windowed frames (float4 writes) ----------------
__device__ __forceinline__ void store_frames(const float* Zr, const float* Zi,
                                             int tid, int fr0, bool hasB){
  float* oa = g_frames + (size_t)fr0 * 2048;
  for (int n4 = tid << 2; n4 < 2048; n4 += 1024){
    float4 wv = *(const float4*)(g_win + n4);
    wv.x *= (1.0f/2048.0f); wv.y *= (1.0f/2048.0f);
    wv.z *= (1.0f/2048.0f); wv.w *= (1.0f/2048.0f);
    float4 va;
    va.x = Zr[PAD(n4)]   * wv.x;
    va.y = Zr[PAD(n4+1)] * wv.y;
    va.z = Zr[PAD(n4+2)] * wv.z;
    va.w = Zr[PAD(n4+3)] * wv.w;
    *(float4*)(oa + n4) = va;
    if (hasB){
      float4 vb;
      vb.x = Zi[PAD(n4)]   * wv.x;
      vb.y = Zi[PAD(n4+1)] * wv.y;
      vb.z = Zi[PAD(n4+2)] * wv.z;
      vb.w = Zi[PAD(n4+3)] * wv.w;
      *(float4*)(oa + 2048 + n4) = vb;
    }
  }
}

// ---------------- mel breakpoints (82 double pows total, once) ----------------
__global__ void k_fpts(){
  int m = threadIdx.x;
  if (m < NMELS+2){
    double mmax = 2595.0*log10(1.0 + 8000.0/700.0);
    g_fpts[m] = (float)(700.0*(pow(10.0, (double)m*mmax/81.0/2595.0) - 1.0));
  }
}

// ---------------- init tables (all float, no pow) ----------------
__global__ void k_tables(){
  int idx = blockIdx.x*blockDim.x + threadIdx.x;
  if (idx < 2048){
    g_win[idx] = 0.5f - 0.5f*cospif((float)idx * (1.0f/1024.0f));
  } else if (idx < 2048+L_OLA){
    int i = idx - 2048;
    int flo = (i - 1792) >> 8; if (flo < 0) flo = 0;
    int fhi = i >> 8;          if (fhi > NFR-1) fhi = NFR-1;
    float acc = 0.f;
    for (int f = flo; f <= fhi; ++f){
      int n = i - 256*f;
      float w = 0.5f - 0.5f*cospif((float)n * (1.0f/1024.0f));
      acc += w*w;
    }
    g_env[i] = acc;
  } else {
    int f = idx - 2048 - L_OLA;
    if (f < NBINS){
      float freq = (float)f * (8000.0f/1024.0f);
      int first = -1; float w0 = 0.f, w1 = 0.f;
      #pragma unroll 4
      for (int m = 0; m < NMELS; ++m){
        float fp0 = g_fpts[m], fp1 = g_fpts[m+1], fp2 = g_fpts[m+2];
        float dn = (freq - fp0)/(fp1 - fp0);
        float up = (fp2 - freq)/(fp2 - fp1);
        float v = fminf(dn, up);
        if (v > 0.f){
          if (first < 0){ first = m; w0 = v; }
          else w1 = v;
        }
      }
      g_fbi[f] = first;
      g_fbw[f] = make_float2(w0, w1);
    }
  }
}

// ---------------- f0 / loudness (1 frame per warp, shuffle autocorr) + MLP ----------------
__global__ void k_feats_mlp(const float* __restrict__ x,
                            const float* __restrict__ W1, const float* __restrict__ b1,
                            const float* __restrict__ W2, const float* __restrict__ b2,
                            const float* __restrict__ W3, const float* __restrict__ b3,
                            float* __restrict__ outc){
  __shared__ float s[8][768];          // 512 window + zero tail (tap reach 735)
  __shared__ float h1s[8*256];
  __shared__ float h2s[8*256];
  __shared__ float feat[8][2];
  int tid = threadIdx.x;
  int w = tid >> 5, lane = tid & 31;
  int base = blockIdx.x * 8;
  const unsigned FULL = 0xffffffffu;

  {
    int fr = base + w;
    int b = fr / NFR, t = fr % NFR;
    const float* xb = x + (size_t)b * T_LEN;
    for (int k = lane; k < 512; k += 32)
      s[w][k] = xb[refl(t*HOP + k - 256, T_LEN)];
    for (int k = 512 + lane; k < 768; k += 32)
      s[w][k] = 0.f;
    __syncwarp();
    float ss = 0.f;
    for (int k = lane; k < 512; k += 32){ float v = s[w][k]; ss += v*v; }
    #pragma unroll
    for (int o = 16; o; o >>= 1) ss += __shfl_xor_sync(FULL, ss, o);
    float acc[7];
    #pragma unroll
    for (int kk = 0; kk < 7; ++kk) acc[kk] = 0.f;
    for (int T = 0; T < 480; T += 32){
      float p = s[w][T + lane];
      float wreg[8];
      #pragma unroll
      for (int kk = 0; kk < 8; ++kk) wreg[kk] = s[w][T + 32 + lane + (kk<<5)];
      #pragma unroll 8
      for (int j = 0; j < 32; ++j){
        float v0 = __shfl_sync(FULL, p, j);
        int src = (lane + j) & 31;
        bool hi = (lane + j) >= 32;
        float sh[8];
        #pragma unroll
        for (int kk = 0; kk < 8; ++kk) sh[kk] = __shfl_sync(FULL, wreg[kk], src);
        #pragma unroll
        for (int kk = 0; kk < 7; ++kk) acc[kk] += v0 * (hi ? sh[kk+1] : sh[kk]);
      }
    }
    float best = -1e30f; int bi = 0;
    #pragma unroll
    for (int kk = 0; kk < 7; ++kk){
      if (acc[kk] > best){ best = acc[kk]; bi = lane + (kk<<5); }
    }
    #pragma unroll
    for (int o = 16; o; o >>= 1){
      float vo = __shfl_xor_sync(FULL, best, o);
      int   io = __shfl_xor_sync(FULL, bi,   o);
      if (vo > best || (vo == best && io < bi)){ best = vo; bi = io; }
    }
    if (lane == 0){
      float period = (float)(bi + MIN_P);
      float f0 = 16000.0f/(period + 1e-8f);
      f0 = fminf(fmaxf(f0, 50.0f), 500.0f);
      float loud = 20.0f*log10f(sqrtf(ss/512.0f) + 1e-8f);
      feat[w][0] = f0; feat[w][1] = loud;
    }
  }
  __syncthreads();

  #pragma unroll
  for (int u = 0; u < 8; ++u){
    float f0 = feat[u][0], ld = feat[u][1];
    float z = f0*W1[tid] + ld*W1[256+tid] + b1[tid];
    h1s[u*256+tid] = z > 0.f ? z : expm1f(z);
  }
  __syncthreads();
  float acc[8];
  #pragma unroll
  for (int u = 0; u < 8; ++u) acc[u] = b2[tid];
  for (int k = 0; k < 256; ++k){
    float wv = W2[k*256 + tid];
    #pragma unroll
    for (int u = 0; u < 8; ++u) acc[u] += h1s[u*256+k]*wv;
  }
  #pragma unroll
  for (int u = 0; u < 8; ++u){
    float z = acc[u];
    h2s[u*256+tid] = z > 0.f ? z : expm1f(z);
  }
  __syncthreads();
  int o = tid & 63;
  for (int pass = 0; pass < 2; ++pass){
    int u = (tid >> 6) + pass*4;
    float a3 = b3[o];
    for (int k = 0; k < 256; ++k) a3 += h2s[u*256+k]*W3[k*64 + o];
    int fr = base + u;
    outc[(size_t)fr*64 + o] = a3;
  }
}

// ---------------- FUSED: STFT -> mag -> mel -> linear -> random phases -> iFFT -> frames ----------------
__global__ void __launch_bounds__(256, 5) k_stft_ifft0(const float* __restrict__ x,
                             unsigned kr0,unsigned kr1,unsigned ki0,unsigned ki1){
  __shared__ float Zr[ZLEN], Zi[ZLEN];
  __shared__ float mel[2][NMELS];
  int tid = threadIdx.x;
  int pb = blockIdx.x;
  int b = pb / NPT, pt = pb % NPT;
  int t0 = 2*pt;
  bool hasB = (t0 + 1 < NFR);
  int fr0 = b*NFR + t0;
  const float* xb = x + (size_t)b * T_LEN;
  load_pair(xb, Zr, Zi, tid, t0, hasB);
  if (tid < 2*NMELS) ((float*)mel)[tid] = 0.f;
  __syncthreads();
  fft2048_r8<1>(Zr, Zi, tid);
  for (int k = tid; k <= 1024; k += 256){
    int m = (2048 - k) & 2047;
    float zkr=Zr[PAD(k)], zki=Zi[PAD(k)], zmr=Zr[PAD(m)], zmi=Zi[PAD(m)];
    float far_ = 0.5f*(zkr + zmr), fai = 0.5f*(zki - zmi);
    float dr = zkr - zmr, di = zki + zmi;
    float fbr = 0.5f*di, fbi = -0.5f*dr;
    float maga = sqrtf(far_*far_ + fai*fai);
    float magb = sqrtf(fbr*fbr + fbi*fbi);
    int i = g_fbi[k];
    float2 w = g_fbw[k];
    if (i >= 0){
      atomicAdd(&mel[0][i], maga*w.x);
      atomicAdd(&mel[1][i], magb*w.x);
      if (w.y != 0.f && i+1 < NMELS){
        atomicAdd(&mel[0][i+1], maga*w.y);
        atomicAdd(&mel[1][i+1], magb*w.y);
      }
    }
  }
  __syncthreads();
  // merged: mel->linear + threefry angles + Hermitian pack (in place).
  for (int k = tid; k <= 1024; k += 256){
    float src = fmaxf((k + 0.5f)*(80.0f/1025.0f) - 0.5f, 0.0f);
    int i0 = (int)floorf(src); if (i0 > 79) i0 = 79; if (i0 < 0) i0 = 0;
    int i1 = i0 + 1; if (i1 > 79) i1 = 79;
    float wq = src - (float)i0;
    float L  = (1.0f - wq)*mel[0][i0] + wq*mel[0][i1];
    float Lb = (1.0f - wq)*mel[1][i0] + wq*mel[1][i1];
    g_lin[(size_t)fr0*NBINS + k] = L;
    if (hasB) g_lin[(size_t)(fr0+1)*NBINS + k] = Lb;
    float msk = (k == 0 || k == 1024) ? 0.f : 1.f;
    unsigned e = ((unsigned)(b*NBINS + k))*((unsigned)NFR) + (unsigned)t0;
    unsigned r0,r1,i0u,i1u;
    tf2x32(kr0,kr1, 0u, e, r0,r1);
    tf2x32(ki0,ki1, 0u, e, i0u,i1u);
    float ar_ = L*u01(r0^r1), ai_ = L*u01(i0u^i1u)*msk;
    float br_ = 0.f, bi_ = 0.f;
    if (hasB){
      tf2x32(kr0,kr1, 0u, e+1u, r0,r1);
      tf2x32(ki0,ki1, 0u, e+1u, i0u,i1u);
      br_ = Lb*u01(r0^r1); bi_ = Lb*u01(i0u^i1u)*msk;
    }
    Zr[PAD(k)] = ar_ - bi_;
    Zi[PAD(k)] = ai_ + br_;
    if (k > 0 && k < 1024){
      int mm = 2048 - k;
      Zr[PAD(mm)] = ar_ + bi_;
      Zi[PAD(mm)] = br_ - ai_;
    }
  }
  __syncthreads();
  fft2048_r8<-1>(Zr, Zi, tid);
  store_frames(Zr, Zi, tid, fr0, hasB);
}

// ---------------- fused GL iteration: fwd FFT of inv + phase update + inverse FFT ----------------
__global__ void __launch_bounds__(256, 6) k_gl(int first){
  __shared__ float Zr[ZLEN], Zi[ZLEN];
  int tid = threadIdx.x;
  int pb = blockIdx.x;
  int b = pb / NPT, pt = pb % NPT;
  int t0 = 2*pt;
  bool hasB = (t0 + 1 < NFR);
  int fr0 = b*NFR + t0;
  const float* xb = g_inv + (size_t)b * T_LEN;
  load_pair(xb, Zr, Zi, tid, t0, hasB);
  __syncthreads();
  fft2048_r8<1>(Zr, Zi, tid);
  const float* lin0 = g_lin   + (size_t)fr0*NBINS;
  float2*      tpp  = g_tprev + (size_t)fr0*NBINS;
  for (int k = tid; k <= 1024; k += 256){
    int m = (2048 - k) & 2047;
    float zkr=Zr[PAD(k)], zki=Zi[PAD(k)], zmr=Zr[PAD(m)], zmi=Zi[PAD(m)];
    float rar = 0.5f*(zkr + zmr), rai = 0.5f*(zki - zmi);
    float dr = zkr - zmr, di = zki + zmi;
    float rbr = 0.5f*di, rbi = -0.5f*dr;
    float msk = (k == 0 || k == 1024) ? 0.f : 1.f;
    float tpx = 0.f, tpy = 0.f;
    if (!first){ float2 tp = tpp[k]; tpx = tp.x; tpy = tp.y; }
    float ax = rar - MOM*tpx, ay = rai - MOM*tpy;
    float mg = sqrtf(ax*ax + ay*ay) + 1e-16f;
    tpp[k] = make_float2(rar, rai);
    float L = lin0[k];
    float ar_ = L*(ax/mg), ai_ = L*(ay/mg)*msk;
    float br_ = 0.f, bi_ = 0.f;
    if (hasB){
      float tbx = 0.f, tby = 0.f;
      if (!first){ float2 tb = tpp[NBINS + k]; tbx = tb.x; tby = tb.y; }
      float bx = rbr - MOM*tbx, by = rbi - MOM*tby;
      float mb = sqrtf(bx*bx + by*by) + 1e-16f;
      tpp[NBINS + k] = make_float2(rbr, rbi);
      float Lb = lin0[NBINS + k];
      br_ = Lb*(bx/mb); bi_ = Lb*(by/mb)*msk;
    }
    Zr[PAD(k)] = ar_ - bi_;
    Zi[PAD(k)] = ai_ + br_;
    if (k > 0 && k < 1024){
      int mm = 2048 - k;
      Zr[PAD(mm)] = ar_ + bi_;
      Zi[PAD(mm)] = br_ - ai_;
    }
  }
  __syncthreads();
  fft2048_r8<-1>(Zr, Zi, tid);
  store_frames(Zr, Zi, tid, fr0, hasB);
}

// ---------------- overlap-add gather: 4 samples/thread, all-float4, branch-free ----------------
__global__ void k_ola(float* __restrict__ out_final, int is_final){
  int q = blockIdx.x*blockDim.x + threadIdx.x;
  if (q >= BATCH*T_LEN/4) return;
  int b = q >> 15;                 /* 32768 quads per batch */
  int i4 = (q & 32767) << 2;
  int pos = i4 + 1024;
  int flo = (pos - 1792) >> 8; if (flo < 0) flo = 0;
  int fhi = pos >> 8;          if (fhi > NFR-1) fhi = NFR-1;
  const float* fbuf = g_frames + (size_t)b * NFR * 2048;
  float a0=0.f, a1=0.f, a2=0.f, a3=0.f;
  for (int f = flo; f <= fhi; ++f){
    float4 v = *(const float4*)(fbuf + (size_t)f*2048 + (pos - (f<<8)));
    a0 += v.x; a1 += v.y; a2 += v.z; a3 += v.w;
  }
  float4 ev = *(const float4*)(g_env + pos);
  float4 r;
  r.x = a0 / (ev.x > 1e-11f ? ev.x : 1.f);
  r.y = a1 / (ev.y > 1e-11f ? ev.y : 1.f);
  r.z = a2 / (ev.z > 1e-11f ? ev.z : 1.f);
  r.w = a3 / (ev.w > 1e-11f ? ev.w : 1.f);
  size_t o = ((size_t)b << 17) + i4;
  if (is_final) *(float4*)(out_final + o) = r;
  else          *(float4*)(g_inv + o) = r;
}

// ---------------- launch (single stream, serial) ----------------
extern "C" void kernel_launch(void* const* d_in, const int* in_sizes, int n_in,
                              void* d_out, int out_size){
  const float* x  = (const float*)d_in[0];
  const float* W1 = (const float*)d_in[1];
  const float* b1 = (const float*)d_in[2];
  const float* W2 = (const float*)d_in[3];
  const float* b2 = (const float*)d_in[4];
  const float* W3 = (const float*)d_in[5];
  const float* b3 = (const float*)d_in[6];
  float* out  = (float*)d_out;
  float* outc = out + (size_t)BATCH*T_LEN;

  unsigned kr0,kr1,ki0,ki1;
  tf2x32(0u, 42u, 0u, 0u, kr0, kr1);
  tf2x32(0u, 42u, 0u, 1u, ki0, ki1);

  k_fpts<<<1, 128>>>();
  k_tables<<<(2048+L_OLA+NBINS + 255)/256, 256>>>();
  k_feats_mlp<<<NFRT/8, 256>>>(x, W1, b1, W2, b2, W3, b3, outc);
  k_stft_ifft0<<<NPAIR, 256>>>(x, kr0, kr1, ki0, ki1);
  k_ola<<<(BATCH*T_LEN/4)/256, 256>>>(out, 0);
  for (int it = 1; it <= 4; ++it){
    k_gl<<<NPAIR, 256>>>(it == 1);
    k_ola<<<(BATCH*T_LEN/4)/256, 256>>>(out, it == 4);
  }
}

// round 14
// speedup vs baseline: 1.8948x; 1.0385x over previous
#include <cuda_runtime.h>
#include <math.h>
#include <stdint.h>

#define BATCH 16
#define T_LEN 131072
#define HOP 256
#define NFFT 2048
#define NBINS 1025
#define NFR 513
#define NFRT (BATCH*NFR)          /* 8208 */
#define NPT 257                    /* frame pairs per batch (last has no B) */
#define NPAIR (BATCH*NPT)          /* 4112 */
#define NMELS 80
#define MIN_P 32
#define L_OLA 133120               /* NFFT + HOP*(NFR-1) */
#define MOM (0.99f/1.99f)

#define PAD(i) ((i) + ((i)>>3))
#define ZLEN 2304                  /* PAD(2047)=2302 */

// ---------------- scratch (static device globals; no allocs) ----------------
__device__ float  g_fpts[NMELS+2];
__device__ float  g_win[NFFT];
__device__ float  g_env[L_OLA];
__device__ int    g_fbi[NBINS];
__device__ float2 g_fbw[NBINS];
__device__ float  g_lin[NFRT*NBINS];
__device__ float2 g_tprev[NFRT*NBINS];
__device__ float  g_frames[NFRT*NFFT];
__device__ float  g_inv[BATCH*T_LEN];

// ---------------- threefry-2x32-20 (matches jax partitionable) ----------------
__host__ __device__ __forceinline__ unsigned rotl32(unsigned x, int r){ return (x<<r)|(x>>(32-r)); }
__host__ __device__ inline void tf2x32(unsigned k0,unsigned k1,unsigned x0,unsigned x1,unsigned&o0,unsigned&o1){
  unsigned k2 = k0^k1^0x1BD11BDAu;
  x0+=k0; x1+=k1;
  #define TFR(r) { x0+=x1; x1=rotl32(x1,(r)); x1^=x0; }
  TFR(13) TFR(15) TFR(26) TFR(6)  x0+=k1; x1+=k2+1u;
  TFR(17) TFR(29) TFR(16) TFR(24) x0+=k2; x1+=k0+2u;
  TFR(13) TFR(15) TFR(26) TFR(6)  x0+=k0; x1+=k1+3u;
  TFR(17) TFR(29) TFR(16) TFR(24) x0+=k1; x1+=k2+4u;
  TFR(13) TFR(15) TFR(26) TFR(6)  x0+=k2; x1+=k0+5u;
  #undef TFR
  o0=x0; o1=x1;
}
__device__ __forceinline__ float u01(unsigned bits){
  return __uint_as_float((bits>>9) | 0x3f800000u) - 1.0f;
}
__device__ __forceinline__ int refl(int j, int n){
  if (j < 0) j = -j;
  if (j >= n) j = 2*n - 2 - j;
  return j;
}

// ---------------- register radix-8 DFT (DIF), DIR=+1 fwd / -1 inv ----------------
template<int DIR>
__device__ __forceinline__ void dft8(float* ar, float* ai){
  const float r2 = 0.70710678118654752f;
  const float d = (float)DIR;
  float t0r=ar[0]+ar[4], t0i=ai[0]+ai[4];
  float t4r=ar[0]-ar[4], t4i=ai[0]-ai[4];
  float t1r=ar[1]+ar[5], t1i=ai[1]+ai[5];
  float t5r=ar[1]-ar[5], t5i=ai[1]-ai[5];
  float t2r=ar[2]+ar[6], t2i=ai[2]+ai[6];
  float t6r=ar[2]-ar[6], t6i=ai[2]-ai[6];
  float t3r=ar[3]+ar[7], t3i=ai[3]+ai[7];
  float t7r=ar[3]-ar[7], t7i=ai[3]-ai[7];
  { float a=t5r,b=t5i; t5r=r2*(a+d*b); t5i=r2*(b-d*a); }      // *w8^1
  { float a=t6r,b=t6i; t6r=d*b; t6i=-d*a; }                   // *w8^2 = -i*d
  { float a=t7r,b=t7i; t7r=r2*(d*b-a); t7i=-r2*(b+d*a); }     // *w8^3
  float u0r=t0r+t2r,u0i=t0i+t2i, u1r=t0r-t2r,u1i=t0i-t2i;
  float u2r=t1r+t3r,u2i=t1i+t3i, u3r=t1r-t3r,u3i=t1i-t3i;
  float vr=d*u3i, vi=-d*u3r;
  ar[0]=u0r+u2r; ai[0]=u0i+u2i;
  ar[4]=u0r-u2r; ai[4]=u0i-u2i;
  ar[2]=u1r+vr;  ai[2]=u1i+vi;
  ar[6]=u1r-vr;  ai[6]=u1i-vi;
  u0r=t4r+t6r; u0i=t4i+t6i; u1r=t4r-t6r; u1i=t4i-t6i;
  u2r=t5r+t7r; u2i=t5i+t7i; u3r=t5r-t7r; u3i=t5i-t7i;
  vr=d*u3i; vi=-d*u3r;
  ar[1]=u0r+u2r; ai[1]=u0i+u2i;
  ar[5]=u0r-u2r; ai[5]=u0i-u2i;
  ar[3]=u1r+vr;  ai[3]=u1i+vi;
  ar[7]=u1r-vr;  ai[7]=u1i-vi;
}

// ---------------- size-2048 Stockham FFT, radix 8*8*8*4, single SoA buffer ----------------
template<int DIR>
__device__ __forceinline__ void fft2048_r8(float* Zr, float* Zi, int tid){
  #pragma unroll
  for (int st = 0; st < 3; ++st){
    const int s = (st==0) ? 1 : (st==1) ? 8 : 64;
    int q = tid & (s-1);
    int ps = tid - q;
    float ar[8], ai[8];
    #pragma unroll
    for (int j=0;j<8;++j){ int idx = tid + (j<<8); ar[j]=Zr[PAD(idx)]; ai[j]=Zi[PAD(idx)]; }
    __syncthreads();
    dft8<DIR>(ar, ai);
    float sn, cs;
    sincospif((float)ps * (1.0f/1024.0f), &sn, &cs);
    float w1r = cs, w1i = -(float)DIR * sn;
    float twr[8], twi[8];
    twr[1]=w1r;                       twi[1]=w1i;
    twr[2]=w1r*w1r - w1i*w1i;         twi[2]=2.f*w1r*w1i;
    twr[3]=twr[2]*w1r - twi[2]*w1i;   twi[3]=twr[2]*w1i + twi[2]*w1r;
    twr[4]=twr[2]*twr[2]-twi[2]*twi[2]; twi[4]=2.f*twr[2]*twi[2];
    twr[5]=twr[4]*w1r - twi[4]*w1i;   twi[5]=twr[4]*w1i + twi[4]*w1r;
    twr[6]=twr[4]*twr[2]-twi[4]*twi[2]; twi[6]=twr[4]*twi[2]+twi[4]*twr[2];
    twr[7]=twr[4]*twr[3]-twi[4]*twi[3]; twi[7]=twr[4]*twi[3]+twi[4]*twr[3];
    int base = q + (ps<<3);
    Zr[PAD(base)] = ar[0]; Zi[PAD(base)] = ai[0];
    #pragma unroll
    for (int k=1;k<8;++k){
      float br = ar[k]*twr[k] - ai[k]*twi[k];
      float bi = ar[k]*twi[k] + ai[k]*twr[k];
      int idx = base + s*k;
      Zr[PAD(idx)] = br; Zi[PAD(idx)] = bi;
    }
    __syncthreads();
  }
  float cr[8], ci[8];
  #pragma unroll
  for (int h=0; h<2; ++h){
    int i = tid + (h<<8);
    #pragma unroll
    for (int j=0;j<4;++j){ int idx = i + (j<<9); cr[h*4+j]=Zr[PAD(idx)]; ci[h*4+j]=Zi[PAD(idx)]; }
  }
  __syncthreads();
  const float d = (float)DIR;
  #pragma unroll
  for (int h=0;h<2;++h){
    int i = tid + (h<<8);
    float u0r=cr[h*4]+cr[h*4+2], u0i=ci[h*4]+ci[h*4+2];
    float u1r=cr[h*4]-cr[h*4+2], u1i=ci[h*4]-ci[h*4+2];
    float u2r=cr[h*4+1]+cr[h*4+3], u2i=ci[h*4+1]+ci[h*4+3];
    float u3r=cr[h*4+1]-cr[h*4+3], u3i=ci[h*4+1]-ci[h*4+3];
    float vr=d*u3i, vi=-d*u3r;
    Zr[PAD(i)]      = u0r+u2r; Zi[PAD(i)]      = u0i+u2i;
    Zr[PAD(i+512)]  = u1r+vr;  Zi[PAD(i+512)]  = u1i+vi;
    Zr[PAD(i+1024)] = u0r-u2r; Zi[PAD(i+1024)] = u0i-u2i;
    Zr[PAD(i+1536)] = u1r-vr;  Zi[PAD(i+1536)] = u1i-vi;
  }
  __syncthreads();
}

// ---------------- load 2 windowed frames into Zr/Zi (float4 fast path) ----------------
__device__ __forceinline__ void load_pair(const float* __restrict__ xb,
                                          float* Zr, float* Zi,
                                          int tid, int t0, bool hasB){
  int start = t0*HOP - 1024;
  if (start >= 0 && start + 256 + 2048 <= T_LEN){
    for (int k4 = tid << 2; k4 < 2048; k4 += 1024){
      float4 wv = *(const float4*)(g_win + k4);
      float4 va = *(const float4*)(xb + start + k4);
      float4 vb = *(const float4*)(xb + start + 256 + k4);
      Zr[PAD(k4)]   = va.x*wv.x; Zi[PAD(k4)]   = vb.x*wv.x;
      Zr[PAD(k4+1)] = va.y*wv.y; Zi[PAD(k4+1)] = vb.y*wv.y;
      Zr[PAD(k4+2)] = va.z*wv.z; Zi[PAD(k4+2)] = vb.z*wv.z;
      Zr[PAD(k4+3)] = va.w*wv.w; Zi[PAD(k4+3)] = vb.w*wv.w;
    }
  } else {
    for (int k = tid; k < 2048; k += 256){
      float w = g_win[k];
      Zr[PAD(k)] = xb[refl(start + k, T_LEN)] * w;
      float vb = 0.f;
      if (hasB) vb = xb[refl(start + 256 + k, T_LEN)] * w;
      Zi[PAD(k)] = vb;
    }
  }
}

// ---------------- store windowed frames (float4 writes) ----------------
__device__ __forceinline__ void store_frames(const float* Zr, const float* Zi,
                                             int tid, int fr0, bool hasB){
  float* oa = g_frames + (size_t)fr0 * 2048;
  for (int n4 = tid << 2; n4 < 2048; n4 += 1024){
    float4 wv = *(const float4*)(g_win + n4);
    wv.x *= (1.0f/2048.0f); wv.y *= (1.0f/2048.0f);
    wv.z *= (1.0f/2048.0f); wv.w *= (1.0f/2048.0f);
    float4 va;
    va.x = Zr[PAD(n4)]   * wv.x;
    va.y = Zr[PAD(n4+1)] * wv.y;
    va.z = Zr[PAD(n4+2)] * wv.z;
    va.w = Zr[PAD(n4+3)] * wv.w;
    *(float4*)(oa + n4) = va;
    if (hasB){
      float4 vb;
      vb.x = Zi[PAD(n4)]   * wv.x;
      vb.y = Zi[PAD(n4+1)] * wv.y;
      vb.z = Zi[PAD(n4+2)] * wv.z;
      vb.w = Zi[PAD(n4+3)] * wv.w;
      *(float4*)(oa + 2048 + n4) = vb;
    }
  }
}

// ---------------- mel breakpoints (82 double pows total, once) ----------------
__global__ void k_fpts(){
  int m = threadIdx.x;
  if (m < NMELS+2){
    double mmax = 2595.0*log10(1.0 + 8000.0/700.0);
    g_fpts[m] = (float)(700.0*(pow(10.0, (double)m*mmax/81.0/2595.0) - 1.0));
  }
}

// ---------------- init tables (all float, no pow) ----------------
__global__ void k_tables(){
  int idx = blockIdx.x*blockDim.x + threadIdx.x;
  if (idx < 2048){
    g_win[idx] = 0.5f - 0.5f*cospif((float)idx * (1.0f/1024.0f));
  } else if (idx < 2048+L_OLA){
    int i = idx - 2048;
    int flo = (i - 1792) >> 8; if (flo < 0) flo = 0;
    int fhi = i >> 8;          if (fhi > NFR-1) fhi = NFR-1;
    float acc = 0.f;
    for (int f = flo; f <= fhi; ++f){
      int n = i - 256*f;
      float w = 0.5f - 0.5f*cospif((float)n * (1.0f/1024.0f));
      acc += w*w;
    }
    g_env[i] = acc;
  } else {
    int f = idx - 2048 - L_OLA;
    if (f < NBINS){
      float freq = (float)f * (8000.0f/1024.0f);
      int first = -1; float w0 = 0.f, w1 = 0.f;
      #pragma unroll 4
      for (int m = 0; m < NMELS; ++m){
        float fp0 = g_fpts[m], fp1 = g_fpts[m+1], fp2 = g_fpts[m+2];
        float dn = (freq - fp0)/(fp1 - fp0);
        float up = (fp2 - freq)/(fp2 - fp1);
        float v = fminf(dn, up);
        if (v > 0.f){
          if (first < 0){ first = m; w0 = v; }
          else w1 = v;
        }
      }
      g_fbi[f] = first;
      g_fbw[f] = make_float2(w0, w1);
    }
  }
}

// ---------------- f0 / loudness (1 frame per warp, shuffle autocorr) + MLP ----------------
__global__ void k_feats_mlp(const float* __restrict__ x,
                            const float* __restrict__ W1, const float* __restrict__ b1,
                            const float* __restrict__ W2, const float* __restrict__ b2,
                            const float* __restrict__ W3, const float* __restrict__ b3,
                            float* __restrict__ outc){
  __shared__ float s[8][768];          // 512 window + zero tail (tap reach 735)
  __shared__ float h1s[8*256];
  __shared__ float h2s[8*256];
  __shared__ float feat[8][2];
  int tid = threadIdx.x;
  int w = tid >> 5, lane = tid & 31;
  int base = blockIdx.x * 8;
  const unsigned FULL = 0xffffffffu;

  {
    int fr = base + w;
    int b = fr / NFR, t = fr % NFR;
    const float* xb = x + (size_t)b * T_LEN;
    for (int k = lane; k < 512; k += 32)
      s[w][k] = xb[refl(t*HOP + k - 256, T_LEN)];
    for (int k = 512 + lane; k < 768; k += 32)
      s[w][k] = 0.f;
    __syncwarp();
    float ss = 0.f;
    for (int k = lane; k < 512; k += 32){ float v = s[w][k]; ss += v*v; }
    #pragma unroll
    for (int o = 16; o; o >>= 1) ss += __shfl_xor_sync(FULL, ss, o);
    float acc[7];
    #pragma unroll
    for (int kk = 0; kk < 7; ++kk) acc[kk] = 0.f;
    for (int T = 0; T < 480; T += 32){
      float p = s[w][T + lane];
      float wreg[8];
      #pragma unroll
      for (int kk = 0; kk < 8; ++kk) wreg[kk] = s[w][T + 32 + lane + (kk<<5)];
      #pragma unroll 8
      for (int j = 0; j < 32; ++j){
        float v0 = __shfl_sync(FULL, p, j);
        int src = (lane + j) & 31;
        bool hi = (lane + j) >= 32;
        float sh[8];
        #pragma unroll
        for (int kk = 0; kk < 8; ++kk) sh[kk] = __shfl_sync(FULL, wreg[kk], src);
        #pragma unroll
        for (int kk = 0; kk < 7; ++kk) acc[kk] += v0 * (hi ? sh[kk+1] : sh[kk]);
      }
    }
    float best = -1e30f; int bi = 0;
    #pragma unroll
    for (int kk = 0; kk < 7; ++kk){
      if (acc[kk] > best){ best = acc[kk]; bi = lane + (kk<<5); }
    }
    #pragma unroll
    for (int o = 16; o; o >>= 1){
      float vo = __shfl_xor_sync(FULL, best, o);
      int   io = __shfl_xor_sync(FULL, bi,   o);
      if (vo > best || (vo == best && io < bi)){ best = vo; bi = io; }
    }
    if (lane == 0){
      float period = (float)(bi + MIN_P);
      float f0 = 16000.0f/(period + 1e-8f);
      f0 = fminf(fmaxf(f0, 50.0f), 500.0f);
      float loud = 20.0f*log10f(sqrtf(ss/512.0f) + 1e-8f);
      feat[w][0] = f0; feat[w][1] = loud;
    }
  }
  __syncthreads();

  #pragma unroll
  for (int u = 0; u < 8; ++u){
    float f0 = feat[u][0], ld = feat[u][1];
    float z = f0*W1[tid] + ld*W1[256+tid] + b1[tid];
    h1s[u*256+tid] = z > 0.f ? z : expm1f(z);
  }
  __syncthreads();
  float acc[8];
  #pragma unroll
  for (int u = 0; u < 8; ++u) acc[u] = b2[tid];
  for (int k = 0; k < 256; ++k){
    float wv = W2[k*256 + tid];
    #pragma unroll
    for (int u = 0; u < 8; ++u) acc[u] += h1s[u*256+k]*wv;
  }
  #pragma unroll
  for (int u = 0; u < 8; ++u){
    float z = acc[u];
    h2s[u*256+tid] = z > 0.f ? z : expm1f(z);
  }
  __syncthreads();
  int o = tid & 63;
  for (int pass = 0; pass < 2; ++pass){
    int u = (tid >> 6) + pass*4;
    float a3 = b3[o];
    for (int k = 0; k < 256; ++k) a3 += h2s[u*256+k]*W3[k*64 + o];
    int fr = base + u;
    outc[(size_t)fr*64 + o] = a3;
  }
}

// ---------------- FUSED: STFT -> mag -> mel -> linear -> random phases -> iFFT -> frames ----------------
__global__ void __launch_bounds__(256, 5) k_stft_ifft0(const float* __restrict__ x,
                             unsigned kr0,unsigned kr1,unsigned ki0,unsigned ki1){
  __shared__ float Zr[ZLEN], Zi[ZLEN];
  __shared__ float mel[2][NMELS];
  int tid = threadIdx.x;
  int pb = blockIdx.x;
  int b = pb / NPT, pt = pb % NPT;
  int t0 = 2*pt;
  bool hasB = (t0 + 1 < NFR);
  int fr0 = b*NFR + t0;
  const float* xb = x + (size_t)b * T_LEN;
  load_pair(xb, Zr, Zi, tid, t0, hasB);
  if (tid < 2*NMELS) ((float*)mel)[tid] = 0.f;
  __syncthreads();
  fft2048_r8<1>(Zr, Zi, tid);
  for (int k = tid; k <= 1024; k += 256){
    int m = (2048 - k) & 2047;
    float zkr=Zr[PAD(k)], zki=Zi[PAD(k)], zmr=Zr[PAD(m)], zmi=Zi[PAD(m)];
    float far_ = 0.5f*(zkr + zmr), fai = 0.5f*(zki - zmi);
    float dr = zkr - zmr, di = zki + zmi;
    float fbr = 0.5f*di, fbi = -0.5f*dr;
    float maga = sqrtf(far_*far_ + fai*fai);
    float magb = sqrtf(fbr*fbr + fbi*fbi);
    int i = g_fbi[k];
    float2 w = g_fbw[k];
    if (i >= 0){
      atomicAdd(&mel[0][i], maga*w.x);
      atomicAdd(&mel[1][i], magb*w.x);
      if (w.y != 0.f && i+1 < NMELS){
        atomicAdd(&mel[0][i+1], maga*w.y);
        atomicAdd(&mel[1][i+1], magb*w.y);
      }
    }
  }
  __syncthreads();
  for (int k = tid; k <= 1024; k += 256){
    float src = fmaxf((k + 0.5f)*(80.0f/1025.0f) - 0.5f, 0.0f);
    int i0 = (int)floorf(src); if (i0 > 79) i0 = 79; if (i0 < 0) i0 = 0;
    int i1 = i0 + 1; if (i1 > 79) i1 = 79;
    float wq = src - (float)i0;
    float L  = (1.0f - wq)*mel[0][i0] + wq*mel[0][i1];
    float Lb = (1.0f - wq)*mel[1][i0] + wq*mel[1][i1];
    g_lin[(size_t)fr0*NBINS + k] = L;
    if (hasB) g_lin[(size_t)(fr0+1)*NBINS + k] = Lb;
    float msk = (k == 0 || k == 1024) ? 0.f : 1.f;
    unsigned e = ((unsigned)(b*NBINS + k))*((unsigned)NFR) + (unsigned)t0;
    unsigned r0,r1,i0u,i1u;
    tf2x32(kr0,kr1, 0u, e, r0,r1);
    tf2x32(ki0,ki1, 0u, e, i0u,i1u);
    float ar_ = L*u01(r0^r1), ai_ = L*u01(i0u^i1u)*msk;
    float br_ = 0.f, bi_ = 0.f;
    if (hasB){
      tf2x32(kr0,kr1, 0u, e+1u, r0,r1);
      tf2x32(ki0,ki1, 0u, e+1u, i0u,i1u);
      br_ = Lb*u01(r0^r1); bi_ = Lb*u01(i0u^i1u)*msk;
    }
    Zr[PAD(k)] = ar_ - bi_;
    Zi[PAD(k)] = ai_ + br_;
    if (k > 0 && k < 1024){
      int mm = 2048 - k;
      Zr[PAD(mm)] = ar_ + bi_;
      Zi[PAD(mm)] = br_ - ai_;
    }
  }
  __syncthreads();
  fft2048_r8<-1>(Zr, Zi, tid);
  store_frames(Zr, Zi, tid, fr0, hasB);
}

// ---------------- fused GL iteration: fwd FFT of inv + phase update + inverse FFT ----------------
__global__ void __launch_bounds__(256, 6) k_gl(int first){
  __shared__ float Zr[ZLEN], Zi[ZLEN];
  int tid = threadIdx.x;
  int pb = blockIdx.x;
  int b = pb / NPT, pt = pb % NPT;
  int t0 = 2*pt;
  bool hasB = (t0 + 1 < NFR);
  int fr0 = b*NFR + t0;
  const float* xb = g_inv + (size_t)b * T_LEN;
  load_pair(xb, Zr, Zi, tid, t0, hasB);
  __syncthreads();
  fft2048_r8<1>(Zr, Zi, tid);
  const float* lin0 = g_lin   + (size_t)fr0*NBINS;
  float2*      tpp  = g_tprev + (size_t)fr0*NBINS;
  for (int k = tid; k <= 1024; k += 256){
    int m = (2048 - k) & 2047;
    float zkr=Zr[PAD(k)], zki=Zi[PAD(k)], zmr=Zr[PAD(m)], zmi=Zi[PAD(m)];
    float rar = 0.5f*(zkr + zmr), rai = 0.5f*(zki - zmi);
    float dr = zkr - zmr, di = zki + zmi;
    float rbr = 0.5f*di, rbi = -0.5f*dr;
    float msk = (k == 0 || k == 1024) ? 0.f : 1.f;
    float tpx = 0.f, tpy = 0.f;
    if (!first){ float2 tp = tpp[k]; tpx = tp.x; tpy = tp.y; }
    float ax = rar - MOM*tpx, ay = rai - MOM*tpy;
    float mg = sqrtf(ax*ax + ay*ay) + 1e-16f;
    tpp[k] = make_float2(rar, rai);
    float L = lin0[k];
    float ar_ = L*(ax/mg), ai_ = L*(ay/mg)*msk;
    float br_ = 0.f, bi_ = 0.f;
    if (hasB){
      float tbx = 0.f, tby = 0.f;
      if (!first){ float2 tb = tpp[NBINS + k]; tbx = tb.x; tby = tb.y; }
      float bx = rbr - MOM*tbx, by = rbi - MOM*tby;
      float mb = sqrtf(bx*bx + by*by) + 1e-16f;
      tpp[NBINS + k] = make_float2(rbr, rbi);
      float Lb = lin0[NBINS + k];
      br_ = Lb*(bx/mb); bi_ = Lb*(by/mb)*msk;
    }
    Zr[PAD(k)] = ar_ - bi_;
    Zi[PAD(k)] = ai_ + br_;
    if (k > 0 && k < 1024){
      int mm = 2048 - k;
      Zr[PAD(mm)] = ar_ + bi_;
      Zi[PAD(mm)] = br_ - ai_;
    }
  }
  __syncthreads();
  fft2048_r8<-1>(Zr, Zi, tid);
  store_frames(Zr, Zi, tid, fr0, hasB);
}

// ---------------- overlap-add gather: 4 samples/thread, all-float4, branch-free ----------------
__global__ void k_ola(float* __restrict__ out_final, int is_final){
  int q = blockIdx.x*blockDim.x + threadIdx.x;
  if (q >= BATCH*T_LEN/4) return;
  int b = q >> 15;                 /* 32768 quads per batch */
  int i4 = (q & 32767) << 2;
  int pos = i4 + 1024;
  int flo = (pos - 1792) >> 8; if (flo < 0) flo = 0;
  int fhi = pos >> 8;          if (fhi > NFR-1) fhi = NFR-1;
  const float* fbuf = g_frames + (size_t)b * NFR * 2048;
  float a0=0.f, a1=0.f, a2=0.f, a3=0.f;
  for (int f = flo; f <= fhi; ++f){
    float4 v = *(const float4*)(fbuf + (size_t)f*2048 + (pos - (f<<8)));
    a0 += v.x; a1 += v.y; a2 += v.z; a3 += v.w;
  }
  float4 ev = *(const float4*)(g_env + pos);
  float4 r;
  r.x = a0 / (ev.x > 1e-11f ? ev.x : 1.f);
  r.y = a1 / (ev.y > 1e-11f ? ev.y : 1.f);
  r.z = a2 / (ev.z > 1e-11f ? ev.z : 1.f);
  r.w = a3 / (ev.w > 1e-11f ? ev.w : 1.f);
  size_t o = ((size_t)b << 17) + i4;
  if (is_final) *(float4*)(out_final + o) = r;
  else          *(float4*)(g_inv + o) = r;
}

// ---------------- launch (main stream + independent feats branch) ----------------
extern "C" void kernel_launch(void* const* d_in, const int* in_sizes, int n_in,
                              void* d_out, int out_size){
  const float* x  = (const float*)d_in[0];
  const float* W1 = (const float*)d_in[1];
  const float* b1 = (const float*)d_in[2];
  const float* W2 = (const float*)d_in[3];
  const float* b2 = (const float*)d_in[4];
  const float* W3 = (const float*)d_in[5];
  const float* b3 = (const float*)d_in[6];
  float* out  = (float*)d_out;
  float* outc = out + (size_t)BATCH*T_LEN;

  unsigned kr0,kr1,ki0,ki1;
  tf2x32(0u, 42u, 0u, 0u, kr0, kr1);
  tf2x32(0u, 42u, 0u, 1u, ki0, ki1);

  // side stream for the independent feats+MLP branch (created once,
  // outside capture — first harness call is the uncaptured correctness run)
  static cudaStream_t s2 = 0;
  static cudaEvent_t ev_fork = 0, ev_join = 0;
  if (!s2){
    cudaStreamCreateWithFlags(&s2, cudaStreamNonBlocking);
    cudaEventCreateWithFlags(&ev_fork, cudaEventDisableTiming);
    cudaEventCreateWithFlags(&ev_join, cudaEventDisableTiming);
  }

  cudaEventRecord(ev_fork, 0);
  cudaStreamWaitEvent(s2, ev_fork, 0);
  k_feats_mlp<<<NFRT/8, 256, 0, s2>>>(x, W1, b1, W2, b2, W3, b3, outc);
  cudaEventRecord(ev_join, s2);

  k_fpts<<<1, 128>>>();
  k_tables<<<(2048+L_OLA+NBINS + 255)/256, 256>>>();
  k_stft_ifft0<<<NPAIR, 256>>>(x, kr0, kr1, ki0, ki1);
  k_ola<<<(BATCH*T_LEN/4)/256, 256>>>(out, 0);
  for (int it = 1; it <= 4; ++it){
    k_gl<<<NPAIR, 256>>>(it == 1);
    if (it == 4) cudaStreamWaitEvent(0, ev_join, 0); // fold feats branch into graph sink
    k_ola<<<(BATCH*T_LEN/4)/256, 256>>>(out, it == 4);
  }
}

// round 15
// speedup vs baseline: 1.9437x; 1.0258x over previous
#include <cuda_runtime.h>
#include <math.h>
#include <stdint.h>

#define BATCH 16
#define T_LEN 131072
#define HOP 256
#define NFFT 2048
#define NBINS 1025
#define NFR 513
#define NFRT (BATCH*NFR)          /* 8208 */
#define NPT 257                    /* frame pairs per batch (last has no B) */
#define NPAIR (BATCH*NPT)          /* 4112 */
#define NPAIRH (NPAIR/2)           /* 2056: one chain = 8 batches */
#define QTOT (BATCH*T_LEN/4)       /* 524288 quads */
#define QH (QTOT/2)                /* 262144 */
#define NMELS 80
#define MIN_P 32
#define L_OLA 133120               /* NFFT + HOP*(NFR-1) */
#define MOM (0.99f/1.99f)

#define PAD(i) ((i) + ((i)>>3))
#define ZLEN 2304                  /* PAD(2047)=2302 */

// ---------------- scratch (static device globals; no allocs) ----------------
__device__ float  g_fpts[NMELS+2];
__device__ float  g_win[NFFT];
__device__ float  g_env[L_OLA];
__device__ int    g_fbi[NBINS];
__device__ float2 g_fbw[NBINS];
__device__ float2 g_tw1[256];        /* exp(-i*pi*t/1024), t=0..255 */
__device__ float  g_lin[NFRT*NBINS];
__device__ float2 g_tprev[NFRT*NBINS];
__device__ float  g_frames[NFRT*NFFT];
__device__ float  g_inv[BATCH*T_LEN];

// ---------------- threefry-2x32-20 (matches jax partitionable) ----------------
__host__ __device__ __forceinline__ unsigned rotl32(unsigned x, int r){ return (x<<r)|(x>>(32-r)); }
__host__ __device__ inline void tf2x32(unsigned k0,unsigned k1,unsigned x0,unsigned x1,unsigned&o0,unsigned&o1){
  unsigned k2 = k0^k1^0x1BD11BDAu;
  x0+=k0; x1+=k1;
  #define TFR(r) { x0+=x1; x1=rotl32(x1,(r)); x1^=x0; }
  TFR(13) TFR(15) TFR(26) TFR(6)  x0+=k1; x1+=k2+1u;
  TFR(17) TFR(29) TFR(16) TFR(24) x0+=k2; x1+=k0+2u;
  TFR(13) TFR(15) TFR(26) TFR(6)  x0+=k0; x1+=k1+3u;
  TFR(17) TFR(29) TFR(16) TFR(24) x0+=k1; x1+=k2+4u;
  TFR(13) TFR(15) TFR(26) TFR(6)  x0+=k2; x1+=k0+5u;
  #undef TFR
  o0=x0; o1=x1;
}
__device__ __forceinline__ float u01(unsigned bits){
  return __uint_as_float((bits>>9) | 0x3f800000u) - 1.0f;
}
__device__ __forceinline__ int refl(int j, int n){
  if (j < 0) j = -j;
  if (j >= n) j = 2*n - 2 - j;
  return j;
}

// ---------------- register radix-8 DFT (DIF), DIR=+1 fwd / -1 inv ----------------
template<int DIR>
__device__ __forceinline__ void dft8(float* ar, float* ai){
  const float r2 = 0.70710678118654752f;
  const float d = (float)DIR;
  float t0r=ar[0]+ar[4], t0i=ai[0]+ai[4];
  float t4r=ar[0]-ar[4], t4i=ai[0]-ai[4];
  float t1r=ar[1]+ar[5], t1i=ai[1]+ai[5];
  float t5r=ar[1]-ar[5], t5i=ai[1]-ai[5];
  float t2r=ar[2]+ar[6], t2i=ai[2]+ai[6];
  float t6r=ar[2]-ar[6], t6i=ai[2]-ai[6];
  float t3r=ar[3]+ar[7], t3i=ai[3]+ai[7];
  float t7r=ar[3]-ar[7], t7i=ai[3]-ai[7];
  { float a=t5r,b=t5i; t5r=r2*(a+d*b); t5i=r2*(b-d*a); }      // *w8^1
  { float a=t6r,b=t6i; t6r=d*b; t6i=-d*a; }                   // *w8^2 = -i*d
  { float a=t7r,b=t7i; t7r=r2*(d*b-a); t7i=-r2*(b+d*a); }     // *w8^3
  float u0r=t0r+t2r,u0i=t0i+t2i, u1r=t0r-t2r,u1i=t0i-t2i;
  float u2r=t1r+t3r,u2i=t1i+t3i, u3r=t1r-t3r,u3i=t1i-t3i;
  float vr=d*u3i, vi=-d*u3r;
  ar[0]=u0r+u2r; ai[0]=u0i+u2i;
  ar[4]=u0r-u2r; ai[4]=u0i-u2i;
  ar[2]=u1r+vr;  ai[2]=u1i+vi;
  ar[6]=u1r-vr;  ai[6]=u1i-vi;
  u0r=t4r+t6r; u0i=t4i+t6i; u1r=t4r-t6r; u1i=t4i-t6i;
  u2r=t5r+t7r; u2i=t5i+t7i; u3r=t5r-t7r; u3i=t5i-t7i;
  vr=d*u3i; vi=-d*u3r;
  ar[1]=u0r+u2r; ai[1]=u0i+u2i;
  ar[5]=u0r-u2r; ai[5]=u0i-u2i;
  ar[3]=u1r+vr;  ai[3]=u1i+vi;
  ar[7]=u1r-vr;  ai[7]=u1i-vi;
}

// ---------------- size-2048 Stockham FFT, radix 8*8*8*4, single SoA buffer ----------------
// tw1[t] = (cos, sin) of pi*t/1024 from sincospif — identical bits to inline call.
template<int DIR>
__device__ __forceinline__ void fft2048_r8(float* Zr, float* Zi, int tid){
  #pragma unroll
  for (int st = 0; st < 3; ++st){
    const int s = (st==0) ? 1 : (st==1) ? 8 : 64;
    int q = tid & (s-1);
    int ps = tid - q;
    float ar[8], ai[8];
    #pragma unroll
    for (int j=0;j<8;++j){ int idx = tid + (j<<8); ar[j]=Zr[PAD(idx)]; ai[j]=Zi[PAD(idx)]; }
    __syncthreads();
    dft8<DIR>(ar, ai);
    float2 t1 = g_tw1[ps];
    float w1r = t1.x, w1i = -(float)DIR * t1.y;
    float twr[8], twi[8];
    twr[1]=w1r;                       twi[1]=w1i;
    twr[2]=w1r*w1r - w1i*w1i;         twi[2]=2.f*w1r*w1i;
    twr[3]=twr[2]*w1r - twi[2]*w1i;   twi[3]=twr[2]*w1i + twi[2]*w1r;
    twr[4]=twr[2]*twr[2]-twi[2]*twi[2]; twi[4]=2.f*twr[2]*twi[2];
    twr[5]=twr[4]*w1r - twi[4]*w1i;   twi[5]=twr[4]*w1i + twi[4]*w1r;
    twr[6]=twr[4]*twr[2]-twi[4]*twi[2]; twi[6]=twr[4]*twi[2]+twi[4]*twr[2];
    twr[7]=twr[4]*twr[3]-twi[4]*twi[3]; twi[7]=twr[4]*twi[3]+twi[4]*twr[3];
    int base = q + (ps<<3);
    Zr[PAD(base)] = ar[0]; Zi[PAD(base)] = ai[0];
    #pragma unroll
    for (int k=1;k<8;++k){
      float br = ar[k]*twr[k] - ai[k]*twi[k];
      float bi = ar[k]*twi[k] + ai[k]*twr[k];
      int idx = base + s*k;
      Zr[PAD(idx)] = br; Zi[PAD(idx)] = bi;
    }
    __syncthreads();
  }
  float cr[8], ci[8];
  #pragma unroll
  for (int h=0; h<2; ++h){
    int i = tid + (h<<8);
    #pragma unroll
    for (int j=0;j<4;++j){ int idx = i + (j<<9); cr[h*4+j]=Zr[PAD(idx)]; ci[h*4+j]=Zi[PAD(idx)]; }
  }
  __syncthreads();
  const float d = (float)DIR;
  #pragma unroll
  for (int h=0;h<2;++h){
    int i = tid + (h<<8);
    float u0r=cr[h*4]+cr[h*4+2], u0i=ci[h*4]+ci[h*4+2];
    float u1r=cr[h*4]-cr[h*4+2], u1i=ci[h*4]-ci[h*4+2];
    float u2r=cr[h*4+1]+cr[h*4+3], u2i=ci[h*4+1]+ci[h*4+3];
    float u3r=cr[h*4+1]-cr[h*4+3], u3i=ci[h*4+1]-ci[h*4+3];
    float vr=d*u3i, vi=-d*u3r;
    Zr[PAD(i)]      = u0r+u2r; Zi[PAD(i)]      = u0i+u2i;
    Zr[PAD(i+512)]  = u1r+vr;  Zi[PAD(i+512)]  = u1i+vi;
    Zr[PAD(i+1024)] = u0r-u2r; Zi[PAD(i+1024)] = u0i-u2i;
    Zr[PAD(i+1536)] = u1r-vr;  Zi[PAD(i+1536)] = u1i-vi;
  }
  __syncthreads();
}

// ---------------- load 2 windowed frames into Zr/Zi (float4 fast path) ----------------
__device__ __forceinline__ void load_pair(const float* __restrict__ xb,
                                          float* Zr, float* Zi,
                                          int tid, int t0, bool hasB){
  int start = t0*HOP - 1024;
  if (start >= 0 && start + 256 + 2048 <= T_LEN){
    for (int k4 = tid << 2; k4 < 2048; k4 += 1024){
      float4 wv = *(const float4*)(g_win + k4);
      float4 va = *(const float4*)(xb + start + k4);
      float4 vb = *(const float4*)(xb + start + 256 + k4);
      Zr[PAD(k4)]   = va.x*wv.x; Zi[PAD(k4)]   = vb.x*wv.x;
      Zr[PAD(k4+1)] = va.y*wv.y; Zi[PAD(k4+1)] = vb.y*wv.y;
      Zr[PAD(k4+2)] = va.z*wv.z; Zi[PAD(k4+2)] = vb.z*wv.z;
      Zr[PAD(k4+3)] = va.w*wv.w; Zi[PAD(k4+3)] = vb.w*wv.w;
    }
  } else {
    for (int k = tid; k < 2048; k += 256){
      float w = g_win[k];
      Zr[PAD(k)] = xb[refl(start + k, T_LEN)] * w;
      float vb = 0.f;
      if (hasB) vb = xb[refl(start + 256 + k, T_LEN)] * w;
      Zi[PAD(k)] = vb;
    }
  }
}

// ---------------- store windowed frames (float4 writes) ----------------
__device__ __forceinline__ void store_frames(const float* Zr, const float* Zi,
                                             int tid, int fr0, bool hasB){
  float* oa = g_frames + (size_t)fr0 * 2048;
  for (int n4 = tid << 2; n4 < 2048; n4 += 1024){
    float4 wv = *(const float4*)(g_win + n4);
    wv.x *= (1.0f/2048.0f); wv.y *= (1.0f/2048.0f);
    wv.z *= (1.0f/2048.0f); wv.w *= (1.0f/2048.0f);
    float4 va;
    va.x = Zr[PAD(n4)]   * wv.x;
    va.y = Zr[PAD(n4+1)] * wv.y;
    va.z = Zr[PAD(n4+2)] * wv.z;
    va.w = Zr[PAD(n4+3)] * wv.w;
    *(float4*)(oa + n4) = va;
    if (hasB){
      float4 vb;
      vb.x = Zi[PAD(n4)]   * wv.x;
      vb.y = Zi[PAD(n4+1)] * wv.y;
      vb.z = Zi[PAD(n4+2)] * wv.z;
      vb.w = Zi[PAD(n4+3)] * wv.w;
      *(float4*)(oa + 2048 + n4) = vb;
    }
  }
}

// ---------------- mel breakpoints (82 double pows total, once) ----------------
__global__ void k_fpts(){
  int m = threadIdx.x;
  if (m < NMELS+2){
    double mmax = 2595.0*log10(1.0 + 8000.0/700.0);
    g_fpts[m] = (float)(700.0*(pow(10.0, (double)m*mmax/81.0/2595.0) - 1.0));
  }
}

// ---------------- init tables (all float, no pow) ----------------
__global__ void k_tables(){
  int idx = blockIdx.x*blockDim.x + threadIdx.x;
  if (idx < 2048){
    g_win[idx] = 0.5f - 0.5f*cospif((float)idx * (1.0f/1024.0f));
  } else if (idx < 2048+L_OLA){
    int i = idx - 2048;
    int flo = (i - 1792) >> 8; if (flo < 0) flo = 0;
    int fhi = i >> 8;          if (fhi > NFR-1) fhi = NFR-1;
    float acc = 0.f;
    for (int f = flo; f <= fhi; ++f){
      int n = i - 256*f;
      float w = 0.5f - 0.5f*cospif((float)n * (1.0f/1024.0f));
      acc += w*w;
    }
    g_env[i] = acc;
  } else if (idx < 2048+L_OLA+NBINS){
    int f = idx - 2048 - L_OLA;
    float freq = (float)f * (8000.0f/1024.0f);
    int first = -1; float w0 = 0.f, w1 = 0.f;
    #pragma unroll 4
    for (int m = 0; m < NMELS; ++m){
      float fp0 = g_fpts[m], fp1 = g_fpts[m+1], fp2 = g_fpts[m+2];
      float dn = (freq - fp0)/(fp1 - fp0);
      float up = (fp2 - freq)/(fp2 - fp1);
      float v = fminf(dn, up);
      if (v > 0.f){
        if (first < 0){ first = m; w0 = v; }
        else w1 = v;
      }
    }
    g_fbi[f] = first;
    g_fbw[f] = make_float2(w0, w1);
  } else {
    int t = idx - 2048 - L_OLA - NBINS;
    if (t < 256){
      float sn, cs;
      sincospif((float)t * (1.0f/1024.0f), &sn, &cs);
      g_tw1[t] = make_float2(cs, sn);
    }
  }
}

// ---------------- f0 / loudness (1 frame per warp, shuffle autocorr) + MLP ----------------
__global__ void k_feats_mlp(const float* __restrict__ x,
                            const float* __restrict__ W1, const float* __restrict__ b1,
                            const float* __restrict__ W2, const float* __restrict__ b2,
                            const float* __restrict__ W3, const float* __restrict__ b3,
                            float* __restrict__ outc){
  __shared__ float s[8][768];          // 512 window + zero tail (tap reach 735)
  __shared__ float h1s[8*256];
  __shared__ float h2s[8*256];
  __shared__ float feat[8][2];
  int tid = threadIdx.x;
  int w = tid >> 5, lane = tid & 31;
  int base = blockIdx.x * 8;
  const unsigned FULL = 0xffffffffu;

  {
    int fr = base + w;
    int b = fr / NFR, t = fr % NFR;
    const float* xb = x + (size_t)b * T_LEN;
    for (int k = lane; k < 512; k += 32)
      s[w][k] = xb[refl(t*HOP + k - 256, T_LEN)];
    for (int k = 512 + lane; k < 768; k += 32)
      s[w][k] = 0.f;
    __syncwarp();
    float ss = 0.f;
    for (int k = lane; k < 512; k += 32){ float v = s[w][k]; ss += v*v; }
    #pragma unroll
    for (int o = 16; o; o >>= 1) ss += __shfl_xor_sync(FULL, ss, o);
    float acc[7];
    #pragma unroll
    for (int kk = 0; kk < 7; ++kk) acc[kk] = 0.f;
    for (int T = 0; T < 480; T += 32){
      float p = s[w][T + lane];
      float wreg[8];
      #pragma unroll
      for (int kk = 0; kk < 8; ++kk) wreg[kk] = s[w][T + 32 + lane + (kk<<5)];
      #pragma unroll 8
      for (int j = 0; j < 32; ++j){
        float v0 = __shfl_sync(FULL, p, j);
        int src = (lane + j) & 31;
        bool hi = (lane + j) >= 32;
        float sh[8];
        #pragma unroll
        for (int kk = 0; kk < 8; ++kk) sh[kk] = __shfl_sync(FULL, wreg[kk], src);
        #pragma unroll
        for (int kk = 0; kk < 7; ++kk) acc[kk] += v0 * (hi ? sh[kk+1] : sh[kk]);
      }
    }
    float best = -1e30f; int bi = 0;
    #pragma unroll
    for (int kk = 0; kk < 7; ++kk){
      if (acc[kk] > best){ best = acc[kk]; bi = lane + (kk<<5); }
    }
    #pragma unroll
    for (int o = 16; o; o >>= 1){
      float vo = __shfl_xor_sync(FULL, best, o);
      int   io = __shfl_xor_sync(FULL, bi,   o);
      if (vo > best || (vo == best && io < bi)){ best = vo; bi = io; }
    }
    if (lane == 0){
      float period = (float)(bi + MIN_P);
      float f0 = 16000.0f/(period + 1e-8f);
      f0 = fminf(fmaxf(f0, 50.0f), 500.0f);
      float loud = 20.0f*log10f(sqrtf(ss/512.0f) + 1e-8f);
      feat[w][0] = f0; feat[w][1] = loud;
    }
  }
  __syncthreads();

  #pragma unroll
  for (int u = 0; u < 8; ++u){
    float f0 = feat[u][0], ld = feat[u][1];
    float z = f0*W1[tid] + ld*W1[256+tid] + b1[tid];
    h1s[u*256+tid] = z > 0.f ? z : expm1f(z);
  }
  __syncthreads();
  float acc[8];
  #pragma unroll
  for (int u = 0; u < 8; ++u) acc[u] = b2[tid];
  for (int k = 0; k < 256; ++k){
    float wv = W2[k*256 + tid];
    #pragma unroll
    for (int u = 0; u < 8; ++u) acc[u] += h1s[u*256+k]*wv;
  }
  #pragma unroll
  for (int u = 0; u < 8; ++u){
    float z = acc[u];
    h2s[u*256+tid] = z > 0.f ? z : expm1f(z);
  }
  __syncthreads();
  int o = tid & 63;
  for (int pass = 0; pass < 2; ++pass){
    int u = (tid >> 6) + pass*4;
    float a3 = b3[o];
    for (int k = 0; k < 256; ++k) a3 += h2s[u*256+k]*W3[k*64 + o];
    int fr = base + u;
    outc[(size_t)fr*64 + o] = a3;
  }
}

// ---------------- FUSED: STFT -> mag -> mel -> linear -> random phases -> iFFT -> frames ----------------
__global__ void __launch_bounds__(256, 5) k_stft_ifft0(const float* __restrict__ x,
                             unsigned kr0,unsigned kr1,unsigned ki0,unsigned ki1,
                             int pb0){
  __shared__ float Zr[ZLEN], Zi[ZLEN];
  __shared__ float mel[2][NMELS];
  int tid = threadIdx.x;
  int pb = blockIdx.x + pb0;
  int b = pb / NPT, pt = pb % NPT;
  int t0 = 2*pt;
  bool hasB = (t0 + 1 < NFR);
  int fr0 = b*NFR + t0;
  const float* xb = x + (size_t)b * T_LEN;
  load_pair(xb, Zr, Zi, tid, t0, hasB);
  if (tid < 2*NMELS) ((float*)mel)[tid] = 0.f;
  __syncthreads();
  fft2048_r8<1>(Zr, Zi, tid);
  for (int k = tid; k <= 1024; k += 256){
    int m = (2048 - k) & 2047;
    float zkr=Zr[PAD(k)], zki=Zi[PAD(k)], zmr=Zr[PAD(m)], zmi=Zi[PAD(m)];
    float far_ = 0.5f*(zkr + zmr), fai = 0.5f*(zki - zmi);
    float dr = zkr - zmr, di = zki + zmi;
    float fbr = 0.5f*di, fbi = -0.5f*dr;
    float maga = sqrtf(far_*far_ + fai*fai);
    float magb = sqrtf(fbr*fbr + fbi*fbi);
    int i = g_fbi[k];
    float2 w = g_fbw[k];
    if (i >= 0){
      atomicAdd(&mel[0][i], maga*w.x);
      atomicAdd(&mel[1][i], magb*w.x);
      if (w.y != 0.f && i+1 < NMELS){
        atomicAdd(&mel[0][i+1], maga*w.y);
        atomicAdd(&mel[1][i+1], magb*w.y);
      }
    }
  }
  __syncthreads();
  for (int k = tid; k <= 1024; k += 256){
    float src = fmaxf((k + 0.5f)*(80.0f/1025.0f) - 0.5f, 0.0f);
    int i0 = (int)floorf(src); if (i0 > 79) i0 = 79; if (i0 < 0) i0 = 0;
    int i1 = i0 + 1; if (i1 > 79) i1 = 79;
    float wq = src - (float)i0;
    float L  = (1.0f - wq)*mel[0][i0] + wq*mel[0][i1];
    float Lb = (1.0f - wq)*mel[1][i0] + wq*mel[1][i1];
    g_lin[(size_t)fr0*NBINS + k] = L;
    if (hasB) g_lin[(size_t)(fr0+1)*NBINS + k] = Lb;
    float msk = (k == 0 || k == 1024) ? 0.f : 1.f;
    unsigned e = ((unsigned)(b*NBINS + k))*((unsigned)NFR) + (unsigned)t0;
    unsigned r0,r1,i0u,i1u;
    tf2x32(kr0,kr1, 0u, e, r0,r1);
    tf2x32(ki0,ki1, 0u, e, i0u,i1u);
    float ar_ = L*u01(r0^r1), ai_ = L*u01(i0u^i1u)*msk;
    float br_ = 0.f, bi_ = 0.f;
    if (hasB){
      tf2x32(kr0,kr1, 0u, e+1u, r0,r1);
      tf2x32(ki0,ki1, 0u, e+1u, i0u,i1u);
      br_ = Lb*u01(r0^r1); bi_ = Lb*u01(i0u^i1u)*msk;
    }
    Zr[PAD(k)] = ar_ - bi_;
    Zi[PAD(k)] = ai_ + br_;
    if (k > 0 && k < 1024){
      int mm = 2048 - k;
      Zr[PAD(mm)] = ar_ + bi_;
      Zi[PAD(mm)] = br_ - ai_;
    }
  }
  __syncthreads();
  fft2048_r8<-1>(Zr, Zi, tid);
  store_frames(Zr, Zi, tid, fr0, hasB);
}

// ---------------- fused GL iteration: fwd FFT of inv + phase update + inverse FFT ----------------
__global__ void __launch_bounds__(256, 6) k_gl(int first, int pb0){
  __shared__ float Zr[ZLEN], Zi[ZLEN];
  int tid = threadIdx.x;
  int pb = blockIdx.x + pb0;
  int b = pb / NPT, pt = pb % NPT;
  int t0 = 2*pt;
  bool hasB = (t0 + 1 < NFR);
  int fr0 = b*NFR + t0;
  const float* xb = g_inv + (size_t)b * T_LEN;
  load_pair(xb, Zr, Zi, tid, t0, hasB);
  __syncthreads();
  fft2048_r8<1>(Zr, Zi, tid);
  const float* lin0 = g_lin   + (size_t)fr0*NBINS;
  float2*      tpp  = g_tprev + (size_t)fr0*NBINS;
  for (int k = tid; k <= 1024; k += 256){
    int m = (2048 - k) & 2047;
    float zkr=Zr[PAD(k)], zki=Zi[PAD(k)], zmr=Zr[PAD(m)], zmi=Zi[PAD(m)];
    float rar = 0.5f*(zkr + zmr), rai = 0.5f*(zki - zmi);
    float dr = zkr - zmr, di = zki + zmi;
    float rbr = 0.5f*di, rbi = -0.5f*dr;
    float msk = (k == 0 || k == 1024) ? 0.f : 1.f;
    float tpx = 0.f, tpy = 0.f;
    if (!first){ float2 tp = tpp[k]; tpx = tp.x; tpy = tp.y; }
    float ax = rar - MOM*tpx, ay = rai - MOM*tpy;
    float mg = sqrtf(ax*ax + ay*ay) + 1e-16f;
    tpp[k] = make_float2(rar, rai);
    float L = lin0[k];
    float ar_ = L*(ax/mg), ai_ = L*(ay/mg)*msk;
    float br_ = 0.f, bi_ = 0.f;
    if (hasB){
      float tbx = 0.f, tby = 0.f;
      if (!first){ float2 tb = tpp[NBINS + k]; tbx = tb.x; tby = tb.y; }
      float bx = rbr - MOM*tbx, by = rbi - MOM*tby;
      float mb = sqrtf(bx*bx + by*by) + 1e-16f;
      tpp[NBINS + k] = make_float2(rbr, rbi);
      float Lb = lin0[NBINS + k];
      br_ = Lb*(bx/mb); bi_ = Lb*(by/mb)*msk;
    }
    Zr[PAD(k)] = ar_ - bi_;
    Zi[PAD(k)] = ai_ + br_;
    if (k > 0 && k < 1024){
      int mm = 2048 - k;
      Zr[PAD(mm)] = ar_ + bi_;
      Zi[PAD(mm)] = br_ - ai_;
    }
  }
  __syncthreads();
  fft2048_r8<-1>(Zr, Zi, tid);
  store_frames(Zr, Zi, tid, fr0, hasB);
}

// ---------------- overlap-add gather: 4 samples/thread, all-float4, branch-free ----------------
__global__ void k_ola(float* __restrict__ out_final, int is_final, int q0){
  int q = blockIdx.x*blockDim.x + threadIdx.x + q0;
  int b = q >> 15;                 /* 32768 quads per batch */
  int i4 = (q & 32767) << 2;
  int pos = i4 + 1024;
  int flo = (pos - 1792) >> 8; if (flo < 0) flo = 0;
  int fhi = pos >> 8;          if (fhi > NFR-1) fhi = NFR-1;
  const float* fbuf = g_frames + (size_t)b * NFR * 2048;
  float a0=0.f, a1=0.f, a2=0.f, a3=0.f;
  for (int f = flo; f <= fhi; ++f){
    float4 v = *(const float4*)(fbuf + (size_t)f*2048 + (pos - (f<<8)));
    a0 += v.x; a1 += v.y; a2 += v.z; a3 += v.w;
  }
  float4 ev = *(const float4*)(g_env + pos);
  float4 r;
  r.x = a0 / (ev.x > 1e-11f ? ev.x : 1.f);
  r.y = a1 / (ev.y > 1e-11f ? ev.y : 1.f);
  r.z = a2 / (ev.z > 1e-11f ? ev.z : 1.f);
  r.w = a3 / (ev.w > 1e-11f ? ev.w : 1.f);
  size_t o = ((size_t)b << 17) + i4;
  if (is_final) *(float4*)(out_final + o) = r;
  else          *(float4*)(g_inv + o) = r;
}

// ---------------- launch: dual batch-split pipelines + feats branch ----------------
extern "C" void kernel_launch(void* const* d_in, const int* in_sizes, int n_in,
                              void* d_out, int out_size){
  const float* x  = (const float*)d_in[0];
  const float* W1 = (const float*)d_in[1];
  const float* b1 = (const float*)d_in[2];
  const float* W2 = (const float*)d_in[3];
  const float* b2 = (const float*)d_in[4];
  const float* W3 = (const float*)d_in[5];
  const float* b3 = (const float*)d_in[6];
  float* out  = (float*)d_out;
  float* outc = out + (size_t)BATCH*T_LEN;

  unsigned kr0,kr1,ki0,ki1;
  tf2x32(0u, 42u, 0u, 0u, kr0, kr1);
  tf2x32(0u, 42u, 0u, 1u, ki0, ki1);

  static cudaStream_t s2 = 0;
  static cudaEvent_t ev_fork = 0, ev_tab = 0, ev_done = 0;
  if (!s2){
    cudaStreamCreateWithFlags(&s2, cudaStreamNonBlocking);
    cudaEventCreateWithFlags(&ev_fork, cudaEventDisableTiming);
    cudaEventCreateWithFlags(&ev_tab,  cudaEventDisableTiming);
    cudaEventCreateWithFlags(&ev_done, cudaEventDisableTiming);
  }

  // fork side stream: feats first (needs only x)
  cudaEventRecord(ev_fork, 0);
  cudaStreamWaitEvent(s2, ev_fork, 0);
  k_feats_mlp<<<NFRT/8, 256, 0, s2>>>(x, W1, b1, W2, b2, W3, b3, outc);

  // tables on main; side chain waits for them
  k_fpts<<<1, 128>>>();
  k_tables<<<(2048+L_OLA+NBINS+256 + 255)/256, 256>>>();
  cudaEventRecord(ev_tab, 0);
  cudaStreamWaitEvent(s2, ev_tab, 0);

  // chain A (batches 0-7) on main, chain B (batches 8-15) on s2
  k_stft_ifft0<<<NPAIRH, 256>>>(x, kr0, kr1, ki0, ki1, 0);
  k_stft_ifft0<<<NPAIRH, 256, 0, s2>>>(x, kr0, kr1, ki0, ki1, NPAIRH);
  k_ola<<<QH/256, 256>>>(out, 0, 0);
  k_ola<<<QH/256, 256, 0, s2>>>(out, 0, QH);
  for (int it = 1; it <= 4; ++it){
    k_gl<<<NPAIRH, 256>>>(it == 1, 0);
    k_gl<<<NPAIRH, 256, 0, s2>>>(it == 1, NPAIRH);
    k_ola<<<QH/256, 256>>>(out, it == 4, 0);
    k_ola<<<QH/256, 256, 0, s2>>>(out, it == 4, QH);
  }
  cudaEventRecord(ev_done, s2);
  cudaStreamWaitEvent(0, ev_done, 0);
}

// round 16
// speedup vs baseline: 1.9438x; 1.0001x over previous
#include <cuda_runtime.h>
#include <math.h>
#include <stdint.h>

#define BATCH 16
#define T_LEN 131072
#define HOP 256
#define NFFT 2048
#define NBINS 1025
#define NFR 513
#define NFRT (BATCH*NFR)          /* 8208 */
#define NPT 257                    /* frame pairs per batch (last has no B) */
#define NPAIR (BATCH*NPT)          /* 4112 */
#define NPAIRH (NPAIR/2)           /* 2056: one chain = 8 batches */
#define QTOT (BATCH*T_LEN/4)       /* 524288 quads */
#define QH (QTOT/2)                /* 262144 */
#define NMELS 80
#define MIN_P 32
#define L_OLA 133120               /* NFFT + HOP*(NFR-1) */
#define MOM (0.99f/1.99f)

#define PAD(i) ((i) + ((i)>>3))
#define ZLEN 2304                  /* PAD(2047)=2302 */

// ---------------- scratch (static device globals; no allocs) ----------------
__device__ float  g_fpts[NMELS+2];
__device__ float  g_win[NFFT];
__device__ float  g_env[L_OLA];
__device__ int    g_fbi[NBINS];
__device__ float2 g_fbw[NBINS];
__device__ float2 g_tw1[256];        /* exp(-i*pi*t/1024), t=0..255 */
__device__ float  g_lin[NFRT*NBINS];
__device__ float2 g_tprev[NFRT*NBINS];
__device__ float  g_frames[NFRT*NFFT];
__device__ float  g_inv[BATCH*T_LEN];

// ---------------- threefry-2x32-20 (matches jax partitionable) ----------------
__host__ __device__ __forceinline__ unsigned rotl32(unsigned x, int r){ return (x<<r)|(x>>(32-r)); }
__host__ __device__ inline void tf2x32(unsigned k0,unsigned k1,unsigned x0,unsigned x1,unsigned&o0,unsigned&o1){
  unsigned k2 = k0^k1^0x1BD11BDAu;
  x0+=k0; x1+=k1;
  #define TFR(r) { x0+=x1; x1=rotl32(x1,(r)); x1^=x0; }
  TFR(13) TFR(15) TFR(26) TFR(6)  x0+=k1; x1+=k2+1u;
  TFR(17) TFR(29) TFR(16) TFR(24) x0+=k2; x1+=k0+2u;
  TFR(13) TFR(15) TFR(26) TFR(6)  x0+=k0; x1+=k1+3u;
  TFR(17) TFR(29) TFR(16) TFR(24) x0+=k1; x1+=k2+4u;
  TFR(13) TFR(15) TFR(26) TFR(6)  x0+=k2; x1+=k0+5u;
  #undef TFR
  o0=x0; o1=x1;
}
__device__ __forceinline__ float u01(unsigned bits){
  return __uint_as_float((bits>>9) | 0x3f800000u) - 1.0f;
}
__device__ __forceinline__ int refl(int j, int n){
  if (j < 0) j = -j;
  if (j >= n) j = 2*n - 2 - j;
  return j;
}

// ---------------- register radix-8 DFT (DIF), DIR=+1 fwd / -1 inv ----------------
template<int DIR>
__device__ __forceinline__ void dft8(float* ar, float* ai){
  const float r2 = 0.70710678118654752f;
  const float d = (float)DIR;
  float t0r=ar[0]+ar[4], t0i=ai[0]+ai[4];
  float t4r=ar[0]-ar[4], t4i=ai[0]-ai[4];
  float t1r=ar[1]+ar[5], t1i=ai[1]+ai[5];
  float t5r=ar[1]-ar[5], t5i=ai[1]-ai[5];
  float t2r=ar[2]+ar[6], t2i=ai[2]+ai[6];
  float t6r=ar[2]-ar[6], t6i=ai[2]-ai[6];
  float t3r=ar[3]+ar[7], t3i=ai[3]+ai[7];
  float t7r=ar[3]-ar[7], t7i=ai[3]-ai[7];
  { float a=t5r,b=t5i; t5r=r2*(a+d*b); t5i=r2*(b-d*a); }      // *w8^1
  { float a=t6r,b=t6i; t6r=d*b; t6i=-d*a; }                   // *w8^2 = -i*d
  { float a=t7r,b=t7i; t7r=r2*(d*b-a); t7i=-r2*(b+d*a); }     // *w8^3
  float u0r=t0r+t2r,u0i=t0i+t2i, u1r=t0r-t2r,u1i=t0i-t2i;
  float u2r=t1r+t3r,u2i=t1i+t3i, u3r=t1r-t3r,u3i=t1i-t3i;
  float vr=d*u3i, vi=-d*u3r;
  ar[0]=u0r+u2r; ai[0]=u0i+u2i;
  ar[4]=u0r-u2r; ai[4]=u0i-u2i;
  ar[2]=u1r+vr;  ai[2]=u1i+vi;
  ar[6]=u1r-vr;  ai[6]=u1i-vi;
  u0r=t4r+t6r; u0i=t4i+t6i; u1r=t4r-t6r; u1i=t4i-t6i;
  u2r=t5r+t7r; u2i=t5i+t7i; u3r=t5r-t7r; u3i=t5i-t7i;
  vr=d*u3i; vi=-d*u3r;
  ar[1]=u0r+u2r; ai[1]=u0i+u2i;
  ar[5]=u0r-u2r; ai[5]=u0i-u2i;
  ar[3]=u1r+vr;  ai[3]=u1i+vi;
  ar[7]=u1r-vr;  ai[7]=u1i-vi;
}

// ---------------- size-2048 Stockham FFT, radix 8*8*8*4, single SoA buffer ----------------
template<int DIR>
__device__ __forceinline__ void fft2048_r8(float* Zr, float* Zi, int tid){
  #pragma unroll
  for (int st = 0; st < 3; ++st){
    const int s = (st==0) ? 1 : (st==1) ? 8 : 64;
    int q = tid & (s-1);
    int ps = tid - q;
    float ar[8], ai[8];
    #pragma unroll
    for (int j=0;j<8;++j){ int idx = tid + (j<<8); ar[j]=Zr[PAD(idx)]; ai[j]=Zi[PAD(idx)]; }
    __syncthreads();
    dft8<DIR>(ar, ai);
    float2 t1 = g_tw1[ps];
    float w1r = t1.x, w1i = -(float)DIR * t1.y;
    float twr[8], twi[8];
    twr[1]=w1r;                       twi[1]=w1i;
    twr[2]=w1r*w1r - w1i*w1i;         twi[2]=2.f*w1r*w1i;
    twr[3]=twr[2]*w1r - twi[2]*w1i;   twi[3]=twr[2]*w1i + twi[2]*w1r;
    twr[4]=twr[2]*twr[2]-twi[2]*twi[2]; twi[4]=2.f*twr[2]*twi[2];
    twr[5]=twr[4]*w1r - twi[4]*w1i;   twi[5]=twr[4]*w1i + twi[4]*w1r;
    twr[6]=twr[4]*twr[2]-twi[4]*twi[2]; twi[6]=twr[4]*twi[2]+twi[4]*twr[2];
    twr[7]=twr[4]*twr[3]-twi[4]*twi[3]; twi[7]=twr[4]*twi[3]+twi[4]*twr[3];
    int base = q + (ps<<3);
    Zr[PAD(base)] = ar[0]; Zi[PAD(base)] = ai[0];
    #pragma unroll
    for (int k=1;k<8;++k){
      float br = ar[k]*twr[k] - ai[k]*twi[k];
      float bi = ar[k]*twi[k] + ai[k]*twr[k];
      int idx = base + s*k;
      Zr[PAD(idx)] = br; Zi[PAD(idx)] = bi;
    }
    __syncthreads();
  }
  float cr[8], ci[8];
  #pragma unroll
  for (int h=0; h<2; ++h){
    int i = tid + (h<<8);
    #pragma unroll
    for (int j=0;j<4;++j){ int idx = i + (j<<9); cr[h*4+j]=Zr[PAD(idx)]; ci[h*4+j]=Zi[PAD(idx)]; }
  }
  __syncthreads();
  const float d = (float)DIR;
  #pragma unroll
  for (int h=0;h<2;++h){
    int i = tid + (h<<8);
    float u0r=cr[h*4]+cr[h*4+2], u0i=ci[h*4]+ci[h*4+2];
    float u1r=cr[h*4]-cr[h*4+2], u1i=ci[h*4]-ci[h*4+2];
    float u2r=cr[h*4+1]+cr[h*4+3], u2i=ci[h*4+1]+ci[h*4+3];
    float u3r=cr[h*4+1]-cr[h*4+3], u3i=ci[h*4+1]-ci[h*4+3];
    float vr=d*u3i, vi=-d*u3r;
    Zr[PAD(i)]      = u0r+u2r; Zi[PAD(i)]      = u0i+u2i;
    Zr[PAD(i+512)]  = u1r+vr;  Zi[PAD(i+512)]  = u1i+vi;
    Zr[PAD(i+1024)] = u0r-u2r; Zi[PAD(i+1024)] = u0i-u2i;
    Zr[PAD(i+1536)] = u1r-vr;  Zi[PAD(i+1536)] = u1i-vi;
  }
  __syncthreads();
}

// ---------------- load 2 windowed frames into Zr/Zi (float4 fast path) ----------------
__device__ __forceinline__ void load_pair(const float* __restrict__ xb,
                                          float* Zr, float* Zi,
                                          int tid, int t0, bool hasB){
  int start = t0*HOP - 1024;
  if (start >= 0 && start + 256 + 2048 <= T_LEN){
    for (int k4 = tid << 2; k4 < 2048; k4 += 1024){
      float4 wv = *(const float4*)(g_win + k4);
      float4 va = *(const float4*)(xb + start + k4);
      float4 vb = *(const float4*)(xb + start + 256 + k4);
      Zr[PAD(k4)]   = va.x*wv.x; Zi[PAD(k4)]   = vb.x*wv.x;
      Zr[PAD(k4+1)] = va.y*wv.y; Zi[PAD(k4+1)] = vb.y*wv.y;
      Zr[PAD(k4+2)] = va.z*wv.z; Zi[PAD(k4+2)] = vb.z*wv.z;
      Zr[PAD(k4+3)] = va.w*wv.w; Zi[PAD(k4+3)] = vb.w*wv.w;
    }
  } else {
    for (int k = tid; k < 2048; k += 256){
      float w = g_win[k];
      Zr[PAD(k)] = xb[refl(start + k, T_LEN)] * w;
      float vb = 0.f;
      if (hasB) vb = xb[refl(start + 256 + k, T_LEN)] * w;
      Zi[PAD(k)] = vb;
    }
  }
}

// ---------------- store windowed frames (float4 writes) ----------------
__device__ __forceinline__ void store_frames(const float* Zr, const float* Zi,
                                             int tid, int fr0, bool hasB){
  float* oa = g_frames + (size_t)fr0 * 2048;
  for (int n4 = tid << 2; n4 < 2048; n4 += 1024){
    float4 wv = *(const float4*)(g_win + n4);
    wv.x *= (1.0f/2048.0f); wv.y *= (1.0f/2048.0f);
    wv.z *= (1.0f/2048.0f); wv.w *= (1.0f/2048.0f);
    float4 va;
    va.x = Zr[PAD(n4)]   * wv.x;
    va.y = Zr[PAD(n4+1)] * wv.y;
    va.z = Zr[PAD(n4+2)] * wv.z;
    va.w = Zr[PAD(n4+3)] * wv.w;
    *(float4*)(oa + n4) = va;
    if (hasB){
      float4 vb;
      vb.x = Zi[PAD(n4)]   * wv.x;
      vb.y = Zi[PAD(n4+1)] * wv.y;
      vb.z = Zi[PAD(n4+2)] * wv.z;
      vb.w = Zi[PAD(n4+3)] * wv.w;
      *(float4*)(oa + 2048 + n4) = vb;
    }
  }
}

// ---------------- mel breakpoints (82 double pows total, once) ----------------
__global__ void k_fpts(){
  int m = threadIdx.x;
  if (m < NMELS+2){
    double mmax = 2595.0*log10(1.0 + 8000.0/700.0);
    g_fpts[m] = (float)(700.0*(pow(10.0, (double)m*mmax/81.0/2595.0) - 1.0));
  }
}

// ---------------- init tables (all float, no pow) ----------------
__global__ void k_tables(){
  int idx = blockIdx.x*blockDim.x + threadIdx.x;
  if (idx < 2048){
    g_win[idx] = 0.5f - 0.5f*cospif((float)idx * (1.0f/1024.0f));
  } else if (idx < 2048+L_OLA){
    int i = idx - 2048;
    int flo = (i - 1792) >> 8; if (flo < 0) flo = 0;
    int fhi = i >> 8;          if (fhi > NFR-1) fhi = NFR-1;
    float acc = 0.f;
    for (int f = flo; f <= fhi; ++f){
      int n = i - 256*f;
      float w = 0.5f - 0.5f*cospif((float)n * (1.0f/1024.0f));
      acc += w*w;
    }
    g_env[i] = acc;
  } else if (idx < 2048+L_OLA+NBINS){
    int f = idx - 2048 - L_OLA;
    float freq = (float)f * (8000.0f/1024.0f);
    int first = -1; float w0 = 0.f, w1 = 0.f;
    #pragma unroll 4
    for (int m = 0; m < NMELS; ++m){
      float fp0 = g_fpts[m], fp1 = g_fpts[m+1], fp2 = g_fpts[m+2];
      float dn = (freq - fp0)/(fp1 - fp0);
      float up = (fp2 - freq)/(fp2 - fp1);
      float v = fminf(dn, up);
      if (v > 0.f){
        if (first < 0){ first = m; w0 = v; }
        else w1 = v;
      }
    }
    g_fbi[f] = first;
    g_fbw[f] = make_float2(w0, w1);
  } else {
    int t = idx - 2048 - L_OLA - NBINS;
    if (t < 256){
      float sn, cs;
      sincospif((float)t * (1.0f/1024.0f), &sn, &cs);
      g_tw1[t] = make_float2(cs, sn);
    }
  }
}

// ---------------- f0 / loudness (1 frame per warp, shuffle autocorr) + MLP ----------------
__global__ void k_feats_mlp(const float* __restrict__ x,
                            const float* __restrict__ W1, const float* __restrict__ b1,
                            const float* __restrict__ W2, const float* __restrict__ b2,
                            const float* __restrict__ W3, const float* __restrict__ b3,
                            float* __restrict__ outc){
  __shared__ float s[8][768];          // 512 window + zero tail (tap reach 735)
  __shared__ float h1s[8*256];
  __shared__ float h2s[8*256];
  __shared__ float feat[8][2];
  int tid = threadIdx.x;
  int w = tid >> 5, lane = tid & 31;
  int base = blockIdx.x * 8;
  const unsigned FULL = 0xffffffffu;

  {
    int fr = base + w;
    int b = fr / NFR, t = fr % NFR;
    const float* xb = x + (size_t)b * T_LEN;
    for (int k = lane; k < 512; k += 32)
      s[w][k] = xb[refl(t*HOP + k - 256, T_LEN)];
    for (int k = 512 + lane; k < 768; k += 32)
      s[w][k] = 0.f;
    __syncwarp();
    float ss = 0.f;
    for (int k = lane; k < 512; k += 32){ float v = s[w][k]; ss += v*v; }
    #pragma unroll
    for (int o = 16; o; o >>= 1) ss += __shfl_xor_sync(FULL, ss, o);
    float acc[7];
    #pragma unroll
    for (int kk = 0; kk < 7; ++kk) acc[kk] = 0.f;
    for (int T = 0; T < 480; T += 32){
      float p = s[w][T + lane];
      float wreg[8];
      #pragma unroll
      for (int kk = 0; kk < 8; ++kk) wreg[kk] = s[w][T + 32 + lane + (kk<<5)];
      #pragma unroll 8
      for (int j = 0; j < 32; ++j){
        float v0 = __shfl_sync(FULL, p, j);
        int src = (lane + j) & 31;
        bool hi = (lane + j) >= 32;
        float sh[8];
        #pragma unroll
        for (int kk = 0; kk < 8; ++kk) sh[kk] = __shfl_sync(FULL, wreg[kk], src);
        #pragma unroll
        for (int kk = 0; kk < 7; ++kk) acc[kk] += v0 * (hi ? sh[kk+1] : sh[kk]);
      }
    }
    float best = -1e30f; int bi = 0;
    #pragma unroll
    for (int kk = 0; kk < 7; ++kk){
      if (acc[kk] > best){ best = acc[kk]; bi = lane + (kk<<5); }
    }
    #pragma unroll
    for (int o = 16; o; o >>= 1){
      float vo = __shfl_xor_sync(FULL, best, o);
      int   io = __shfl_xor_sync(FULL, bi,   o);
      if (vo > best || (vo == best && io < bi)){ best = vo; bi = io; }
    }
    if (lane == 0){
      float period = (float)(bi + MIN_P);
      float f0 = 16000.0f/(period + 1e-8f);
      f0 = fminf(fmaxf(f0, 50.0f), 500.0f);
      float loud = 20.0f*log10f(sqrtf(ss/512.0f) + 1e-8f);
      feat[w][0] = f0; feat[w][1] = loud;
    }
  }
  __syncthreads();

  #pragma unroll
  for (int u = 0; u < 8; ++u){
    float f0 = feat[u][0], ld = feat[u][1];
    float z = f0*W1[tid] + ld*W1[256+tid] + b1[tid];
    h1s[u*256+tid] = z > 0.f ? z : expm1f(z);
  }
  __syncthreads();
  float acc[8];
  #pragma unroll
  for (int u = 0; u < 8; ++u) acc[u] = b2[tid];
  for (int k = 0; k < 256; ++k){
    float wv = W2[k*256 + tid];
    #pragma unroll
    for (int u = 0; u < 8; ++u) acc[u] += h1s[u*256+k]*wv;
  }
  #pragma unroll
  for (int u = 0; u < 8; ++u){
    float z = acc[u];
    h2s[u*256+tid] = z > 0.f ? z : expm1f(z);
  }
  __syncthreads();
  int o = tid & 63;
  for (int pass = 0; pass < 2; ++pass){
    int u = (tid >> 6) + pass*4;
    float a3 = b3[o];
    for (int k = 0; k < 256; ++k) a3 += h2s[u*256+k]*W3[k*64 + o];
    int fr = base + u;
    outc[(size_t)fr*64 + o] = a3;
  }
}

// ---------------- FUSED: STFT -> mag -> mel -> linear -> random phases -> iFFT -> frames ----------------
__global__ void __launch_bounds__(256, 5) k_stft_ifft0(const float* __restrict__ x,
                             unsigned kr0,unsigned kr1,unsigned ki0,unsigned ki1,
                             int pb0){
  __shared__ float Zr[ZLEN], Zi[ZLEN];
  __shared__ float mel[2][NMELS];
  int tid = threadIdx.x;
  int pb = blockIdx.x + pb0;
  int b = pb / NPT, pt = pb % NPT;
  int t0 = 2*pt;
  bool hasB = (t0 + 1 < NFR);
  int fr0 = b*NFR + t0;
  const float* xb = x + (size_t)b * T_LEN;
  load_pair(xb, Zr, Zi, tid, t0, hasB);
  if (tid < 2*NMELS) ((float*)mel)[tid] = 0.f;
  __syncthreads();
  fft2048_r8<1>(Zr, Zi, tid);
  for (int k = tid; k <= 1024; k += 256){
    int m = (2048 - k) & 2047;
    float zkr=Zr[PAD(k)], zki=Zi[PAD(k)], zmr=Zr[PAD(m)], zmi=Zi[PAD(m)];
    float far_ = 0.5f*(zkr + zmr), fai = 0.5f*(zki - zmi);
    float dr = zkr - zmr, di = zki + zmi;
    float fbr = 0.5f*di, fbi = -0.5f*dr;
    float maga = sqrtf(far_*far_ + fai*fai);
    float magb = sqrtf(fbr*fbr + fbi*fbi);
    int i = g_fbi[k];
    float2 w = g_fbw[k];
    if (i >= 0){
      atomicAdd(&mel[0][i], maga*w.x);
      atomicAdd(&mel[1][i], magb*w.x);
      if (w.y != 0.f && i+1 < NMELS){
        atomicAdd(&mel[0][i+1], maga*w.y);
        atomicAdd(&mel[1][i+1], magb*w.y);
      }
    }
  }
  __syncthreads();
  for (int k = tid; k <= 1024; k += 256){
    float src = fmaxf((k + 0.5f)*(80.0f/1025.0f) - 0.5f, 0.0f);
    int i0 = (int)floorf(src); if (i0 > 79) i0 = 79; if (i0 < 0) i0 = 0;
    int i1 = i0 + 1; if (i1 > 79) i1 = 79;
    float wq = src - (float)i0;
    float L  = (1.0f - wq)*mel[0][i0] + wq*mel[0][i1];
    float Lb = (1.0f - wq)*mel[1][i0] + wq*mel[1][i1];
    g_lin[(size_t)fr0*NBINS + k] = L;
    if (hasB) g_lin[(size_t)(fr0+1)*NBINS + k] = Lb;
    float msk = (k == 0 || k == 1024) ? 0.f : 1.f;
    unsigned e = ((unsigned)(b*NBINS + k))*((unsigned)NFR) + (unsigned)t0;
    unsigned r0,r1,i0u,i1u;
    tf2x32(kr0,kr1, 0u, e, r0,r1);
    tf2x32(ki0,ki1, 0u, e, i0u,i1u);
    float ar_ = L*u01(r0^r1), ai_ = L*u01(i0u^i1u)*msk;
    float br_ = 0.f, bi_ = 0.f;
    if (hasB){
      tf2x32(kr0,kr1, 0u, e+1u, r0,r1);
      tf2x32(ki0,ki1, 0u, e+1u, i0u,i1u);
      br_ = Lb*u01(r0^r1); bi_ = Lb*u01(i0u^i1u)*msk;
    }
    Zr[PAD(k)] = ar_ - bi_;
    Zi[PAD(k)] = ai_ + br_;
    if (k > 0 && k < 1024){
      int mm = 2048 - k;
      Zr[PAD(mm)] = ar_ + bi_;
      Zi[PAD(mm)] = br_ - ai_;
    }
  }
  __syncthreads();
  fft2048_r8<-1>(Zr, Zi, tid);
  store_frames(Zr, Zi, tid, fr0, hasB);
}

// ---------------- fused GL iteration: fwd FFT of inv + phase update + inverse FFT ----------------
__global__ void __launch_bounds__(256, 6) k_gl(int first, int pb0){
  __shared__ float Zr[ZLEN], Zi[ZLEN];
  int tid = threadIdx.x;
  int pb = blockIdx.x + pb0;
  int b = pb / NPT, pt = pb % NPT;
  int t0 = 2*pt;
  bool hasB = (t0 + 1 < NFR);
  int fr0 = b*NFR + t0;
  const float* xb = g_inv + (size_t)b * T_LEN;
  load_pair(xb, Zr, Zi, tid, t0, hasB);
  __syncthreads();
  fft2048_r8<1>(Zr, Zi, tid);
  const float* lin0 = g_lin   + (size_t)fr0*NBINS;
  float2*      tpp  = g_tprev + (size_t)fr0*NBINS;
  for (int k = tid; k <= 1024; k += 256){
    int m = (2048 - k) & 2047;
    float zkr=Zr[PAD(k)], zki=Zi[PAD(k)], zmr=Zr[PAD(m)], zmi=Zi[PAD(m)];
    float rar = 0.5f*(zkr + zmr), rai = 0.5f*(zki - zmi);
    float dr = zkr - zmr, di = zki + zmi;
    float rbr = 0.5f*di, rbi = -0.5f*dr;
    float msk = (k == 0 || k == 1024) ? 0.f : 1.f;
    float tpx = 0.f, tpy = 0.f;
    if (!first){ float2 tp = tpp[k]; tpx = tp.x; tpy = tp.y; }
    float ax = rar - MOM*tpx, ay = rai - MOM*tpy;
    float mg = sqrtf(ax*ax + ay*ay) + 1e-16f;
    tpp[k] = make_float2(rar, rai);
    float L = lin0[k];
    float ar_ = L*(ax/mg), ai_ = L*(ay/mg)*msk;
    float br_ = 0.f, bi_ = 0.f;
    if (hasB){
      float tbx = 0.f, tby = 0.f;
      if (!first){ float2 tb = tpp[NBINS + k]; tbx = tb.x; tby = tb.y; }
      float bx = rbr - MOM*tbx, by = rbi - MOM*tby;
      float mb = sqrtf(bx*bx + by*by) + 1e-16f;
      tpp[NBINS + k] = make_float2(rbr, rbi);
      float Lb = lin0[NBINS + k];
      br_ = Lb*(bx/mb); bi_ = Lb*(by/mb)*msk;
    }
    Zr[PAD(k)] = ar_ - bi_;
    Zi[PAD(k)] = ai_ + br_;
    if (k > 0 && k < 1024){
      int mm = 2048 - k;
      Zr[PAD(mm)] = ar_ + bi_;
      Zi[PAD(mm)] = br_ - ai_;
    }
  }
  __syncthreads();
  fft2048_r8<-1>(Zr, Zi, tid);
  store_frames(Zr, Zi, tid, fr0, hasB);
}

// ---------------- overlap-add gather: 4 samples/thread, all-float4, branch-free ----------------
__global__ void k_ola(float* __restrict__ out_final, int is_final, int q0){
  int q = blockIdx.x*blockDim.x + threadIdx.x + q0;
  int b = q >> 15;                 /* 32768 quads per batch */
  int i4 = (q & 32767) << 2;
  int pos = i4 + 1024;
  int flo = (pos - 1792) >> 8; if (flo < 0) flo = 0;
  int fhi = pos >> 8;          if (fhi > NFR-1) fhi = NFR-1;
  const float* fbuf = g_frames + (size_t)b * NFR * 2048;
  float a0=0.f, a1=0.f, a2=0.f, a3=0.f;
  for (int f = flo; f <= fhi; ++f){
    float4 v = *(const float4*)(fbuf + (size_t)f*2048 + (pos - (f<<8)));
    a0 += v.x; a1 += v.y; a2 += v.z; a3 += v.w;
  }
  float4 ev = *(const float4*)(g_env + pos);
  float4 r;
  r.x = a0 / (ev.x > 1e-11f ? ev.x : 1.f);
  r.y = a1 / (ev.y > 1e-11f ? ev.y : 1.f);
  r.z = a2 / (ev.z > 1e-11f ? ev.z : 1.f);
  r.w = a3 / (ev.w > 1e-11f ? ev.w : 1.f);
  size_t o = ((size_t)b << 17) + i4;
  if (is_final) *(float4*)(out_final + o) = r;
  else          *(float4*)(g_inv + o) = r;
}

// ---------------- launch: dual batch-split pipelines + separate feats stream ----------------
extern "C" void kernel_launch(void* const* d_in, const int* in_sizes, int n_in,
                              void* d_out, int out_size){
  const float* x  = (const float*)d_in[0];
  const float* W1 = (const float*)d_in[1];
  const float* b1 = (const float*)d_in[2];
  const float* W2 = (const float*)d_in[3];
  const float* b2 = (const float*)d_in[4];
  const float* W3 = (const float*)d_in[5];
  const float* b3 = (const float*)d_in[6];
  float* out  = (float*)d_out;
  float* outc = out + (size_t)BATCH*T_LEN;

  unsigned kr0,kr1,ki0,ki1;
  tf2x32(0u, 42u, 0u, 0u, kr0, kr1);
  tf2x32(0u, 42u, 0u, 1u, ki0, ki1);

  static cudaStream_t s2 = 0, s3 = 0;
  static cudaEvent_t ev_fork = 0, ev_tab = 0, ev_done2 = 0, ev_done3 = 0;
  if (!s2){
    cudaStreamCreateWithFlags(&s2, cudaStreamNonBlocking);
    cudaStreamCreateWithFlags(&s3, cudaStreamNonBlocking);
    cudaEventCreateWithFlags(&ev_fork,  cudaEventDisableTiming);
    cudaEventCreateWithFlags(&ev_tab,   cudaEventDisableTiming);
    cudaEventCreateWithFlags(&ev_done2, cudaEventDisableTiming);
    cudaEventCreateWithFlags(&ev_done3, cudaEventDisableTiming);
  }

  // feats on its own stream s3 — off both chains' critical paths
  cudaEventRecord(ev_fork, 0);
  cudaStreamWaitEvent(s3, ev_fork, 0);
  k_feats_mlp<<<NFRT/8, 256, 0, s3>>>(x, W1, b1, W2, b2, W3, b3, outc);
  cudaEventRecord(ev_done3, s3);

  // tables on main; chain B waits only on tables
  k_fpts<<<1, 128>>>();
  k_tables<<<(2048+L_OLA+NBINS+256 + 255)/256, 256>>>();
  cudaEventRecord(ev_tab, 0);
  cudaStreamWaitEvent(s2, ev_tab, 0);

  // chain A (batches 0-7) on main, chain B (batches 8-15) on s2
  k_stft_ifft0<<<NPAIRH, 256>>>(x, kr0, kr1, ki0, ki1, 0);
  k_stft_ifft0<<<NPAIRH, 256, 0, s2>>>(x, kr0, kr1, ki0, ki1, NPAIRH);
  k_ola<<<QH/256, 256>>>(out, 0, 0);
  k_ola<<<QH/256, 256, 0, s2>>>(out, 0, QH);
  for (int it = 1; it <= 4; ++it){
    k_gl<<<NPAIRH, 256>>>(it == 1, 0);
    k_gl<<<NPAIRH, 256, 0, s2>>>(it == 1, NPAIRH);
    k_ola<<<QH/256, 256>>>(out, it == 4, 0);
    k_ola<<<QH/256, 256, 0, s2>>>(out, it == 4, QH);
  }
  cudaEventRecord(ev_done2, s2);
  cudaStreamWaitEvent(0, ev_done2, 0);
  cudaStreamWaitEvent(0, ev_done3, 0);
}

// round 17
// speedup vs baseline: 1.9943x; 1.0260x over previous
#include <cuda_runtime.h>
#include <math.h>
#include <stdint.h>

#define BATCH 16
#define T_LEN 131072
#define HOP 256
#define NFFT 2048
#define NBINS 1025
#define NFR 513
#define NFRT (BATCH*NFR)          /* 8208 */
#define NPT 257                    /* frame pairs per batch (last has no B) */
#define NPAIR (BATCH*NPT)          /* 4112 */
#define NPAIRH (NPAIR/2)           /* 2056: one chain = 8 batches */
#define QTOT (BATCH*T_LEN/4)       /* 524288 quads */
#define QH (QTOT/2)                /* 262144 */
#define NMELS 80
#define MIN_P 32
#define L_OLA 133120               /* NFFT + HOP*(NFR-1) */
#define MOM (0.99f/1.99f)

#define PAD(i) ((i) + ((i)>>3))
#define ZLEN 2304                  /* PAD(2047)=2302 */

// ---------------- scratch (static device globals; no allocs) ----------------
__device__ float  g_fpts[NMELS+2];
__device__ float  g_win[NFFT];
__device__ float  g_env[L_OLA];
__device__ int    g_fbi[NBINS];
__device__ float2 g_fbw[NBINS];
__device__ float2 g_tw1[256];        /* (cos,sin) of pi*t/1024, t=0..255 */
__device__ float  g_lin[NFRT*NBINS];
__device__ float2 g_tprev[NFRT*NBINS];
__device__ float  g_frames[NFRT*NFFT];
__device__ float  g_inv[BATCH*T_LEN];

// ---------------- threefry-2x32-20 (matches jax partitionable) ----------------
__host__ __device__ __forceinline__ unsigned rotl32(unsigned x, int r){ return (x<<r)|(x>>(32-r)); }
__host__ __device__ inline void tf2x32(unsigned k0,unsigned k1,unsigned x0,unsigned x1,unsigned&o0,unsigned&o1){
  unsigned k2 = k0^k1^0x1BD11BDAu;
  x0+=k0; x1+=k1;
  #define TFR(r) { x0+=x1; x1=rotl32(x1,(r)); x1^=x0; }
  TFR(13) TFR(15) TFR(26) TFR(6)  x0+=k1; x1+=k2+1u;
  TFR(17) TFR(29) TFR(16) TFR(24) x0+=k2; x1+=k0+2u;
  TFR(13) TFR(15) TFR(26) TFR(6)  x0+=k0; x1+=k1+3u;
  TFR(17) TFR(29) TFR(16) TFR(24) x0+=k1; x1+=k2+4u;
  TFR(13) TFR(15) TFR(26) TFR(6)  x0+=k2; x1+=k0+5u;
  #undef TFR
  o0=x0; o1=x1;
}
__device__ __forceinline__ float u01(unsigned bits){
  return __uint_as_float((bits>>9) | 0x3f800000u) - 1.0f;
}
__device__ __forceinline__ int refl(int j, int n){
  if (j < 0) j = -j;
  if (j >= n) j = 2*n - 2 - j;
  return j;
}

// ---------------- register radix-8 DFT (DIF), DIR=+1 fwd / -1 inv ----------------
template<int DIR>
__device__ __forceinline__ void dft8(float* ar, float* ai){
  const float r2 = 0.70710678118654752f;
  const float d = (float)DIR;
  float t0r=ar[0]+ar[4], t0i=ai[0]+ai[4];
  float t4r=ar[0]-ar[4], t4i=ai[0]-ai[4];
  float t1r=ar[1]+ar[5], t1i=ai[1]+ai[5];
  float t5r=ar[1]-ar[5], t5i=ai[1]-ai[5];
  float t2r=ar[2]+ar[6], t2i=ai[2]+ai[6];
  float t6r=ar[2]-ar[6], t6i=ai[2]-ai[6];
  float t3r=ar[3]+ar[7], t3i=ai[3]+ai[7];
  float t7r=ar[3]-ar[7], t7i=ai[3]-ai[7];
  { float a=t5r,b=t5i; t5r=r2*(a+d*b); t5i=r2*(b-d*a); }      // *w8^1
  { float a=t6r,b=t6i; t6r=d*b; t6i=-d*a; }                   // *w8^2 = -i*d
  { float a=t7r,b=t7i; t7r=r2*(d*b-a); t7i=-r2*(b+d*a); }     // *w8^3
  float u0r=t0r+t2r,u0i=t0i+t2i, u1r=t0r-t2r,u1i=t0i-t2i;
  float u2r=t1r+t3r,u2i=t1i+t3i, u3r=t1r-t3r,u3i=t1i-t3i;
  float vr=d*u3i, vi=-d*u3r;
  ar[0]=u0r+u2r; ai[0]=u0i+u2i;
  ar[4]=u0r-u2r; ai[4]=u0i-u2i;
  ar[2]=u1r+vr;  ai[2]=u1i+vi;
  ar[6]=u1r-vr;  ai[6]=u1i-vi;
  u0r=t4r+t6r; u0i=t4i+t6i; u1r=t4r-t6r; u1i=t4i-t6i;
  u2r=t5r+t7r; u2i=t5i+t7i; u3r=t5r-t7r; u3i=t5i-t7i;
  vr=d*u3i; vi=-d*u3r;
  ar[1]=u0r+u2r; ai[1]=u0i+u2i;
  ar[5]=u0r-u2r; ai[5]=u0i-u2i;
  ar[3]=u1r+vr;  ai[3]=u1i+vi;
  ar[7]=u1r-vr;  ai[7]=u1i-vi;
}

// twiddle tree + strided store for one radix-8 stage
template<int DIR>
__device__ __forceinline__ void tw_store(float* ar, float* ai, float* Zr, float* Zi,
                                         int q, int ps, int S){
  float2 t1 = g_tw1[ps];
  float w1r = t1.x, w1i = -(float)DIR * t1.y;
  float twr[8], twi[8];
  twr[1]=w1r;                       twi[1]=w1i;
  twr[2]=w1r*w1r - w1i*w1i;         twi[2]=2.f*w1r*w1i;
  twr[3]=twr[2]*w1r - twi[2]*w1i;   twi[3]=twr[2]*w1i + twi[2]*w1r;
  twr[4]=twr[2]*twr[2]-twi[2]*twi[2]; twi[4]=2.f*twr[2]*twi[2];
  twr[5]=twr[4]*w1r - twi[4]*w1i;   twi[5]=twr[4]*w1i + twi[4]*w1r;
  twr[6]=twr[4]*twr[2]-twi[4]*twi[2]; twi[6]=twr[4]*twi[2]+twi[4]*twr[2];
  twr[7]=twr[4]*twr[3]-twi[4]*twi[3]; twi[7]=twr[4]*twi[3]+twi[4]*twr[3];
  int base = q + (ps<<3);
  Zr[PAD(base)] = ar[0]; Zi[PAD(base)] = ai[0];
  #pragma unroll
  for (int k=1;k<8;++k){
    float br = ar[k]*twr[k] - ai[k]*twi[k];
    float bi = ar[k]*twi[k] + ai[k]*twr[k];
    int idx = base + S*k;
    Zr[PAD(idx)] = br; Zi[PAD(idx)] = bi;
  }
}

// stage 1 (s=1) with register input — no smem read, no leading sync
template<int DIR>
__device__ __forceinline__ void fft_stage1_reg(float* ar, float* ai,
                                               float* Zr, float* Zi, int tid){
  dft8<DIR>(ar, ai);
  tw_store<DIR>(ar, ai, Zr, Zi, 0, tid, 1);
  __syncthreads();
}

// generic smem->smem radix-8 stage
template<int DIR, int S>
__device__ __forceinline__ void fft_stage(float* Zr, float* Zi, int tid){
  int q = tid & (S-1);
  int ps = tid - q;
  float ar[8], ai[8];
  #pragma unroll
  for (int j=0;j<8;++j){ int idx = tid + (j<<8); ar[j]=Zr[PAD(idx)]; ai[j]=Zi[PAD(idx)]; }
  __syncthreads();
  dft8<DIR>(ar, ai);
  tw_store<DIR>(ar, ai, Zr, Zi, q, ps, S);
  __syncthreads();
}

// final radix-4 stage (s=512, no twiddles) -> smem
template<int DIR>
__device__ __forceinline__ void fft_final_smem(float* Zr, float* Zi, int tid){
  float cr[8], ci[8];
  #pragma unroll
  for (int h=0; h<2; ++h){
    int i = tid + (h<<8);
    #pragma unroll
    for (int j=0;j<4;++j){ int idx = i + (j<<9); cr[h*4+j]=Zr[PAD(idx)]; ci[h*4+j]=Zi[PAD(idx)]; }
  }
  __syncthreads();
  const float d = (float)DIR;
  #pragma unroll
  for (int h=0;h<2;++h){
    int i = tid + (h<<8);
    float u0r=cr[h*4]+cr[h*4+2], u0i=ci[h*4]+ci[h*4+2];
    float u1r=cr[h*4]-cr[h*4+2], u1i=ci[h*4]-ci[h*4+2];
    float u2r=cr[h*4+1]+cr[h*4+3], u2i=ci[h*4+1]+ci[h*4+3];
    float u3r=cr[h*4+1]-cr[h*4+3], u3i=ci[h*4+1]-ci[h*4+3];
    float vr=d*u3i, vi=-d*u3r;
    Zr[PAD(i)]      = u0r+u2r; Zi[PAD(i)]      = u0i+u2i;
    Zr[PAD(i+512)]  = u1r+vr;  Zi[PAD(i+512)]  = u1i+vi;
    Zr[PAD(i+1024)] = u0r-u2r; Zi[PAD(i+1024)] = u0i-u2i;
    Zr[PAD(i+1536)] = u1r-vr;  Zi[PAD(i+1536)] = u1i-vi;
  }
  __syncthreads();
}

// final radix-4 stage -> registers. orr[h*4+j] holds output index tid+h*256 + j*512.
template<int DIR>
__device__ __forceinline__ void fft_final_regs(float* Zr, float* Zi, int tid,
                                               float* orr, float* ori){
  float cr[8], ci[8];
  #pragma unroll
  for (int h=0; h<2; ++h){
    int i = tid + (h<<8);
    #pragma unroll
    for (int j=0;j<4;++j){ int idx = i + (j<<9); cr[h*4+j]=Zr[PAD(idx)]; ci[h*4+j]=Zi[PAD(idx)]; }
  }
  const float d = (float)DIR;
  #pragma unroll
  for (int h=0;h<2;++h){
    float u0r=cr[h*4]+cr[h*4+2], u0i=ci[h*4]+ci[h*4+2];
    float u1r=cr[h*4]-cr[h*4+2], u1i=ci[h*4]-ci[h*4+2];
    float u2r=cr[h*4+1]+cr[h*4+3], u2i=ci[h*4+1]+ci[h*4+3];
    float u3r=cr[h*4+1]-cr[h*4+3], u3i=ci[h*4+1]-ci[h*4+3];
    float vr=d*u3i, vi=-d*u3r;
    orr[h*4+0]=u0r+u2r; ori[h*4+0]=u0i+u2i;
    orr[h*4+1]=u1r+vr;  ori[h*4+1]=u1i+vi;
    orr[h*4+2]=u0r-u2r; ori[h*4+2]=u0i-u2i;
    orr[h*4+3]=u1r-vr;  ori[h*4+3]=u1i-vi;
  }
}

// load 2 windowed frames straight into stage-1 registers (coalesced per warp)
__device__ __forceinline__ void load_regs(const float* __restrict__ xb,
                                          float* ar, float* ai,
                                          int tid, int t0, bool hasB){
  int start = t0*HOP - 1024;
  if (start >= 0 && start + 256 + 2048 <= T_LEN){
    #pragma unroll
    for (int j=0;j<8;++j){
      int n = tid + (j<<8);
      float w = g_win[n];
      ar[j] = xb[start+n]*w;
      ai[j] = xb[start+256+n]*w;
    }
  } else {
    #pragma unroll
    for (int j=0;j<8;++j){
      int n = tid + (j<<8);
      float w = g_win[n];
      ar[j] = xb[refl(start+n, T_LEN)]*w;
      ai[j] = hasB ? xb[refl(start+256+n, T_LEN)]*w : 0.f;
    }
  }
}

// direct global store of both windowed iFFT results
__device__ __forceinline__ void store_regs(const float* orr, const float* ori,
                                           int tid, int fr0, bool hasB){
  float* oa = g_frames + (size_t)fr0 * 2048;
  #pragma unroll
  for (int h=0;h<2;++h){
    int i = tid + (h<<8);
    #pragma unroll
    for (int j=0;j<4;++j){
      int n = i + (j<<9);
      float w = g_win[n]*(1.0f/2048.0f);
      oa[n] = orr[h*4+j]*w;
      if (hasB) oa[2048+n] = ori[h*4+j]*w;
    }
  }
}

// ---------------- mel breakpoints (82 double pows total, once) ----------------
__global__ void k_fpts(){
  int m = threadIdx.x;
  if (m < NMELS+2){
    double mmax = 2595.0*log10(1.0 + 8000.0/700.0);
    g_fpts[m] = (float)(700.0*(pow(10.0, (double)m*mmax/81.0/2595.0) - 1.0));
  }
}

// ---------------- init tables (all float, no pow) ----------------
__global__ void k_tables(){
  int idx = blockIdx.x*blockDim.x + threadIdx.x;
  if (idx < 2048){
    g_win[idx] = 0.5f - 0.5f*cospif((float)idx * (1.0f/1024.0f));
  } else if (idx < 2048+L_OLA){
    int i = idx - 2048;
    int flo = (i - 1792) >> 8; if (flo < 0) flo = 0;
    int fhi = i >> 8;          if (fhi > NFR-1) fhi = NFR-1;
    float acc = 0.f;
    for (int f = flo; f <= fhi; ++f){
      int n = i - 256*f;
      float w = 0.5f - 0.5f*cospif((float)n * (1.0f/1024.0f));
      acc += w*w;
    }
    g_env[i] = acc;
  } else if (idx < 2048+L_OLA+NBINS){
    int f = idx - 2048 - L_OLA;
    float freq = (float)f * (8000.0f/1024.0f);
    int first = -1; float w0 = 0.f, w1 = 0.f;
    #pragma unroll 4
    for (int m = 0; m < NMELS; ++m){
      float fp0 = g_fpts[m], fp1 = g_fpts[m+1], fp2 = g_fpts[m+2];
      float dn = (freq - fp0)/(fp1 - fp0);
      float up = (fp2 - freq)/(fp2 - fp1);
      float v = fminf(dn, up);
      if (v > 0.f){
        if (first < 0){ first = m; w0 = v; }
        else w1 = v;
      }
    }
    g_fbi[f] = first;
    g_fbw[f] = make_float2(w0, w1);
  } else {
    int t = idx - 2048 - L_OLA - NBINS;
    if (t < 256){
      float sn, cs;
      sincospif((float)t * (1.0f/1024.0f), &sn, &cs);
      g_tw1[t] = make_float2(cs, sn);
    }
  }
}

// ---------------- f0 / loudness (1 frame per warp, shuffle autocorr) + MLP ----------------
__global__ void k_feats_mlp(const float* __restrict__ x,
                            const float* __restrict__ W1, const float* __restrict__ b1,
                            const float* __restrict__ W2, const float* __restrict__ b2,
                            const float* __restrict__ W3, const float* __restrict__ b3,
                            float* __restrict__ outc){
  __shared__ float s[8][768];          // 512 window + zero tail (tap reach 735)
  __shared__ float h1s[8*256];
  __shared__ float h2s[8*256];
  __shared__ float feat[8][2];
  int tid = threadIdx.x;
  int w = tid >> 5, lane = tid & 31;
  int base = blockIdx.x * 8;
  const unsigned FULL = 0xffffffffu;

  {
    int fr = base + w;
    int b = fr / NFR, t = fr % NFR;
    const float* xb = x + (size_t)b * T_LEN;
    for (int k = lane; k < 512; k += 32)
      s[w][k] = xb[refl(t*HOP + k - 256, T_LEN)];
    for (int k = 512 + lane; k < 768; k += 32)
      s[w][k] = 0.f;
    __syncwarp();
    float ss = 0.f;
    for (int k = lane; k < 512; k += 32){ float v = s[w][k]; ss += v*v; }
    #pragma unroll
    for (int o = 16; o; o >>= 1) ss += __shfl_xor_sync(FULL, ss, o);
    float acc[7];
    #pragma unroll
    for (int kk = 0; kk < 7; ++kk) acc[kk] = 0.f;
    for (int T = 0; T < 480; T += 32){
      float p = s[w][T + lane];
      float wreg[8];
      #pragma unroll
      for (int kk = 0; kk < 8; ++kk) wreg[kk] = s[w][T + 32 + lane + (kk<<5)];
      #pragma unroll 8
      for (int j = 0; j < 32; ++j){
        float v0 = __shfl_sync(FULL, p, j);
        int src = (lane + j) & 31;
        bool hi = (lane + j) >= 32;
        float sh[8];
        #pragma unroll
        for (int kk = 0; kk < 8; ++kk) sh[kk] = __shfl_sync(FULL, wreg[kk], src);
        #pragma unroll
        for (int kk = 0; kk < 7; ++kk) acc[kk] += v0 * (hi ? sh[kk+1] : sh[kk]);
      }
    }
    float best = -1e30f; int bi = 0;
    #pragma unroll
    for (int kk = 0; kk < 7; ++kk){
      if (acc[kk] > best){ best = acc[kk]; bi = lane + (kk<<5); }
    }
    #pragma unroll
    for (int o = 16; o; o >>= 1){
      float vo = __shfl_xor_sync(FULL, best, o);
      int   io = __shfl_xor_sync(FULL, bi,   o);
      if (vo > best || (vo == best && io < bi)){ best = vo; bi = io; }
    }
    if (lane == 0){
      float period = (float)(bi + MIN_P);
      float f0 = 16000.0f/(period + 1e-8f);
      f0 = fminf(fmaxf(f0, 50.0f), 500.0f);
      float loud = 20.0f*log10f(sqrtf(ss/512.0f) + 1e-8f);
      feat[w][0] = f0; feat[w][1] = loud;
    }
  }
  __syncthreads();

  #pragma unroll
  for (int u = 0; u < 8; ++u){
    float f0 = feat[u][0], ld = feat[u][1];
    float z = f0*W1[tid] + ld*W1[256+tid] + b1[tid];
    h1s[u*256+tid] = z > 0.f ? z : expm1f(z);
  }
  __syncthreads();
  float acc[8];
  #pragma unroll
  for (int u = 0; u < 8; ++u) acc[u] = b2[tid];
  for (int k = 0; k < 256; ++k){
    float wv = W2[k*256 + tid];
    #pragma unroll
    for (int u = 0; u < 8; ++u) acc[u] += h1s[u*256+k]*wv;
  }
  #pragma unroll
  for (int u = 0; u < 8; ++u){
    float z = acc[u];
    h2s[u*256+tid] = z > 0.f ? z : expm1f(z);
  }
  __syncthreads();
  int o = tid & 63;
  for (int pass = 0; pass < 2; ++pass){
    int u = (tid >> 6) + pass*4;
    float a3 = b3[o];
    for (int k = 0; k < 256; ++k) a3 += h2s[u*256+k]*W3[k*64 + o];
    int fr = base + u;
    outc[(size_t)fr*64 + o] = a3;
  }
}

// ---------------- FUSED: STFT -> mag -> mel -> linear -> random phases -> iFFT -> frames ----------------
__global__ void __launch_bounds__(256, 5) k_stft_ifft0(const float* __restrict__ x,
                             unsigned kr0,unsigned kr1,unsigned ki0,unsigned ki1,
                             int pb0){
  __shared__ float Zr[ZLEN], Zi[ZLEN];
  __shared__ float mel[2][NMELS];
  int tid = threadIdx.x;
  int pb = blockIdx.x + pb0;
  int b = pb / NPT, pt = pb % NPT;
  int t0 = 2*pt;
  bool hasB = (t0 + 1 < NFR);
  int fr0 = b*NFR + t0;
  const float* xb = x + (size_t)b * T_LEN;
  if (tid < 2*NMELS) ((float*)mel)[tid] = 0.f;
  float ar[8], ai[8];
  load_regs(xb, ar, ai, tid, t0, hasB);
  // forward FFT (stage 1 from registers)
  fft_stage1_reg<1>(ar, ai, Zr, Zi, tid);
  fft_stage<1, 8>(Zr, Zi, tid);
  fft_stage<1, 64>(Zr, Zi, tid);
  fft_final_smem<1>(Zr, Zi, tid);
  for (int k = tid; k <= 1024; k += 256){
    int m = (2048 - k) & 2047;
    float zkr=Zr[PAD(k)], zki=Zi[PAD(k)], zmr=Zr[PAD(m)], zmi=Zi[PAD(m)];
    float far_ = 0.5f*(zkr + zmr), fai = 0.5f*(zki - zmi);
    float dr = zkr - zmr, di = zki + zmi;
    float fbr = 0.5f*di, fbi = -0.5f*dr;
    float maga = sqrtf(far_*far_ + fai*fai);
    float magb = sqrtf(fbr*fbr + fbi*fbi);
    int i = g_fbi[k];
    float2 w = g_fbw[k];
    if (i >= 0){
      atomicAdd(&mel[0][i], maga*w.x);
      atomicAdd(&mel[1][i], magb*w.x);
      if (w.y != 0.f && i+1 < NMELS){
        atomicAdd(&mel[0][i+1], maga*w.y);
        atomicAdd(&mel[1][i+1], magb*w.y);
      }
    }
  }
  __syncthreads();
  for (int k = tid; k <= 1024; k += 256){
    float src = fmaxf((k + 0.5f)*(80.0f/1025.0f) - 0.5f, 0.0f);
    int i0 = (int)floorf(src); if (i0 > 79) i0 = 79; if (i0 < 0) i0 = 0;
    int i1 = i0 + 1; if (i1 > 79) i1 = 79;
    float wq = src - (float)i0;
    float L  = (1.0f - wq)*mel[0][i0] + wq*mel[0][i1];
    float Lb = (1.0f - wq)*mel[1][i0] + wq*mel[1][i1];
    g_lin[(size_t)fr0*NBINS + k] = L;
    if (hasB) g_lin[(size_t)(fr0+1)*NBINS + k] = Lb;
    float msk = (k == 0 || k == 1024) ? 0.f : 1.f;
    unsigned e = ((unsigned)(b*NBINS + k))*((unsigned)NFR) + (unsigned)t0;
    unsigned r0,r1,i0u,i1u;
    tf2x32(kr0,kr1, 0u, e, r0,r1);
    tf2x32(ki0,ki1, 0u, e, i0u,i1u);
    float ar_ = L*u01(r0^r1), ai_ = L*u01(i0u^i1u)*msk;
    float br_ = 0.f, bi_ = 0.f;
    if (hasB){
      tf2x32(kr0,kr1, 0u, e+1u, r0,r1);
      tf2x32(ki0,ki1, 0u, e+1u, i0u,i1u);
      br_ = Lb*u01(r0^r1); bi_ = Lb*u01(i0u^i1u)*msk;
    }
    Zr[PAD(k)] = ar_ - bi_;
    Zi[PAD(k)] = ai_ + br_;
    if (k > 0 && k < 1024){
      int mm = 2048 - k;
      Zr[PAD(mm)] = ar_ + bi_;
      Zi[PAD(mm)] = br_ - ai_;
    }
  }
  __syncthreads();
  // inverse FFT (final stage to registers -> direct global store)
  fft_stage<-1, 1>(Zr, Zi, tid);
  fft_stage<-1, 8>(Zr, Zi, tid);
  fft_stage<-1, 64>(Zr, Zi, tid);
  float orr[8], ori[8];
  fft_final_regs<-1>(Zr, Zi, tid, orr, ori);
  store_regs(orr, ori, tid, fr0, hasB);
}

// ---------------- fused GL iteration: fwd FFT of inv + phase update + inverse FFT ----------------
__global__ void __launch_bounds__(256, 6) k_gl(int first, int pb0){
  __shared__ float Zr[ZLEN], Zi[ZLEN];
  int tid = threadIdx.x;
  int pb = blockIdx.x + pb0;
  int b = pb / NPT, pt = pb % NPT;
  int t0 = 2*pt;
  bool hasB = (t0 + 1 < NFR);
  int fr0 = b*NFR + t0;
  const float* xb = g_inv + (size_t)b * T_LEN;
  float ar[8], ai[8];
  load_regs(xb, ar, ai, tid, t0, hasB);
  fft_stage1_reg<1>(ar, ai, Zr, Zi, tid);
  fft_stage<1, 8>(Zr, Zi, tid);
  fft_stage<1, 64>(Zr, Zi, tid);
  fft_final_smem<1>(Zr, Zi, tid);
  const float* lin0 = g_lin   + (size_t)fr0*NBINS;
  float2*      tpp  = g_tprev + (size_t)fr0*NBINS;
  for (int k = tid; k <= 1024; k += 256){
    int m = (2048 - k) & 2047;
    float zkr=Zr[PAD(k)], zki=Zi[PAD(k)], zmr=Zr[PAD(m)], zmi=Zi[PAD(m)];
    float rar = 0.5f*(zkr + zmr), rai = 0.5f*(zki - zmi);
    float dr = zkr - zmr, di = zki + zmi;
    float rbr = 0.5f*di, rbi = -0.5f*dr;
    float msk = (k == 0 || k == 1024) ? 0.f : 1.f;
    float tpx = 0.f, tpy = 0.f;
    if (!first){ float2 tp = tpp[k]; tpx = tp.x; tpy = tp.y; }
    float ax = rar - MOM*tpx, ay = rai - MOM*tpy;
    float mg = sqrtf(ax*ax + ay*ay) + 1e-16f;
    tpp[k] = make_float2(rar, rai);
    float L = lin0[k];
    float ar_ = L*(ax/mg), ai_ = L*(ay/mg)*msk;
    float br_ = 0.f, bi_ = 0.f;
    if (hasB){
      float tbx = 0.f, tby = 0.f;
      if (!first){ float2 tb = tpp[NBINS + k]; tbx = tb.x; tby = tb.y; }
      float bx = rbr - MOM*tbx, by = rbi - MOM*tby;
      float mb = sqrtf(bx*bx + by*by) + 1e-16f;
      tpp[NBINS + k] = make_float2(rbr, rbi);
      float Lb = lin0[NBINS + k];
      br_ = Lb*(bx/mb); bi_ = Lb*(by/mb)*msk;
    }
    Zr[PAD(k)] = ar_ - bi_;
    Zi[PAD(k)] = ai_ + br_;
    if (k > 0 && k < 1024){
      int mm = 2048 - k;
      Zr[PAD(mm)] = ar_ + bi_;
      Zi[PAD(mm)] = br_ - ai_;
    }
  }
  __syncthreads();
  fft_stage<-1, 1>(Zr, Zi, tid);
  fft_stage<-1, 8>(Zr, Zi, tid);
  fft_stage<-1, 64>(Zr, Zi, tid);
  float orr[8], ori[8];
  fft_final_regs<-1>(Zr, Zi, tid, orr, ori);
  store_regs(orr, ori, tid, fr0, hasB);
}

// ---------------- overlap-add gather: 4 samples/thread, all-float4, branch-free ----------------
__global__ void k_ola(float* __restrict__ out_final, int is_final, int q0){
  int q = blockIdx.x*blockDim.x + threadIdx.x + q0;
  int b = q >> 15;                 /* 32768 quads per batch */
  int i4 = (q & 32767) << 2;
  int pos = i4 + 1024;
  int flo = (pos - 1792) >> 8; if (flo < 0) flo = 0;
  int fhi = pos >> 8;          if (fhi > NFR-1) fhi = NFR-1;
  const float* fbuf = g_frames + (size_t)b * NFR * 2048;
  float a0=0.f, a1=0.f, a2=0.f, a3=0.f;
  for (int f = flo; f <= fhi; ++f){
    float4 v = *(const float4*)(fbuf + (size_t)f*2048 + (pos - (f<<8)));
    a0 += v.x; a1 += v.y; a2 += v.z; a3 += v.w;
  }
  float4 ev = *(const float4*)(g_env + pos);
  float4 r;
  r.x = a0 / (ev.x > 1e-11f ? ev.x : 1.f);
  r.y = a1 / (ev.y > 1e-11f ? ev.y : 1.f);
  r.z = a2 / (ev.z > 1e-11f ? ev.z : 1.f);
  r.w = a3 / (ev.w > 1e-11f ? ev.w : 1.f);
  size_t o = ((size_t)b << 17) + i4;
  if (is_final) *(float4*)(out_final + o) = r;
  else          *(float4*)(g_inv + o) = r;
}

// ---------------- launch: dual batch-split pipelines + separate feats stream ----------------
extern "C" void kernel_launch(void* const* d_in, const int* in_sizes, int n_in,
                              void* d_out, int out_size){
  const float* x  = (const float*)d_in[0];
  const float* W1 = (const float*)d_in[1];
  const float* b1 = (const float*)d_in[2];
  const float* W2 = (const float*)d_in[3];
  const float* b2 = (const float*)d_in[4];
  const float* W3 = (const float*)d_in[5];
  const float* b3 = (const float*)d_in[6];
  float* out  = (float*)d_out;
  float* outc = out + (size_t)BATCH*T_LEN;

  unsigned kr0,kr1,ki0,ki1;
  tf2x32(0u, 42u, 0u, 0u, kr0, kr1);
  tf2x32(0u, 42u, 0u, 1u, ki0, ki1);

  static cudaStream_t s2 = 0, s3 = 0;
  static cudaEvent_t ev_fork = 0, ev_tab = 0, ev_done2 = 0, ev_done3 = 0;
  if (!s2){
    cudaStreamCreateWithFlags(&s2, cudaStreamNonBlocking);
    cudaStreamCreateWithFlags(&s3, cudaStreamNonBlocking);
    cudaEventCreateWithFlags(&ev_fork,  cudaEventDisableTiming);
    cudaEventCreateWithFlags(&ev_tab,   cudaEventDisableTiming);
    cudaEventCreateWithFlags(&ev_done2, cudaEventDisableTiming);
    cudaEventCreateWithFlags(&ev_done3, cudaEventDisableTiming);
  }

  // feats on its own stream s3 — off both chains' critical paths
  cudaEventRecord(ev_fork, 0);
  cudaStreamWaitEvent(s3, ev_fork, 0);
  k_feats_mlp<<<NFRT/8, 256, 0, s3>>>(x, W1, b1, W2, b2, W3, b3, outc);
  cudaEventRecord(ev_done3, s3);

  // tables on main; chain B waits only on tables
  k_fpts<<<1, 128>>>();
  k_tables<<<(2048+L_OLA+NBINS+256 + 255)/256, 256>>>();
  cudaEventRecord(ev_tab, 0);
  cudaStreamWaitEvent(s2, ev_tab, 0);

  // chain A (batches 0-7) on main, chain B (batches 8-15) on s2
  k_stft_ifft0<<<NPAIRH, 256>>>(x, kr0, kr1, ki0, ki1, 0);
  k_stft_ifft0<<<NPAIRH, 256, 0, s2>>>(x, kr0, kr1, ki0, ki1, NPAIRH);
  k_ola<<<QH/256, 256>>>(out, 0, 0);
  k_ola<<<QH/256, 256, 0, s2>>>(out, 0, QH);
  for (int it = 1; it <= 4; ++it){
    k_gl<<<NPAIRH, 256>>>(it == 1, 0);
    k_gl<<<NPAIRH, 256, 0, s2>>>(it == 1, NPAIRH);
    k_ola<<<QH/256, 256>>>(out, it == 4, 0);
    k_ola<<<QH/256, 256, 0, s2>>>(out, it == 4, QH);
  }
  cudaEventRecord(ev_done2, s2);
  cudaStreamWaitEvent(0, ev_done2, 0);
  cudaStreamWaitEvent(0, ev_done3, 0);
}